// round 1
// baseline (speedup 1.0000x reference)
#include <cuda_runtime.h>
#include <math.h>

// Problem constants
#define RR 128
#define CC 256
#define EE 768
#define HH 12
#define DKK 64
#define MTOK (RR*CC)          // 32768 tokens

// Scratch (device globals — no allocation allowed)
__device__ float g_q[(size_t)MTOK * EE];
__device__ float g_k[(size_t)MTOK * EE];
__device__ float g_v[(size_t)MTOK * EE];
__device__ float g_c[(size_t)MTOK * EE];
__device__ float g_attn[(size_t)HH * CC * CC];

// ---------------------------------------------------------------------------
// NT SGEMM:  out[m,n] = alpha * ( sum_k A[m,k]*W[n,k] + bias[n] )
// A: [M,K] row-major, W: [N,K] row-major. M%128==0, N%128==0, K%16==0.
// 128x128 block tile, BK=16, 256 threads, 8x8 per-thread microtile.
// ---------------------------------------------------------------------------
__global__ __launch_bounds__(256) void gemm_nt_kernel(
    const float* __restrict__ A, const float* __restrict__ W,
    const float* __restrict__ bias, float* __restrict__ out,
    int Mdim, int Ndim, int Kdim, float alpha)
{
    __shared__ float As[16][128];
    __shared__ float Ws[16][128];

    const int bm = blockIdx.y * 128;
    const int bn = blockIdx.x * 128;
    const int tid = threadIdx.x;
    const int lr = tid >> 2;          // 0..63
    const int lc = (tid & 3) << 2;    // 0,4,8,12
    const int tx = tid & 15;          // 0..15 (n)
    const int ty = tid >> 4;          // 0..15 (m)

    float acc[8][8];
#pragma unroll
    for (int i = 0; i < 8; i++)
#pragma unroll
        for (int j = 0; j < 8; j++) acc[i][j] = 0.f;

    const float* Ap = A + (size_t)(bm + lr) * Kdim + lc;
    const float* Wp = W + (size_t)(bn + lr) * Kdim + lc;

    for (int k0 = 0; k0 < Kdim; k0 += 16) {
        float4 a0 = *(const float4*)(Ap + k0);
        float4 a1 = *(const float4*)(Ap + (size_t)64 * Kdim + k0);
        float4 w0 = *(const float4*)(Wp + k0);
        float4 w1 = *(const float4*)(Wp + (size_t)64 * Kdim + k0);
        __syncthreads();
        As[lc+0][lr] = a0.x; As[lc+1][lr] = a0.y; As[lc+2][lr] = a0.z; As[lc+3][lr] = a0.w;
        As[lc+0][lr+64] = a1.x; As[lc+1][lr+64] = a1.y; As[lc+2][lr+64] = a1.z; As[lc+3][lr+64] = a1.w;
        Ws[lc+0][lr] = w0.x; Ws[lc+1][lr] = w0.y; Ws[lc+2][lr] = w0.z; Ws[lc+3][lr] = w0.w;
        Ws[lc+0][lr+64] = w1.x; Ws[lc+1][lr+64] = w1.y; Ws[lc+2][lr+64] = w1.z; Ws[lc+3][lr+64] = w1.w;
        __syncthreads();
#pragma unroll
        for (int kk = 0; kk < 16; kk++) {
            float4 am0 = *(const float4*)&As[kk][ty * 8];
            float4 am1 = *(const float4*)&As[kk][ty * 8 + 4];
            float4 bn0 = *(const float4*)&Ws[kk][tx * 8];
            float4 bn1 = *(const float4*)&Ws[kk][tx * 8 + 4];
            float a[8] = {am0.x, am0.y, am0.z, am0.w, am1.x, am1.y, am1.z, am1.w};
            float b[8] = {bn0.x, bn0.y, bn0.z, bn0.w, bn1.x, bn1.y, bn1.z, bn1.w};
#pragma unroll
            for (int i = 0; i < 8; i++)
#pragma unroll
                for (int j = 0; j < 8; j++)
                    acc[i][j] = fmaf(a[i], b[j], acc[i][j]);
        }
    }

    float bb[8];
#pragma unroll
    for (int j = 0; j < 8; j++) bb[j] = bias[bn + tx * 8 + j];

#pragma unroll
    for (int i = 0; i < 8; i++) {
        float* o = out + (size_t)(bm + ty * 8 + i) * Ndim + bn + tx * 8;
#pragma unroll
        for (int j = 0; j < 8; j++)
            o[j] = alpha * (acc[i][j] + bb[j]);
    }
}

// ---------------------------------------------------------------------------
// Attention logits: attn[h,i,j] = sum_{r,d} q[(r*C+i)*E + h*DK + d] * k[...j...]
// Block computes a 64x64 (i,j) tile for one head; reduce over r (128) x d (64).
// grid: (4 j-tiles, 4 i-tiles, H). 256 threads, 4x4 microtile.
// ---------------------------------------------------------------------------
__global__ __launch_bounds__(256) void attn_logits_kernel()
{
    __shared__ float Qs[64][68];   // [d][i]
    __shared__ float Ks[64][68];   // [d][j]

    const int h  = blockIdx.z;
    const int i0 = blockIdx.y * 64;
    const int j0 = blockIdx.x * 64;
    const int tid = threadIdx.x;
    const int lr = tid >> 2;        // 0..63
    const int g  = tid & 3;
    const int tx = tid & 15;
    const int ty = tid >> 4;

    float acc[4][4];
#pragma unroll
    for (int i = 0; i < 4; i++)
#pragma unroll
        for (int j = 0; j < 4; j++) acc[i][j] = 0.f;

    for (int r = 0; r < RR; r++) {
        const float* qb = g_q + ((size_t)r * CC) * EE + h * DKK;
        const float* kb = g_k + ((size_t)r * CC) * EE + h * DKK;
        __syncthreads();
#pragma unroll
        for (int f = 0; f < 4; f++) {
            int d = 16 * g + 4 * f;
            float4 qv = *(const float4*)(qb + (size_t)(i0 + lr) * EE + d);
            float4 kv = *(const float4*)(kb + (size_t)(j0 + lr) * EE + d);
            Qs[d+0][lr] = qv.x; Qs[d+1][lr] = qv.y; Qs[d+2][lr] = qv.z; Qs[d+3][lr] = qv.w;
            Ks[d+0][lr] = kv.x; Ks[d+1][lr] = kv.y; Ks[d+2][lr] = kv.z; Ks[d+3][lr] = kv.w;
        }
        __syncthreads();
#pragma unroll
        for (int kk = 0; kk < 64; kk++) {
            float4 av = *(const float4*)&Qs[kk][ty * 4];
            float4 bv = *(const float4*)&Ks[kk][tx * 4];
            float a[4] = {av.x, av.y, av.z, av.w};
            float b[4] = {bv.x, bv.y, bv.z, bv.w};
#pragma unroll
            for (int i = 0; i < 4; i++)
#pragma unroll
                for (int j = 0; j < 4; j++)
                    acc[i][j] = fmaf(a[i], b[j], acc[i][j]);
        }
    }

    float* ab = g_attn + (size_t)h * CC * CC;
#pragma unroll
    for (int i = 0; i < 4; i++)
#pragma unroll
        for (int j = 0; j < 4; j++)
            ab[(size_t)(i0 + ty * 4 + i) * CC + j0 + tx * 4 + j] = acc[i][j];
}

// ---------------------------------------------------------------------------
// Row softmax over j (256), one block per (h,i) row. Writes normalized probs
// back into g_attn (for the context kernel) AND to the probs output region.
// ---------------------------------------------------------------------------
__global__ __launch_bounds__(256) void softmax_kernel(float* __restrict__ probs_out)
{
    __shared__ float red[256];
    const int row = blockIdx.x;                 // 0 .. H*C-1
    const int tid = threadIdx.x;
    float v = g_attn[(size_t)row * CC + tid];

    red[tid] = v; __syncthreads();
    for (int s = 128; s > 0; s >>= 1) {
        if (tid < s) red[tid] = fmaxf(red[tid], red[tid + s]);
        __syncthreads();
    }
    float mx = red[0];
    __syncthreads();

    float e = __expf(v - mx);
    red[tid] = e; __syncthreads();
    for (int s = 128; s > 0; s >>= 1) {
        if (tid < s) red[tid] += red[tid + s];
        __syncthreads();
    }
    float p = e / red[0];

    g_attn[(size_t)row * CC + tid] = p;
    probs_out[(size_t)row * CC + tid] = p;
}

// ---------------------------------------------------------------------------
// Context: c[(r*C+i)*E + h*DK + d] = sum_j probs[h,i,j] * v[(r*C+j)*E + h*DK + d]
// Block: fixed (h, r), 64(i) x 64(d) output tile. grid: (4 i-tiles, H, R).
// ---------------------------------------------------------------------------
__global__ __launch_bounds__(256) void context_kernel()
{
    __shared__ float Ps[64][68];   // [j][i]
    __shared__ float Vs[64][68];   // [j][d]

    const int i0 = blockIdx.x * 64;
    const int h  = blockIdx.y;
    const int r  = blockIdx.z;
    const int tid = threadIdx.x;
    const int lr = tid >> 2;
    const int g  = tid & 3;
    const int tx = tid & 15;
    const int ty = tid >> 4;

    float acc[4][4];
#pragma unroll
    for (int i = 0; i < 4; i++)
#pragma unroll
        for (int j = 0; j < 4; j++) acc[i][j] = 0.f;

    const float* pb = g_attn + (size_t)h * CC * CC;
    const float* vb = g_v + ((size_t)r * CC) * EE + h * DKK;

    for (int j0 = 0; j0 < CC; j0 += 64) {
        __syncthreads();
#pragma unroll
        for (int f = 0; f < 4; f++) {
            int c4 = 16 * g + 4 * f;
            float4 pv = *(const float4*)(pb + (size_t)(i0 + lr) * CC + j0 + c4);
            Ps[c4+0][lr] = pv.x; Ps[c4+1][lr] = pv.y; Ps[c4+2][lr] = pv.z; Ps[c4+3][lr] = pv.w;
            float4 vv = *(const float4*)(vb + (size_t)(j0 + lr) * EE + c4);
            *(float4*)&Vs[lr][c4] = vv;
        }
        __syncthreads();
#pragma unroll
        for (int kk = 0; kk < 64; kk++) {
            float4 av = *(const float4*)&Ps[kk][ty * 4];
            float4 bv = *(const float4*)&Vs[kk][tx * 4];
            float a[4] = {av.x, av.y, av.z, av.w};
            float b[4] = {bv.x, bv.y, bv.z, bv.w};
#pragma unroll
            for (int i = 0; i < 4; i++)
#pragma unroll
                for (int j = 0; j < 4; j++)
                    acc[i][j] = fmaf(a[i], b[j], acc[i][j]);
        }
    }

    float* cb = g_c + ((size_t)r * CC) * EE + h * DKK;
#pragma unroll
    for (int i = 0; i < 4; i++)
#pragma unroll
        for (int j = 0; j < 4; j++)
            cb[(size_t)(i0 + ty * 4 + i) * EE + tx * 4 + j] = acc[i][j];
}

// ---------------------------------------------------------------------------
extern "C" void kernel_launch(void* const* d_in, const int* in_sizes, int n_in,
                              void* d_out, int out_size)
{
    const float* x  = (const float*)d_in[0];
    const float* Wq = (const float*)d_in[1];
    const float* bq = (const float*)d_in[2];
    const float* Wk = (const float*)d_in[3];
    const float* bk = (const float*)d_in[4];
    const float* Wv = (const float*)d_in[5];
    const float* bv = (const float*)d_in[6];
    const float* Wo = (const float*)d_in[7];
    const float* bo = (const float*)d_in[8];

    float* out = (float*)d_out;                       // [R,C,B,E] = 25165824 floats
    float* probs = out + (size_t)MTOK * EE;           // [H,B,C,C] =   786432 floats

    float* q; cudaGetSymbolAddress((void**)&q, g_q);
    float* k; cudaGetSymbolAddress((void**)&k, g_k);
    float* v; cudaGetSymbolAddress((void**)&v, g_v);
    float* c; cudaGetSymbolAddress((void**)&c, g_c);

    const float scaling = 0.125f / sqrtf((float)RR);  // DK^-0.5 / sqrt(R)

    dim3 gemmGrid(EE / 128, MTOK / 128);              // (6, 256)
    gemm_nt_kernel<<<gemmGrid, 256>>>(x, Wq, bq, q, MTOK, EE, EE, scaling);
    gemm_nt_kernel<<<gemmGrid, 256>>>(x, Wk, bk, k, MTOK, EE, EE, 1.0f);
    gemm_nt_kernel<<<gemmGrid, 256>>>(x, Wv, bv, v, MTOK, EE, EE, 1.0f);

    attn_logits_kernel<<<dim3(4, 4, HH), 256>>>();
    softmax_kernel<<<HH * CC, 256>>>(probs);
    context_kernel<<<dim3(4, HH, RR), 256>>>();

    gemm_nt_kernel<<<gemmGrid, 256>>>(c, Wo, bo, out, MTOK, EE, EE, 1.0f);
}

// round 3
// speedup vs baseline: 1.8217x; 1.8217x over previous
#include <cuda_runtime.h>
#include <cuda_bf16.h>
#include <math.h>
#include <stdint.h>

// Problem constants
#define RR 128
#define CC 256
#define EE 768
#define HH 12
#define DKK 64
#define MTOK (RR*CC)          // 32768 tokens
#define NPART 4               // r-split for attention logits

// ---------------------------------------------------------------------------
// Scratch (device globals — no allocation allowed)
// ---------------------------------------------------------------------------
__device__ float g_q[(size_t)MTOK * EE];
__device__ float g_k[(size_t)MTOK * EE];
__device__ float g_v[(size_t)MTOK * EE];
__device__ float g_c[(size_t)MTOK * EE];
__device__ float g_attn[(size_t)HH * CC * CC];
__device__ float g_attn_part[NPART][(size_t)HH * CC * CC];

__device__ __nv_bfloat16 g_xhi[(size_t)MTOK * EE];
__device__ __nv_bfloat16 g_xlo[(size_t)MTOK * EE];
__device__ __nv_bfloat16 g_chi[(size_t)MTOK * EE];
__device__ __nv_bfloat16 g_clo[(size_t)MTOK * EE];
__device__ __nv_bfloat16 g_whi[4][(size_t)EE * EE];
__device__ __nv_bfloat16 g_wlo[4][(size_t)EE * EE];

// ---------------------------------------------------------------------------
// Helpers (suffix-free PTX only: cp.async / ldmatrix / mma.sync)
// ---------------------------------------------------------------------------
__device__ __forceinline__ uint32_t smem_u32(const void* p) {
    uint32_t a;
    asm("{ .reg .u64 t; cvta.to.shared.u64 t, %1; cvt.u32.u64 %0, t; }"
        : "=r"(a) : "l"(p));
    return a;
}

__device__ __forceinline__ uint32_t swz(uint32_t off) {
    return off ^ ((off >> 3) & 0x30);   // 64B-row swizzle, conflict-free LDSM
}

__device__ __forceinline__ void cpa16(uint32_t dst, const void* src) {
    asm volatile("cp.async.cg.shared.global [%0], [%1], 16;"
                 :: "r"(dst), "l"(src));
}
#define CP_COMMIT() asm volatile("cp.async.commit_group;" ::: "memory")
#define CP_WAIT1()  asm volatile("cp.async.wait_group 1;" ::: "memory")

// A-fragment ldmatrix.x4: m16 x k16 tile from smem [row][64B], rows = m
__device__ __forceinline__ void ldsm4_a(uint32_t* r, uint32_t sb, int mbase, int k16) {
    int lane = threadIdx.x & 31;
    uint32_t row = mbase + (lane & 15);
    uint32_t cb  = (lane & 16);                    // +16B for k8-15 pieces
    uint32_t addr = sb + swz(row * 64 + k16 * 32 + cb);
    asm volatile("ldmatrix.sync.aligned.m8n8.x4.shared.b16 {%0,%1,%2,%3}, [%4];"
                 : "=r"(r[0]), "=r"(r[1]), "=r"(r[2]), "=r"(r[3]) : "r"(addr));
}

// B-fragment ldmatrix.x4: two n8 x k16 fragments from W[n][k] smem rows
__device__ __forceinline__ void ldsm4_b(uint32_t* r, uint32_t sb, int nbase, int k16) {
    int lane = threadIdx.x & 31;
    uint32_t row = nbase + (lane & 7) + ((lane & 16) >> 1);  // +8 rows for 2nd frag
    uint32_t cb  = (lane & 8) << 1;                          // +16B for k8-15
    uint32_t addr = sb + swz(row * 64 + k16 * 32 + cb);
    asm volatile("ldmatrix.sync.aligned.m8n8.x4.shared.b16 {%0,%1,%2,%3}, [%4];"
                 : "=r"(r[0]), "=r"(r[1]), "=r"(r[2]), "=r"(r[3]) : "r"(addr));
}

__device__ __forceinline__ void mma16816(float* c, const uint32_t* a, const uint32_t* b) {
    asm volatile(
        "mma.sync.aligned.m16n8k16.row.col.f32.bf16.bf16.f32 "
        "{%0,%1,%2,%3}, {%4,%5,%6,%7}, {%8,%9}, {%0,%1,%2,%3};"
        : "+f"(c[0]), "+f"(c[1]), "+f"(c[2]), "+f"(c[3])
        : "r"(a[0]), "r"(a[1]), "r"(a[2]), "r"(a[3]), "r"(b[0]), "r"(b[1]));
}

// ---------------------------------------------------------------------------
// Split fp32 -> bf16 (hi, lo) with lo = bf16(x - float(hi)).  n4 = n/4.
// ---------------------------------------------------------------------------
__global__ __launch_bounds__(256) void split_kernel(
    const float* __restrict__ src,
    __nv_bfloat16* __restrict__ hi, __nv_bfloat16* __restrict__ lo, int n4)
{
    int i = blockIdx.x * 256 + threadIdx.x;
    if (i >= n4) return;
    float4 v = ((const float4*)src)[i];
    __nv_bfloat16 h0 = __float2bfloat16(v.x);
    __nv_bfloat16 h1 = __float2bfloat16(v.y);
    __nv_bfloat16 h2 = __float2bfloat16(v.z);
    __nv_bfloat16 h3 = __float2bfloat16(v.w);
    __nv_bfloat16 l0 = __float2bfloat16(v.x - __bfloat162float(h0));
    __nv_bfloat16 l1 = __float2bfloat16(v.y - __bfloat162float(h1));
    __nv_bfloat16 l2 = __float2bfloat16(v.z - __bfloat162float(h2));
    __nv_bfloat16 l3 = __float2bfloat16(v.w - __bfloat162float(h3));
    __nv_bfloat162* hp = (__nv_bfloat162*)hi;
    __nv_bfloat162* lp = (__nv_bfloat162*)lo;
    hp[2 * i + 0] = __halves2bfloat162(h0, h1);
    hp[2 * i + 1] = __halves2bfloat162(h2, h3);
    lp[2 * i + 0] = __halves2bfloat162(l0, l1);
    lp[2 * i + 1] = __halves2bfloat162(l2, l3);
}

// ---------------------------------------------------------------------------
// HMMA bf16 split-precision NT GEMM:
//   out[m,n] = alpha * (sum_k A[m,k]*W[n,k] + bias[n])
//   D = Ahi*Whi + Ahi*Wlo + Alo*Whi  (fp32 accum)
// CTA 128x128, BK=32, 8 warps (2m x 4n), warp tile 64x32,
// 3-stage cp.async pipeline, SW64-swizzled smem, ldmatrix fragments.
// ---------------------------------------------------------------------------
#define BKC 32
#define STG_BYTES 32768            // 4 tiles x 128 x 32 x 2B
#define GEMM_DSMEM (3 * STG_BYTES)

__global__ __launch_bounds__(256) void gemm_mma_kernel(
    const __nv_bfloat16* __restrict__ Ahi, const __nv_bfloat16* __restrict__ Alo,
    const __nv_bfloat16* __restrict__ Whi, const __nv_bfloat16* __restrict__ Wlo,
    const float* __restrict__ bias, float* __restrict__ out,
    int Kdim, int Ndim, float alpha)
{
    extern __shared__ char dsm[];
    const uint32_t sbase = smem_u32(dsm);

    const int tid  = threadIdx.x;
    const int wid  = tid >> 5;
    const int lane = tid & 31;
    const int wm = wid >> 2;        // 0..1
    const int wn = wid & 3;         // 0..3
    const int bm = blockIdx.y * 128;
    const int bn = blockIdx.x * 128;
    const int nch = Kdim / BKC;     // 24

    const __nv_bfloat16* srcs[4] = {
        Ahi + (size_t)bm * Kdim, Alo + (size_t)bm * Kdim,
        Whi + (size_t)bn * Kdim, Wlo + (size_t)bn * Kdim };

    // per-thread g2s mapping: 2 consecutive 16B segments per tile
    const int seg0 = tid * 2;
    const int row_g = seg0 >> 2;          // 0..127
    const int ch0   = seg0 & 3;           // 0 or 2

    auto load_stage = [&](int kc, int buf) {
#pragma unroll
        for (int t = 0; t < 4; t++) {
            const __nv_bfloat16* s = srcs[t] + (size_t)row_g * Kdim + kc * BKC;
            uint32_t base = sbase + buf * STG_BYTES + t * 8192 + row_g * 64;
            cpa16(base - row_g * 64 + swz(row_g * 64 + (ch0 + 0) * 16), s + (ch0 + 0) * 8);
            cpa16(base - row_g * 64 + swz(row_g * 64 + (ch0 + 1) * 16), s + (ch0 + 1) * 8);
        }
        CP_COMMIT();
    };

    float acc[4][4][4];
#pragma unroll
    for (int mt = 0; mt < 4; mt++)
#pragma unroll
        for (int nt = 0; nt < 4; nt++)
#pragma unroll
            for (int e = 0; e < 4; e++) acc[mt][nt][e] = 0.f;

    load_stage(0, 0);
    load_stage(1, 1);

    for (int kc = 0; kc < nch; kc++) {
        CP_WAIT1();
        __syncthreads();
        int nb = kc + 2;
        if (nb < nch) load_stage(nb, nb % 3);
        else CP_COMMIT();                      // keep group counts uniform

        const uint32_t st = sbase + (kc % 3) * STG_BYTES;
        const uint32_t sAh = st, sAl = st + 8192, sWh = st + 16384, sWl = st + 24576;

#pragma unroll
        for (int k16 = 0; k16 < 2; k16++) {
            uint32_t Ah[4][4], Al[4][4], Bh[2][4], Bl[2][4];
#pragma unroll
            for (int mt = 0; mt < 4; mt++) ldsm4_a(Ah[mt], sAh, wm * 64 + mt * 16, k16);
#pragma unroll
            for (int mt = 0; mt < 4; mt++) ldsm4_a(Al[mt], sAl, wm * 64 + mt * 16, k16);
#pragma unroll
            for (int p = 0; p < 2; p++) ldsm4_b(Bh[p], sWh, wn * 32 + p * 16, k16);
#pragma unroll
            for (int p = 0; p < 2; p++) ldsm4_b(Bl[p], sWl, wn * 32 + p * 16, k16);

#pragma unroll
            for (int mt = 0; mt < 4; mt++) {
#pragma unroll
                for (int nt = 0; nt < 4; nt++) {
                    const uint32_t* bh = &Bh[nt >> 1][(nt & 1) * 2];
                    const uint32_t* bl = &Bl[nt >> 1][(nt & 1) * 2];
                    mma16816(acc[mt][nt], Ah[mt], bh);   // hi*hi
                    mma16816(acc[mt][nt], Ah[mt], bl);   // hi*lo
                    mma16816(acc[mt][nt], Al[mt], bh);   // lo*hi
                }
            }
        }
    }

    // Epilogue: c0,c1 -> (row, col..col+1); c2,c3 -> (row+8, ...)
#pragma unroll
    for (int mt = 0; mt < 4; mt++) {
        const int m0 = bm + wm * 64 + mt * 16 + (lane >> 2);
#pragma unroll
        for (int nt = 0; nt < 4; nt++) {
            const int col = bn + wn * 32 + nt * 8 + 2 * (lane & 3);
            const float b0 = bias[col], b1 = bias[col + 1];
            float2 v0 = make_float2(alpha * (acc[mt][nt][0] + b0),
                                    alpha * (acc[mt][nt][1] + b1));
            float2 v1 = make_float2(alpha * (acc[mt][nt][2] + b0),
                                    alpha * (acc[mt][nt][3] + b1));
            *(float2*)(out + (size_t)m0 * Ndim + col) = v0;
            *(float2*)(out + (size_t)(m0 + 8) * Ndim + col) = v1;
        }
    }
}

// ---------------------------------------------------------------------------
// Attention logits (partial over r): part[p][h,i,j] = sum_{r in chunk p, d} q*k
// grid: (4 j-tiles, 4 i-tiles, HH*NPART). 256 threads, 4x4 microtile.
// ---------------------------------------------------------------------------
__global__ __launch_bounds__(256) void attn_logits_kernel()
{
    __shared__ float Qs[64][68];   // [d][i]
    __shared__ float Ks[64][68];   // [d][j]

    const int zz = blockIdx.z;
    const int h  = zz % HH;
    const int p  = zz / HH;
    const int i0 = blockIdx.y * 64;
    const int j0 = blockIdx.x * 64;
    const int tid = threadIdx.x;
    const int lr = tid >> 2;        // 0..63
    const int g  = tid & 3;
    const int tx = tid & 15;
    const int ty = tid >> 4;

    float acc[4][4];
#pragma unroll
    for (int i = 0; i < 4; i++)
#pragma unroll
        for (int j = 0; j < 4; j++) acc[i][j] = 0.f;

    const int rbeg = p * (RR / NPART);
    const int rend = rbeg + (RR / NPART);
    for (int r = rbeg; r < rend; r++) {
        const float* qb = g_q + ((size_t)r * CC) * EE + h * DKK;
        const float* kb = g_k + ((size_t)r * CC) * EE + h * DKK;
        __syncthreads();
#pragma unroll
        for (int f = 0; f < 4; f++) {
            int d = 16 * g + 4 * f;
            float4 qv = *(const float4*)(qb + (size_t)(i0 + lr) * EE + d);
            float4 kv = *(const float4*)(kb + (size_t)(j0 + lr) * EE + d);
            Qs[d+0][lr] = qv.x; Qs[d+1][lr] = qv.y; Qs[d+2][lr] = qv.z; Qs[d+3][lr] = qv.w;
            Ks[d+0][lr] = kv.x; Ks[d+1][lr] = kv.y; Ks[d+2][lr] = kv.z; Ks[d+3][lr] = kv.w;
        }
        __syncthreads();
#pragma unroll
        for (int kk = 0; kk < 64; kk++) {
            float4 av = *(const float4*)&Qs[kk][ty * 4];
            float4 bv = *(const float4*)&Ks[kk][tx * 4];
            float a[4] = {av.x, av.y, av.z, av.w};
            float b[4] = {bv.x, bv.y, bv.z, bv.w};
#pragma unroll
            for (int i = 0; i < 4; i++)
#pragma unroll
                for (int j = 0; j < 4; j++)
                    acc[i][j] = fmaf(a[i], b[j], acc[i][j]);
        }
    }

    float* ab = g_attn_part[p] + (size_t)h * CC * CC;
#pragma unroll
    for (int i = 0; i < 4; i++)
#pragma unroll
        for (int j = 0; j < 4; j++)
            ab[(size_t)(i0 + ty * 4 + i) * CC + j0 + tx * 4 + j] = acc[i][j];
}

// ---------------------------------------------------------------------------
// Row softmax over j (256); sums the NPART partials first.
// ---------------------------------------------------------------------------
__global__ __launch_bounds__(256) void softmax_kernel(float* __restrict__ probs_out)
{
    __shared__ float red[256];
    const int row = blockIdx.x;                 // 0 .. H*C-1
    const int tid = threadIdx.x;
    float v = 0.f;
#pragma unroll
    for (int pp = 0; pp < NPART; pp++)
        v += g_attn_part[pp][(size_t)row * CC + tid];

    red[tid] = v; __syncthreads();
    for (int s = 128; s > 0; s >>= 1) {
        if (tid < s) red[tid] = fmaxf(red[tid], red[tid + s]);
        __syncthreads();
    }
    float mx = red[0];
    __syncthreads();

    float e = __expf(v - mx);
    red[tid] = e; __syncthreads();
    for (int s = 128; s > 0; s >>= 1) {
        if (tid < s) red[tid] += red[tid + s];
        __syncthreads();
    }
    float pr = e / red[0];

    g_attn[(size_t)row * CC + tid] = pr;
    probs_out[(size_t)row * CC + tid] = pr;
}

// ---------------------------------------------------------------------------
// Context: c[(r*C+i)*E + h*DK + d] = sum_j probs[h,i,j] * v[(r*C+j)*E + h*DK + d]
// ---------------------------------------------------------------------------
__global__ __launch_bounds__(256) void context_kernel()
{
    __shared__ float Ps[64][68];   // [j][i]
    __shared__ float Vs[64][68];   // [j][d]

    const int i0 = blockIdx.x * 64;
    const int h  = blockIdx.y;
    const int r  = blockIdx.z;
    const int tid = threadIdx.x;
    const int lr = tid >> 2;
    const int g  = tid & 3;
    const int tx = tid & 15;
    const int ty = tid >> 4;

    float acc[4][4];
#pragma unroll
    for (int i = 0; i < 4; i++)
#pragma unroll
        for (int j = 0; j < 4; j++) acc[i][j] = 0.f;

    const float* pb = g_attn + (size_t)h * CC * CC;
    const float* vb = g_v + ((size_t)r * CC) * EE + h * DKK;

    for (int j0 = 0; j0 < CC; j0 += 64) {
        __syncthreads();
#pragma unroll
        for (int f = 0; f < 4; f++) {
            int c4 = 16 * g + 4 * f;
            float4 pv = *(const float4*)(pb + (size_t)(i0 + lr) * CC + j0 + c4);
            Ps[c4+0][lr] = pv.x; Ps[c4+1][lr] = pv.y; Ps[c4+2][lr] = pv.z; Ps[c4+3][lr] = pv.w;
            float4 vv = *(const float4*)(vb + (size_t)(j0 + lr) * EE + c4);
            *(float4*)&Vs[lr][c4] = vv;
        }
        __syncthreads();
#pragma unroll
        for (int kk = 0; kk < 64; kk++) {
            float4 av = *(const float4*)&Ps[kk][ty * 4];
            float4 bv = *(const float4*)&Vs[kk][tx * 4];
            float a[4] = {av.x, av.y, av.z, av.w};
            float b[4] = {bv.x, bv.y, bv.z, bv.w};
#pragma unroll
            for (int i = 0; i < 4; i++)
#pragma unroll
                for (int j = 0; j < 4; j++)
                    acc[i][j] = fmaf(a[i], b[j], acc[i][j]);
        }
    }

    float* cb = g_c + ((size_t)r * CC) * EE + h * DKK;
#pragma unroll
    for (int i = 0; i < 4; i++)
#pragma unroll
        for (int j = 0; j < 4; j++)
            cb[(size_t)(i0 + ty * 4 + i) * EE + tx * 4 + j] = acc[i][j];
}

// ---------------------------------------------------------------------------
extern "C" void kernel_launch(void* const* d_in, const int* in_sizes, int n_in,
                              void* d_out, int out_size)
{
    const float* x  = (const float*)d_in[0];
    const float* Wq = (const float*)d_in[1];
    const float* bq = (const float*)d_in[2];
    const float* Wk = (const float*)d_in[3];
    const float* bk = (const float*)d_in[4];
    const float* Wv = (const float*)d_in[5];
    const float* bv = (const float*)d_in[6];
    const float* Wo = (const float*)d_in[7];
    const float* bo = (const float*)d_in[8];

    float* out = (float*)d_out;                       // [R,C,B,E]
    float* probs = out + (size_t)MTOK * EE;           // [H,B,C,C]

    float* q; cudaGetSymbolAddress((void**)&q, g_q);
    float* k; cudaGetSymbolAddress((void**)&k, g_k);
    float* v; cudaGetSymbolAddress((void**)&v, g_v);
    float* c; cudaGetSymbolAddress((void**)&c, g_c);
    __nv_bfloat16* xhi; cudaGetSymbolAddress((void**)&xhi, g_xhi);
    __nv_bfloat16* xlo; cudaGetSymbolAddress((void**)&xlo, g_xlo);
    __nv_bfloat16* chi; cudaGetSymbolAddress((void**)&chi, g_chi);
    __nv_bfloat16* clo; cudaGetSymbolAddress((void**)&clo, g_clo);
    __nv_bfloat16* whi; cudaGetSymbolAddress((void**)&whi, g_whi);
    __nv_bfloat16* wlo; cudaGetSymbolAddress((void**)&wlo, g_wlo);

    cudaFuncSetAttribute(gemm_mma_kernel,
                         cudaFuncAttributeMaxDynamicSharedMemorySize, GEMM_DSMEM);

    const float scaling = 0.125f / sqrtf((float)RR);  // DK^-0.5 / sqrt(R)
    const size_t WN = (size_t)EE * EE;

    // splits
    {
        int n4x = (int)((size_t)MTOK * EE / 4);
        split_kernel<<<(n4x + 255) / 256, 256>>>(x, xhi, xlo, n4x);
        int n4w = (int)(WN / 4);
        split_kernel<<<(n4w + 255) / 256, 256>>>(Wq, whi + 0 * WN, wlo + 0 * WN, n4w);
        split_kernel<<<(n4w + 255) / 256, 256>>>(Wk, whi + 1 * WN, wlo + 1 * WN, n4w);
        split_kernel<<<(n4w + 255) / 256, 256>>>(Wv, whi + 2 * WN, wlo + 2 * WN, n4w);
        split_kernel<<<(n4w + 255) / 256, 256>>>(Wo, whi + 3 * WN, wlo + 3 * WN, n4w);
    }

    dim3 gemmGrid(EE / 128, MTOK / 128);              // (6, 256)
    gemm_mma_kernel<<<gemmGrid, 256, GEMM_DSMEM>>>(xhi, xlo, whi + 0 * WN, wlo + 0 * WN,
                                                   bq, q, EE, EE, scaling);
    gemm_mma_kernel<<<gemmGrid, 256, GEMM_DSMEM>>>(xhi, xlo, whi + 1 * WN, wlo + 1 * WN,
                                                   bk, k, EE, EE, 1.0f);
    gemm_mma_kernel<<<gemmGrid, 256, GEMM_DSMEM>>>(xhi, xlo, whi + 2 * WN, wlo + 2 * WN,
                                                   bv, v, EE, EE, 1.0f);

    attn_logits_kernel<<<dim3(4, 4, HH * NPART), 256>>>();
    softmax_kernel<<<HH * CC, 256>>>(probs);
    context_kernel<<<dim3(4, HH, RR), 256>>>();

    {
        int n4c = (int)((size_t)MTOK * EE / 4);
        split_kernel<<<(n4c + 255) / 256, 256>>>(c, chi, clo, n4c);
    }
    gemm_mma_kernel<<<gemmGrid, 256, GEMM_DSMEM>>>(chi, clo, whi + 3 * WN, wlo + 3 * WN,
                                                   bo, out, EE, EE, 1.0f);
}

// round 4
// speedup vs baseline: 2.5384x; 1.3935x over previous
#include <cuda_runtime.h>
#include <cuda_fp16.h>
#include <math.h>
#include <stdint.h>

// Problem constants
#define RR 128
#define CC 256
#define EE 768
#define HH 12
#define DKK 64
#define MTOK (RR*CC)          // 32768 tokens
#define NPART 4               // r-split for attention logits

// ---------------------------------------------------------------------------
// Scratch (device globals — no allocation allowed)
// ---------------------------------------------------------------------------
__device__ float g_q[(size_t)MTOK * EE];
__device__ float g_k[(size_t)MTOK * EE];
__device__ float g_v[(size_t)MTOK * EE];
__device__ float g_attn[(size_t)HH * CC * CC];
__device__ float g_attn_part[NPART][(size_t)HH * CC * CC];

__device__ __half g_xhi[(size_t)MTOK * EE];
__device__ __half g_xlo[(size_t)MTOK * EE];
__device__ __half g_chi[(size_t)MTOK * EE];
__device__ __half g_clo[(size_t)MTOK * EE];
__device__ __half g_whi[4][(size_t)EE * EE];

// ---------------------------------------------------------------------------
// Helpers (suffix-free PTX only: cp.async / ldmatrix / mma.sync)
// ---------------------------------------------------------------------------
__device__ __forceinline__ uint32_t smem_u32(const void* p) {
    uint32_t a;
    asm("{ .reg .u64 t; cvta.to.shared.u64 t, %1; cvt.u32.u64 %0, t; }"
        : "=r"(a) : "l"(p));
    return a;
}

__device__ __forceinline__ uint32_t swz(uint32_t off) {
    return off ^ ((off >> 3) & 0x30);   // 64B-row swizzle, conflict-free LDSM
}

__device__ __forceinline__ void cpa16(uint32_t dst, const void* src) {
    asm volatile("cp.async.cg.shared.global [%0], [%1], 16;"
                 :: "r"(dst), "l"(src));
}
#define CP_COMMIT() asm volatile("cp.async.commit_group;" ::: "memory")
#define CP_WAIT1()  asm volatile("cp.async.wait_group 1;" ::: "memory")

// A-fragment ldmatrix.x4: m16 x k16 tile from smem [row][64B], rows = m
__device__ __forceinline__ void ldsm4_a(uint32_t* r, uint32_t sb, int mbase, int k16) {
    int lane = threadIdx.x & 31;
    uint32_t row = mbase + (lane & 15);
    uint32_t cb  = (lane & 16);                    // +16B for k8-15 pieces
    uint32_t addr = sb + swz(row * 64 + k16 * 32 + cb);
    asm volatile("ldmatrix.sync.aligned.m8n8.x4.shared.b16 {%0,%1,%2,%3}, [%4];"
                 : "=r"(r[0]), "=r"(r[1]), "=r"(r[2]), "=r"(r[3]) : "r"(addr));
}

// B-fragment ldmatrix.x4: two n8 x k16 fragments from W[n][k] smem rows
__device__ __forceinline__ void ldsm4_b(uint32_t* r, uint32_t sb, int nbase, int k16) {
    int lane = threadIdx.x & 31;
    uint32_t row = nbase + (lane & 7) + ((lane & 16) >> 1);  // +8 rows for 2nd frag
    uint32_t cb  = (lane & 8) << 1;                          // +16B for k8-15
    uint32_t addr = sb + swz(row * 64 + k16 * 32 + cb);
    asm volatile("ldmatrix.sync.aligned.m8n8.x4.shared.b16 {%0,%1,%2,%3}, [%4];"
                 : "=r"(r[0]), "=r"(r[1]), "=r"(r[2]), "=r"(r[3]) : "r"(addr));
}

__device__ __forceinline__ void mma16816(float* c, const uint32_t* a, const uint32_t* b) {
    asm volatile(
        "mma.sync.aligned.m16n8k16.row.col.f32.f16.f16.f32 "
        "{%0,%1,%2,%3}, {%4,%5,%6,%7}, {%8,%9}, {%0,%1,%2,%3};"
        : "+f"(c[0]), "+f"(c[1]), "+f"(c[2]), "+f"(c[3])
        : "r"(a[0]), "r"(a[1]), "r"(a[2]), "r"(a[3]), "r"(b[0]), "r"(b[1]));
}

// ---------------------------------------------------------------------------
// Split fp32 -> fp16 (hi, lo) with lo = fp16(x - float(hi)).  n4 = n/4.
// ---------------------------------------------------------------------------
__global__ __launch_bounds__(256) void split_kernel(
    const float* __restrict__ src,
    __half* __restrict__ hi, __half* __restrict__ lo, int n4)
{
    int i = blockIdx.x * 256 + threadIdx.x;
    if (i >= n4) return;
    float4 v = ((const float4*)src)[i];
    __half h0 = __float2half(v.x);
    __half h1 = __float2half(v.y);
    __half h2 = __float2half(v.z);
    __half h3 = __float2half(v.w);
    __half l0 = __float2half(v.x - __half2float(h0));
    __half l1 = __float2half(v.y - __half2float(h1));
    __half l2 = __float2half(v.z - __half2float(h2));
    __half l3 = __float2half(v.w - __half2float(h3));
    __half2* hp = (__half2*)hi;
    __half2* lp = (__half2*)lo;
    hp[2 * i + 0] = __halves2half2(h0, h1);
    hp[2 * i + 1] = __halves2half2(h2, h3);
    lp[2 * i + 0] = __halves2half2(l0, l1);
    lp[2 * i + 1] = __halves2half2(l2, l3);
}

// hi-only variant for weights
__global__ __launch_bounds__(256) void split_hi_kernel(
    const float* __restrict__ src, __half* __restrict__ hi, int n4)
{
    int i = blockIdx.x * 256 + threadIdx.x;
    if (i >= n4) return;
    float4 v = ((const float4*)src)[i];
    __half2* hp = (__half2*)hi;
    hp[2 * i + 0] = __halves2half2(__float2half(v.x), __float2half(v.y));
    hp[2 * i + 1] = __halves2half2(__float2half(v.z), __float2half(v.w));
}

// ---------------------------------------------------------------------------
// HMMA fp16 split-precision NT GEMM (2 products):
//   out[m,n] = alpha * (sum_k A[m,k]*Whi[n,k] + bias[n]),  A = Ahi + Alo exact
// CTA 128x128, BK=32, 8 warps (2m x 4n), warp tile 64x32,
// 3-stage cp.async pipeline (3 tiles/stage), SW64 swizzle, ldmatrix fragments.
// ---------------------------------------------------------------------------
#define BKC 32
#define STG_BYTES 24576            // 3 tiles x 128 x 32 x 2B
#define GEMM_DSMEM (3 * STG_BYTES)

__global__ __launch_bounds__(256) void gemm_mma_kernel(
    const __half* __restrict__ Ahi, const __half* __restrict__ Alo,
    const __half* __restrict__ Whi,
    const float* __restrict__ bias, float* __restrict__ out,
    int Kdim, int Ndim, float alpha)
{
    extern __shared__ char dsm[];
    const uint32_t sbase = smem_u32(dsm);

    const int tid  = threadIdx.x;
    const int wid  = tid >> 5;
    const int lane = tid & 31;
    const int wm = wid >> 2;        // 0..1
    const int wn = wid & 3;         // 0..3
    const int bm = blockIdx.y * 128;
    const int bn = blockIdx.x * 128;
    const int nch = Kdim / BKC;     // 24

    const __half* srcs[3] = {
        Ahi + (size_t)bm * Kdim, Alo + (size_t)bm * Kdim,
        Whi + (size_t)bn * Kdim };

    // per-thread g2s mapping: 2 consecutive 16B segments per tile
    const int seg0 = tid * 2;
    const int row_g = seg0 >> 2;          // 0..127
    const int ch0   = seg0 & 3;           // 0 or 2

    auto load_stage = [&](int kc, int buf) {
#pragma unroll
        for (int t = 0; t < 3; t++) {
            const __half* s = srcs[t] + (size_t)row_g * Kdim + kc * BKC;
            uint32_t base = sbase + buf * STG_BYTES + t * 8192;
            cpa16(base + swz(row_g * 64 + (ch0 + 0) * 16), s + (ch0 + 0) * 8);
            cpa16(base + swz(row_g * 64 + (ch0 + 1) * 16), s + (ch0 + 1) * 8);
        }
        CP_COMMIT();
    };

    float acc[4][4][4];
#pragma unroll
    for (int mt = 0; mt < 4; mt++)
#pragma unroll
        for (int nt = 0; nt < 4; nt++)
#pragma unroll
            for (int e = 0; e < 4; e++) acc[mt][nt][e] = 0.f;

    load_stage(0, 0);
    load_stage(1, 1);

    for (int kc = 0; kc < nch; kc++) {
        CP_WAIT1();
        __syncthreads();
        int nb = kc + 2;
        if (nb < nch) load_stage(nb, nb % 3);
        else CP_COMMIT();                      // keep group counts uniform

        const uint32_t st = sbase + (kc % 3) * STG_BYTES;
        const uint32_t sAh = st, sAl = st + 8192, sWh = st + 16384;

#pragma unroll
        for (int k16 = 0; k16 < 2; k16++) {
            uint32_t Ah[4][4], Al[4][4], Bh[2][4];
#pragma unroll
            for (int mt = 0; mt < 4; mt++) ldsm4_a(Ah[mt], sAh, wm * 64 + mt * 16, k16);
#pragma unroll
            for (int mt = 0; mt < 4; mt++) ldsm4_a(Al[mt], sAl, wm * 64 + mt * 16, k16);
#pragma unroll
            for (int p = 0; p < 2; p++) ldsm4_b(Bh[p], sWh, wn * 32 + p * 16, k16);

#pragma unroll
            for (int mt = 0; mt < 4; mt++) {
#pragma unroll
                for (int nt = 0; nt < 4; nt++) {
                    const uint32_t* bh = &Bh[nt >> 1][(nt & 1) * 2];
                    mma16816(acc[mt][nt], Ah[mt], bh);   // hi*hi
                    mma16816(acc[mt][nt], Al[mt], bh);   // lo*hi
                }
            }
        }
    }

    // Epilogue: c0,c1 -> (row, col..col+1); c2,c3 -> (row+8, ...)
#pragma unroll
    for (int mt = 0; mt < 4; mt++) {
        const int m0 = bm + wm * 64 + mt * 16 + (lane >> 2);
#pragma unroll
        for (int nt = 0; nt < 4; nt++) {
            const int col = bn + wn * 32 + nt * 8 + 2 * (lane & 3);
            const float b0 = bias[col], b1 = bias[col + 1];
            float2 v0 = make_float2(alpha * (acc[mt][nt][0] + b0),
                                    alpha * (acc[mt][nt][1] + b1));
            float2 v1 = make_float2(alpha * (acc[mt][nt][2] + b0),
                                    alpha * (acc[mt][nt][3] + b1));
            *(float2*)(out + (size_t)m0 * Ndim + col) = v0;
            *(float2*)(out + (size_t)(m0 + 8) * Ndim + col) = v1;
        }
    }
}

// ---------------------------------------------------------------------------
// Attention logits (partial over r): part[p][h,i,j] = sum_{r in chunk p, d} q*k
// grid: (4 j-tiles, 4 i-tiles, HH*NPART). 256 threads, 4x4 microtile.
// ---------------------------------------------------------------------------
__global__ __launch_bounds__(256) void attn_logits_kernel()
{
    __shared__ float Qs[64][68];   // [d][i]
    __shared__ float Ks[64][68];   // [d][j]

    const int zz = blockIdx.z;
    const int h  = zz % HH;
    const int p  = zz / HH;
    const int i0 = blockIdx.y * 64;
    const int j0 = blockIdx.x * 64;
    const int tid = threadIdx.x;
    const int lr = tid >> 2;        // 0..63
    const int g  = tid & 3;
    const int tx = tid & 15;
    const int ty = tid >> 4;

    float acc[4][4];
#pragma unroll
    for (int i = 0; i < 4; i++)
#pragma unroll
        for (int j = 0; j < 4; j++) acc[i][j] = 0.f;

    const int rbeg = p * (RR / NPART);
    const int rend = rbeg + (RR / NPART);
    for (int r = rbeg; r < rend; r++) {
        const float* qb = g_q + ((size_t)r * CC) * EE + h * DKK;
        const float* kb = g_k + ((size_t)r * CC) * EE + h * DKK;
        __syncthreads();
#pragma unroll
        for (int f = 0; f < 4; f++) {
            int d = 16 * g + 4 * f;
            float4 qv = *(const float4*)(qb + (size_t)(i0 + lr) * EE + d);
            float4 kv = *(const float4*)(kb + (size_t)(j0 + lr) * EE + d);
            Qs[d+0][lr] = qv.x; Qs[d+1][lr] = qv.y; Qs[d+2][lr] = qv.z; Qs[d+3][lr] = qv.w;
            Ks[d+0][lr] = kv.x; Ks[d+1][lr] = kv.y; Ks[d+2][lr] = kv.z; Ks[d+3][lr] = kv.w;
        }
        __syncthreads();
#pragma unroll
        for (int kk = 0; kk < 64; kk++) {
            float4 av = *(const float4*)&Qs[kk][ty * 4];
            float4 bv = *(const float4*)&Ks[kk][tx * 4];
            float a[4] = {av.x, av.y, av.z, av.w};
            float b[4] = {bv.x, bv.y, bv.z, bv.w};
#pragma unroll
            for (int i = 0; i < 4; i++)
#pragma unroll
                for (int j = 0; j < 4; j++)
                    acc[i][j] = fmaf(a[i], b[j], acc[i][j]);
        }
    }

    float* ab = g_attn_part[p] + (size_t)h * CC * CC;
#pragma unroll
    for (int i = 0; i < 4; i++)
#pragma unroll
        for (int j = 0; j < 4; j++)
            ab[(size_t)(i0 + ty * 4 + i) * CC + j0 + tx * 4 + j] = acc[i][j];
}

// ---------------------------------------------------------------------------
// Row softmax over j (256); sums the NPART partials first.
// ---------------------------------------------------------------------------
__global__ __launch_bounds__(256) void softmax_kernel(float* __restrict__ probs_out)
{
    __shared__ float red[256];
    const int row = blockIdx.x;                 // 0 .. H*C-1
    const int tid = threadIdx.x;
    float v = 0.f;
#pragma unroll
    for (int pp = 0; pp < NPART; pp++)
        v += g_attn_part[pp][(size_t)row * CC + tid];

    red[tid] = v; __syncthreads();
    for (int s = 128; s > 0; s >>= 1) {
        if (tid < s) red[tid] = fmaxf(red[tid], red[tid + s]);
        __syncthreads();
    }
    float mx = red[0];
    __syncthreads();

    float e = __expf(v - mx);
    red[tid] = e; __syncthreads();
    for (int s = 128; s > 0; s >>= 1) {
        if (tid < s) red[tid] += red[tid + s];
        __syncthreads();
    }
    float pr = e / red[0];

    g_attn[(size_t)row * CC + tid] = pr;
    probs_out[(size_t)row * CC + tid] = pr;
}

// ---------------------------------------------------------------------------
// Context: c[(r*C+i)*E + h*DK + d] = sum_j probs[h,i,j] * v[(r*C+j)*E + h*DK + d]
// Writes c as fp16 (hi, lo) directly — feeds the O projection.
// ---------------------------------------------------------------------------
__global__ __launch_bounds__(256) void context_kernel()
{
    __shared__ float Ps[64][68];   // [j][i]
    __shared__ float Vs[64][68];   // [j][d]

    const int i0 = blockIdx.x * 64;
    const int h  = blockIdx.y;
    const int r  = blockIdx.z;
    const int tid = threadIdx.x;
    const int lr = tid >> 2;
    const int g  = tid & 3;
    const int tx = tid & 15;
    const int ty = tid >> 4;

    float acc[4][4];
#pragma unroll
    for (int i = 0; i < 4; i++)
#pragma unroll
        for (int j = 0; j < 4; j++) acc[i][j] = 0.f;

    const float* pb = g_attn + (size_t)h * CC * CC;
    const float* vb = g_v + ((size_t)r * CC) * EE + h * DKK;

    for (int j0 = 0; j0 < CC; j0 += 64) {
        __syncthreads();
#pragma unroll
        for (int f = 0; f < 4; f++) {
            int c4 = 16 * g + 4 * f;
            float4 pv = *(const float4*)(pb + (size_t)(i0 + lr) * CC + j0 + c4);
            Ps[c4+0][lr] = pv.x; Ps[c4+1][lr] = pv.y; Ps[c4+2][lr] = pv.z; Ps[c4+3][lr] = pv.w;
            float4 vv = *(const float4*)(vb + (size_t)(j0 + lr) * EE + c4);
            *(float4*)&Vs[lr][c4] = vv;
        }
        __syncthreads();
#pragma unroll
        for (int kk = 0; kk < 64; kk++) {
            float4 av = *(const float4*)&Ps[kk][ty * 4];
            float4 bv = *(const float4*)&Vs[kk][tx * 4];
            float a[4] = {av.x, av.y, av.z, av.w};
            float b[4] = {bv.x, bv.y, bv.z, bv.w};
#pragma unroll
            for (int i = 0; i < 4; i++)
#pragma unroll
                for (int j = 0; j < 4; j++)
                    acc[i][j] = fmaf(a[i], b[j], acc[i][j]);
        }
    }

    __half* chb = g_chi + ((size_t)r * CC) * EE + h * DKK;
    __half* clb = g_clo + ((size_t)r * CC) * EE + h * DKK;
#pragma unroll
    for (int i = 0; i < 4; i++) {
        size_t rowoff = (size_t)(i0 + ty * 4 + i) * EE + tx * 4;
        __half2 h2[2], l2[2];
#pragma unroll
        for (int j2 = 0; j2 < 2; j2++) {
            float a0 = acc[i][j2 * 2 + 0], a1 = acc[i][j2 * 2 + 1];
            __half h0 = __float2half(a0), h1 = __float2half(a1);
            h2[j2] = __halves2half2(h0, h1);
            l2[j2] = __halves2half2(__float2half(a0 - __half2float(h0)),
                                    __float2half(a1 - __half2float(h1)));
        }
        *(__half2*)(chb + rowoff) = h2[0];
        *(__half2*)(chb + rowoff + 2) = h2[1];
        *(__half2*)(clb + rowoff) = l2[0];
        *(__half2*)(clb + rowoff + 2) = l2[1];
    }
}

// ---------------------------------------------------------------------------
extern "C" void kernel_launch(void* const* d_in, const int* in_sizes, int n_in,
                              void* d_out, int out_size)
{
    const float* x  = (const float*)d_in[0];
    const float* Wq = (const float*)d_in[1];
    const float* bq = (const float*)d_in[2];
    const float* Wk = (const float*)d_in[3];
    const float* bk = (const float*)d_in[4];
    const float* Wv = (const float*)d_in[5];
    const float* bv = (const float*)d_in[6];
    const float* Wo = (const float*)d_in[7];
    const float* bo = (const float*)d_in[8];

    float* out = (float*)d_out;                       // [R,C,B,E]
    float* probs = out + (size_t)MTOK * EE;           // [H,B,C,C]

    float* q; cudaGetSymbolAddress((void**)&q, g_q);
    float* k; cudaGetSymbolAddress((void**)&k, g_k);
    float* v; cudaGetSymbolAddress((void**)&v, g_v);
    __half* xhi; cudaGetSymbolAddress((void**)&xhi, g_xhi);
    __half* xlo; cudaGetSymbolAddress((void**)&xlo, g_xlo);
    __half* chi; cudaGetSymbolAddress((void**)&chi, g_chi);
    __half* clo; cudaGetSymbolAddress((void**)&clo, g_clo);
    __half* whi; cudaGetSymbolAddress((void**)&whi, g_whi);

    cudaFuncSetAttribute(gemm_mma_kernel,
                         cudaFuncAttributeMaxDynamicSharedMemorySize, GEMM_DSMEM);

    const float scaling = 0.125f / sqrtf((float)RR);  // DK^-0.5 / sqrt(R)
    const size_t WN = (size_t)EE * EE;

    // splits
    {
        int n4x = (int)((size_t)MTOK * EE / 4);
        split_kernel<<<(n4x + 255) / 256, 256>>>(x, xhi, xlo, n4x);
        int n4w = (int)(WN / 4);
        split_hi_kernel<<<(n4w + 255) / 256, 256>>>(Wq, whi + 0 * WN, n4w);
        split_hi_kernel<<<(n4w + 255) / 256, 256>>>(Wk, whi + 1 * WN, n4w);
        split_hi_kernel<<<(n4w + 255) / 256, 256>>>(Wv, whi + 2 * WN, n4w);
        split_hi_kernel<<<(n4w + 255) / 256, 256>>>(Wo, whi + 3 * WN, n4w);
    }

    dim3 gemmGrid(EE / 128, MTOK / 128);              // (6, 256)
    gemm_mma_kernel<<<gemmGrid, 256, GEMM_DSMEM>>>(xhi, xlo, whi + 0 * WN,
                                                   bq, q, EE, EE, scaling);
    gemm_mma_kernel<<<gemmGrid, 256, GEMM_DSMEM>>>(xhi, xlo, whi + 1 * WN,
                                                   bk, k, EE, EE, 1.0f);
    gemm_mma_kernel<<<gemmGrid, 256, GEMM_DSMEM>>>(xhi, xlo, whi + 2 * WN,
                                                   bv, v, EE, EE, 1.0f);

    attn_logits_kernel<<<dim3(4, 4, HH * NPART), 256>>>();
    softmax_kernel<<<HH * CC, 256>>>(probs);
    context_kernel<<<dim3(4, HH, RR), 256>>>();

    gemm_mma_kernel<<<gemmGrid, 256, GEMM_DSMEM>>>(chi, clo, whi + 3 * WN,
                                                   bo, out, EE, EE, 1.0f);
}

// round 5
// speedup vs baseline: 3.5770x; 1.4091x over previous
#include <cuda_runtime.h>
#include <cuda_fp16.h>
#include <math.h>
#include <stdint.h>

// Problem constants
#define RR 128
#define CC 256
#define EE 768
#define HH 12
#define DKK 64
#define MTOK (RR*CC)          // 32768 tokens
#define NPARTL 8              // r-split for attention logits

// ---------------------------------------------------------------------------
// Scratch (device globals — no allocation allowed)
// ---------------------------------------------------------------------------
__device__ float g_attn_part[NPARTL][(size_t)HH * CC * CC];

__device__ __half g_xhi[(size_t)MTOK * EE];
__device__ __half g_xlo[(size_t)MTOK * EE];
__device__ __half g_qhi[(size_t)MTOK * EE];
__device__ __half g_qlo[(size_t)MTOK * EE];
__device__ __half g_khi[(size_t)MTOK * EE];
__device__ __half g_vt [(size_t)EE * MTOK];     // V transposed: [E][token]
__device__ __half g_phi[(size_t)HH * CC * CC];
__device__ __half g_plo[(size_t)HH * CC * CC];
__device__ __half g_chi[(size_t)MTOK * EE];
__device__ __half g_clo[(size_t)MTOK * EE];
__device__ __half g_whi[4][(size_t)EE * EE];

// ---------------------------------------------------------------------------
// Helpers (suffix-free PTX only: cp.async / ldmatrix / mma.sync)
// ---------------------------------------------------------------------------
__device__ __forceinline__ uint32_t smem_u32(const void* p) {
    uint32_t a;
    asm("{ .reg .u64 t; cvta.to.shared.u64 t, %1; cvt.u32.u64 %0, t; }"
        : "=r"(a) : "l"(p));
    return a;
}

__device__ __forceinline__ uint32_t swz64(uint32_t off) {
    return off ^ ((off >> 3) & 0x30);   // 64B-row swizzle
}
__device__ __forceinline__ uint32_t swz128(uint32_t off) {
    return off ^ ((off >> 3) & 0x70);   // 128B-row swizzle
}

__device__ __forceinline__ void cpa16(uint32_t dst, const void* src) {
    asm volatile("cp.async.cg.shared.global [%0], [%1], 16;"
                 :: "r"(dst), "l"(src));
}
#define CP_COMMIT() asm volatile("cp.async.commit_group;" ::: "memory")
#define CP_WAIT1()  asm volatile("cp.async.wait_group 1;" ::: "memory")
#define CP_WAIT0()  asm volatile("cp.async.wait_group 0;" ::: "memory")

// ldmatrix x4 from 64B-row tile: A side (m16 x k16)
__device__ __forceinline__ void ldsm4_a(uint32_t* r, uint32_t sb, int mbase, int k16) {
    int lane = threadIdx.x & 31;
    uint32_t row = mbase + (lane & 15);
    uint32_t cb  = (lane & 16);
    uint32_t addr = sb + swz64(row * 64 + k16 * 32 + cb);
    asm volatile("ldmatrix.sync.aligned.m8n8.x4.shared.b16 {%0,%1,%2,%3}, [%4];"
                 : "=r"(r[0]), "=r"(r[1]), "=r"(r[2]), "=r"(r[3]) : "r"(addr));
}
// ldmatrix x4 from 64B-row tile: B side (two n8 x k16 frags)
__device__ __forceinline__ void ldsm4_b(uint32_t* r, uint32_t sb, int nbase, int k16) {
    int lane = threadIdx.x & 31;
    uint32_t row = nbase + (lane & 7) + ((lane & 16) >> 1);
    uint32_t cb  = (lane & 8) << 1;
    uint32_t addr = sb + swz64(row * 64 + k16 * 32 + cb);
    asm volatile("ldmatrix.sync.aligned.m8n8.x4.shared.b16 {%0,%1,%2,%3}, [%4];"
                 : "=r"(r[0]), "=r"(r[1]), "=r"(r[2]), "=r"(r[3]) : "r"(addr));
}
// 128B-row variants (BK=64 tiles)
__device__ __forceinline__ void ldsm4_a128(uint32_t* r, uint32_t sb, int mbase, int k16) {
    int lane = threadIdx.x & 31;
    uint32_t row = mbase + (lane & 15);
    uint32_t cb  = (lane & 16);
    uint32_t addr = sb + swz128(row * 128 + k16 * 32 + cb);
    asm volatile("ldmatrix.sync.aligned.m8n8.x4.shared.b16 {%0,%1,%2,%3}, [%4];"
                 : "=r"(r[0]), "=r"(r[1]), "=r"(r[2]), "=r"(r[3]) : "r"(addr));
}
__device__ __forceinline__ void ldsm4_b128(uint32_t* r, uint32_t sb, int nbase, int k16) {
    int lane = threadIdx.x & 31;
    uint32_t row = nbase + (lane & 7) + ((lane & 16) >> 1);
    uint32_t cb  = (lane & 8) << 1;
    uint32_t addr = sb + swz128(row * 128 + k16 * 32 + cb);
    asm volatile("ldmatrix.sync.aligned.m8n8.x4.shared.b16 {%0,%1,%2,%3}, [%4];"
                 : "=r"(r[0]), "=r"(r[1]), "=r"(r[2]), "=r"(r[3]) : "r"(addr));
}

__device__ __forceinline__ void mma16816(float* c, const uint32_t* a, const uint32_t* b) {
    asm volatile(
        "mma.sync.aligned.m16n8k16.row.col.f32.f16.f16.f32 "
        "{%0,%1,%2,%3}, {%4,%5,%6,%7}, {%8,%9}, {%0,%1,%2,%3};"
        : "+f"(c[0]), "+f"(c[1]), "+f"(c[2]), "+f"(c[3])
        : "r"(a[0]), "r"(a[1]), "r"(a[2]), "r"(a[3]), "r"(b[0]), "r"(b[1]));
}

// ---------------------------------------------------------------------------
// Split fp32 -> fp16 (hi, lo); and hi-only variant.
// ---------------------------------------------------------------------------
__global__ __launch_bounds__(256) void split_kernel(
    const float* __restrict__ src,
    __half* __restrict__ hi, __half* __restrict__ lo, int n4)
{
    int i = blockIdx.x * 256 + threadIdx.x;
    if (i >= n4) return;
    float4 v = ((const float4*)src)[i];
    __half h0 = __float2half(v.x), h1 = __float2half(v.y);
    __half h2 = __float2half(v.z), h3 = __float2half(v.w);
    __half2* hp = (__half2*)hi;
    __half2* lp = (__half2*)lo;
    hp[2 * i + 0] = __halves2half2(h0, h1);
    hp[2 * i + 1] = __halves2half2(h2, h3);
    lp[2 * i + 0] = __halves2half2(__float2half(v.x - __half2float(h0)),
                                   __float2half(v.y - __half2float(h1)));
    lp[2 * i + 1] = __halves2half2(__float2half(v.z - __half2float(h2)),
                                   __float2half(v.w - __half2float(h3)));
}

__global__ __launch_bounds__(256) void split_hi_kernel(
    const float* __restrict__ src, __half* __restrict__ hi, int n4)
{
    int i = blockIdx.x * 256 + threadIdx.x;
    if (i >= n4) return;
    float4 v = ((const float4*)src)[i];
    __half2* hp = (__half2*)hi;
    hp[2 * i + 0] = __halves2half2(__float2half(v.x), __float2half(v.y));
    hp[2 * i + 1] = __halves2half2(__float2half(v.z), __float2half(v.w));
}

// ---------------------------------------------------------------------------
// Fused QKV projection GEMM (HMMA, fp16 split A, 2 products):
//   proj[m,n] = sum_k x[m,k]*W[n,k] + b[n]
// N = 3*768 combined; per-n-tile epilogue:
//   wsel 0 (Q): q = scaling*proj -> g_qhi/g_qlo
//   wsel 1 (K): g_khi
//   wsel 2 (V): transposed -> g_vt[n][m]  (smem transpose, coalesced)
// CTA 128x128, BK=32, 8 warps (2m x 4n), 3-stage cp.async pipeline.
// ---------------------------------------------------------------------------
#define BKC 32
#define STG3 24576            // 3 tiles x 128 x 32 x 2B
#define GEMM_DSMEM (3 * STG3)

__global__ __launch_bounds__(256) void qkv_gemm_kernel(
    const __half* __restrict__ Ahi, const __half* __restrict__ Alo,
    const float* __restrict__ bq, const float* __restrict__ bk,
    const float* __restrict__ bv, float scaling)
{
    extern __shared__ char dsm[];
    const uint32_t sbase = smem_u32(dsm);

    const int tid  = threadIdx.x;
    const int wid  = tid >> 5;
    const int lane = tid & 31;
    const int wm = wid >> 2;
    const int wn = wid & 3;
    const int bm = blockIdx.y * 128;
    const int bng = blockIdx.x * 128;
    const int wsel = bng / EE;
    const int bn = bng - wsel * EE;
    const int Kdim = EE;
    const int nch = Kdim / BKC;     // 24

    const __half* W = g_whi[wsel];
    const float* bias = (wsel == 0) ? bq : (wsel == 1) ? bk : bv;

    const __half* srcs[3] = {
        Ahi + (size_t)bm * Kdim, Alo + (size_t)bm * Kdim,
        W + (size_t)bn * Kdim };

    const int seg0 = tid * 2;
    const int row_g = seg0 >> 2;
    const int ch0   = seg0 & 3;

    auto load_stage = [&](int kc, int buf) {
#pragma unroll
        for (int t = 0; t < 3; t++) {
            const __half* s = srcs[t] + (size_t)row_g * Kdim + kc * BKC;
            uint32_t base = sbase + buf * STG3 + t * 8192;
            cpa16(base + swz64(row_g * 64 + (ch0 + 0) * 16), s + (ch0 + 0) * 8);
            cpa16(base + swz64(row_g * 64 + (ch0 + 1) * 16), s + (ch0 + 1) * 8);
        }
        CP_COMMIT();
    };

    float acc[4][4][4];
#pragma unroll
    for (int mt = 0; mt < 4; mt++)
#pragma unroll
        for (int nt = 0; nt < 4; nt++)
#pragma unroll
            for (int e = 0; e < 4; e++) acc[mt][nt][e] = 0.f;

    load_stage(0, 0);
    load_stage(1, 1);

    for (int kc = 0; kc < nch; kc++) {
        CP_WAIT1();
        __syncthreads();
        int nb = kc + 2;
        if (nb < nch) load_stage(nb, nb % 3);
        else CP_COMMIT();

        const uint32_t st = sbase + (kc % 3) * STG3;
        const uint32_t sAh = st, sAl = st + 8192, sWh = st + 16384;

#pragma unroll
        for (int k16 = 0; k16 < 2; k16++) {
            uint32_t Ah[4][4], Al[4][4], Bh[2][4];
#pragma unroll
            for (int mt = 0; mt < 4; mt++) ldsm4_a(Ah[mt], sAh, wm * 64 + mt * 16, k16);
#pragma unroll
            for (int mt = 0; mt < 4; mt++) ldsm4_a(Al[mt], sAl, wm * 64 + mt * 16, k16);
#pragma unroll
            for (int p = 0; p < 2; p++) ldsm4_b(Bh[p], sWh, wn * 32 + p * 16, k16);

#pragma unroll
            for (int mt = 0; mt < 4; mt++)
#pragma unroll
                for (int nt = 0; nt < 4; nt++) {
                    const uint32_t* bh = &Bh[nt >> 1][(nt & 1) * 2];
                    mma16816(acc[mt][nt], Ah[mt], bh);
                    mma16816(acc[mt][nt], Al[mt], bh);
                }
        }
    }

    if (wsel == 2) {
        // V: transpose via smem, write g_vt[n][m] coalesced
        CP_WAIT0();
        __syncthreads();
        __half* smt = (__half*)dsm;     // [128 n][128 m]
#pragma unroll
        for (int mt = 0; mt < 4; mt++) {
            const int ml = wm * 64 + mt * 16 + (lane >> 2);
#pragma unroll
            for (int nt = 0; nt < 4; nt++) {
                const int nl = wn * 32 + nt * 8 + 2 * (lane & 3);
                const float b0 = bias[bn + nl], b1 = bias[bn + nl + 1];
                smt[(nl + 0) * 128 + ml] = __float2half(acc[mt][nt][0] + b0);
                smt[(nl + 1) * 128 + ml] = __float2half(acc[mt][nt][1] + b1);
                smt[(nl + 0) * 128 + ml + 8] = __float2half(acc[mt][nt][2] + b0);
                smt[(nl + 1) * 128 + ml + 8] = __float2half(acc[mt][nt][3] + b1);
            }
        }
        __syncthreads();
        const int nrow = tid >> 1;
        const int seg  = tid & 1;
        const uint4* srcv = (const uint4*)(smt + nrow * 128 + seg * 64);
        uint4* dstv = (uint4*)(g_vt + (size_t)(bn + nrow) * MTOK + bm + seg * 64);
#pragma unroll
        for (int u = 0; u < 8; u++) dstv[u] = srcv[u];
        return;
    }

#pragma unroll
    for (int mt = 0; mt < 4; mt++) {
        const int m0 = bm + wm * 64 + mt * 16 + (lane >> 2);
#pragma unroll
        for (int nt = 0; nt < 4; nt++) {
            const int col = bn + wn * 32 + nt * 8 + 2 * (lane & 3);
            const float b0 = bias[col], b1 = bias[col + 1];
            float v00 = acc[mt][nt][0] + b0, v01 = acc[mt][nt][1] + b1;
            float v10 = acc[mt][nt][2] + b0, v11 = acc[mt][nt][3] + b1;
            if (wsel == 0) {
                v00 *= scaling; v01 *= scaling; v10 *= scaling; v11 *= scaling;
                __half h00 = __float2half(v00), h01 = __float2half(v01);
                __half h10 = __float2half(v10), h11 = __float2half(v11);
                *(__half2*)(g_qhi + (size_t)m0 * EE + col) = __halves2half2(h00, h01);
                *(__half2*)(g_qhi + (size_t)(m0 + 8) * EE + col) = __halves2half2(h10, h11);
                *(__half2*)(g_qlo + (size_t)m0 * EE + col) =
                    __halves2half2(__float2half(v00 - __half2float(h00)),
                                   __float2half(v01 - __half2float(h01)));
                *(__half2*)(g_qlo + (size_t)(m0 + 8) * EE + col) =
                    __halves2half2(__float2half(v10 - __half2float(h10)),
                                   __float2half(v11 - __half2float(h11)));
            } else {
                *(__half2*)(g_khi + (size_t)m0 * EE + col) =
                    __halves2half2(__float2half(v00), __float2half(v01));
                *(__half2*)(g_khi + (size_t)(m0 + 8) * EE + col) =
                    __halves2half2(__float2half(v10), __float2half(v11));
            }
        }
    }
}

// ---------------------------------------------------------------------------
// O projection GEMM: out = c @ Wo.T + bo  (fp32 out), c = chi + clo
// ---------------------------------------------------------------------------
__global__ __launch_bounds__(256) void o_gemm_kernel(
    const float* __restrict__ bias, float* __restrict__ out)
{
    extern __shared__ char dsm[];
    const uint32_t sbase = smem_u32(dsm);

    const int tid  = threadIdx.x;
    const int wid  = tid >> 5;
    const int lane = tid & 31;
    const int wm = wid >> 2;
    const int wn = wid & 3;
    const int bm = blockIdx.y * 128;
    const int bn = blockIdx.x * 128;
    const int Kdim = EE;
    const int nch = Kdim / BKC;

    const __half* srcs[3] = {
        g_chi + (size_t)bm * Kdim, g_clo + (size_t)bm * Kdim,
        g_whi[3] + (size_t)bn * Kdim };

    const int seg0 = tid * 2;
    const int row_g = seg0 >> 2;
    const int ch0   = seg0 & 3;

    auto load_stage = [&](int kc, int buf) {
#pragma unroll
        for (int t = 0; t < 3; t++) {
            const __half* s = srcs[t] + (size_t)row_g * Kdim + kc * BKC;
            uint32_t base = sbase + buf * STG3 + t * 8192;
            cpa16(base + swz64(row_g * 64 + (ch0 + 0) * 16), s + (ch0 + 0) * 8);
            cpa16(base + swz64(row_g * 64 + (ch0 + 1) * 16), s + (ch0 + 1) * 8);
        }
        CP_COMMIT();
    };

    float acc[4][4][4];
#pragma unroll
    for (int mt = 0; mt < 4; mt++)
#pragma unroll
        for (int nt = 0; nt < 4; nt++)
#pragma unroll
            for (int e = 0; e < 4; e++) acc[mt][nt][e] = 0.f;

    load_stage(0, 0);
    load_stage(1, 1);

    for (int kc = 0; kc < nch; kc++) {
        CP_WAIT1();
        __syncthreads();
        int nb = kc + 2;
        if (nb < nch) load_stage(nb, nb % 3);
        else CP_COMMIT();

        const uint32_t st = sbase + (kc % 3) * STG3;
        const uint32_t sAh = st, sAl = st + 8192, sWh = st + 16384;

#pragma unroll
        for (int k16 = 0; k16 < 2; k16++) {
            uint32_t Ah[4][4], Al[4][4], Bh[2][4];
#pragma unroll
            for (int mt = 0; mt < 4; mt++) ldsm4_a(Ah[mt], sAh, wm * 64 + mt * 16, k16);
#pragma unroll
            for (int mt = 0; mt < 4; mt++) ldsm4_a(Al[mt], sAl, wm * 64 + mt * 16, k16);
#pragma unroll
            for (int p = 0; p < 2; p++) ldsm4_b(Bh[p], sWh, wn * 32 + p * 16, k16);

#pragma unroll
            for (int mt = 0; mt < 4; mt++)
#pragma unroll
                for (int nt = 0; nt < 4; nt++) {
                    const uint32_t* bh = &Bh[nt >> 1][(nt & 1) * 2];
                    mma16816(acc[mt][nt], Ah[mt], bh);
                    mma16816(acc[mt][nt], Al[mt], bh);
                }
        }
    }

#pragma unroll
    for (int mt = 0; mt < 4; mt++) {
        const int m0 = bm + wm * 64 + mt * 16 + (lane >> 2);
#pragma unroll
        for (int nt = 0; nt < 4; nt++) {
            const int col = bn + wn * 32 + nt * 8 + 2 * (lane & 3);
            const float b0 = bias[col], b1 = bias[col + 1];
            *(float2*)(out + (size_t)m0 * EE + col) =
                make_float2(acc[mt][nt][0] + b0, acc[mt][nt][1] + b1);
            *(float2*)(out + (size_t)(m0 + 8) * EE + col) =
                make_float2(acc[mt][nt][2] + b0, acc[mt][nt][3] + b1);
        }
    }
}

// ---------------------------------------------------------------------------
// Attention logits (HMMA): part[p][h,i,j] = sum_{r in chunk, d} q[i]*k[j]
// Per CTA: 128(i) x 128(j), K = 16 r x 64 d, BK = 64 (one r).
// grid (2 j, 2 i, HH*NPARTL). smem: 3 stages x 48KB.
// ---------------------------------------------------------------------------
#define LSTG 49152
#define LOGITS_DSMEM (3 * LSTG)

__global__ __launch_bounds__(256) void logits_kernel()
{
    extern __shared__ char dsm[];
    const uint32_t sbase = smem_u32(dsm);

    const int tid  = threadIdx.x;
    const int wid  = tid >> 5;
    const int lane = tid & 31;
    const int wm = wid >> 2;
    const int wn = wid & 3;
    const int j0 = blockIdx.x * 128;
    const int i0 = blockIdx.y * 128;
    const int h  = blockIdx.z % HH;
    const int p  = blockIdx.z / HH;
    const int rbeg = p * (RR / NPARTL);    // 16 r's per CTA
    const int nch = RR / NPARTL;

    const int lrow = tid & 127;
    const int sg0  = (tid >> 7) * 4;

    auto load_stage = [&](int rc, int buf) {
        const int r = rbeg + rc;
        const __half* qh = g_qhi + ((size_t)(r * CC + i0 + lrow)) * EE + h * DKK;
        const __half* ql = g_qlo + ((size_t)(r * CC + i0 + lrow)) * EE + h * DKK;
        const __half* kh = g_khi + ((size_t)(r * CC + j0 + lrow)) * EE + h * DKK;
        uint32_t b0 = sbase + buf * LSTG;
#pragma unroll
        for (int s = 0; s < 4; s++) {
            uint32_t off = swz128(lrow * 128 + (sg0 + s) * 16);
            cpa16(b0 + off, qh + (sg0 + s) * 8);
            cpa16(b0 + 16384 + off, ql + (sg0 + s) * 8);
            cpa16(b0 + 32768 + off, kh + (sg0 + s) * 8);
        }
        CP_COMMIT();
    };

    float acc[4][4][4];
#pragma unroll
    for (int mt = 0; mt < 4; mt++)
#pragma unroll
        for (int nt = 0; nt < 4; nt++)
#pragma unroll
            for (int e = 0; e < 4; e++) acc[mt][nt][e] = 0.f;

    load_stage(0, 0);
    load_stage(1, 1);

    for (int rc = 0; rc < nch; rc++) {
        CP_WAIT1();
        __syncthreads();
        int nb = rc + 2;
        if (nb < nch) load_stage(nb, nb % 3);
        else CP_COMMIT();

        const uint32_t st = sbase + (rc % 3) * LSTG;
        const uint32_t sQh = st, sQl = st + 16384, sKh = st + 32768;

#pragma unroll
        for (int k16 = 0; k16 < 4; k16++) {
            uint32_t Ah[4][4], Al[4][4], Bh[2][4];
#pragma unroll
            for (int mt = 0; mt < 4; mt++) ldsm4_a128(Ah[mt], sQh, wm * 64 + mt * 16, k16);
#pragma unroll
            for (int mt = 0; mt < 4; mt++) ldsm4_a128(Al[mt], sQl, wm * 64 + mt * 16, k16);
#pragma unroll
            for (int pq = 0; pq < 2; pq++) ldsm4_b128(Bh[pq], sKh, wn * 32 + pq * 16, k16);

#pragma unroll
            for (int mt = 0; mt < 4; mt++)
#pragma unroll
                for (int nt = 0; nt < 4; nt++) {
                    const uint32_t* bh = &Bh[nt >> 1][(nt & 1) * 2];
                    mma16816(acc[mt][nt], Ah[mt], bh);
                    mma16816(acc[mt][nt], Al[mt], bh);
                }
        }
    }

    float* ab = g_attn_part[p] + (size_t)h * CC * CC;
#pragma unroll
    for (int mt = 0; mt < 4; mt++) {
        const int m0 = i0 + wm * 64 + mt * 16 + (lane >> 2);
#pragma unroll
        for (int nt = 0; nt < 4; nt++) {
            const int col = j0 + wn * 32 + nt * 8 + 2 * (lane & 3);
            *(float2*)(ab + (size_t)m0 * CC + col) =
                make_float2(acc[mt][nt][0], acc[mt][nt][1]);
            *(float2*)(ab + (size_t)(m0 + 8) * CC + col) =
                make_float2(acc[mt][nt][2], acc[mt][nt][3]);
        }
    }
}

// ---------------------------------------------------------------------------
// Row softmax over j (256); sums NPARTL partials; writes fp32 probs (output)
// and fp16 hi/lo probs for the context GEMM.
// ---------------------------------------------------------------------------
__global__ __launch_bounds__(256) void softmax_kernel(float* __restrict__ probs_out)
{
    __shared__ float red[256];
    const int row = blockIdx.x;                 // 0 .. H*C-1
    const int tid = threadIdx.x;
    float v = 0.f;
#pragma unroll
    for (int pp = 0; pp < NPARTL; pp++)
        v += g_attn_part[pp][(size_t)row * CC + tid];

    red[tid] = v; __syncthreads();
    for (int s = 128; s > 0; s >>= 1) {
        if (tid < s) red[tid] = fmaxf(red[tid], red[tid + s]);
        __syncthreads();
    }
    float mx = red[0];
    __syncthreads();

    float e = __expf(v - mx);
    red[tid] = e; __syncthreads();
    for (int s = 128; s > 0; s >>= 1) {
        if (tid < s) red[tid] += red[tid + s];
        __syncthreads();
    }
    float pr = e / red[0];

    probs_out[(size_t)row * CC + tid] = pr;
    __half hh = __float2half(pr);
    g_phi[(size_t)row * CC + tid] = hh;
    g_plo[(size_t)row * CC + tid] = __float2half(pr - __half2float(hh));
}

// ---------------------------------------------------------------------------
// Context (HMMA): c[(r*C+i), (h,d)] = sum_j probs[h,i,j] * v_t[h*64+d][r*C+j]
// Per CTA: fixed (h, r); 128(i) x 64(d), K = 256(j), BK = 32.
// grid (2 i-tiles, RR, HH). Writes chi/clo fp16 for the O projection.
// ---------------------------------------------------------------------------
#define CSTG 20480             // Phi 8K + Plo 8K + V 4K
#define CTX_DSMEM (3 * CSTG)

__global__ __launch_bounds__(256) void context_kernel()
{
    extern __shared__ char dsm[];
    const uint32_t sbase = smem_u32(dsm);

    const int tid  = threadIdx.x;
    const int wid  = tid >> 5;
    const int lane = tid & 31;
    const int wm = wid >> 2;        // 0..1
    const int wn = wid & 3;         // 0..3
    const int i0 = blockIdx.x * 128;
    const int r  = blockIdx.y;
    const int h  = blockIdx.z;
    const int nch = CC / BKC;       // 8

    const __half* Ph = g_phi + (size_t)h * CC * CC + (size_t)i0 * CC;
    const __half* Pl = g_plo + (size_t)h * CC * CC + (size_t)i0 * CC;
    const __half* Vb = g_vt + (size_t)(h * DKK) * MTOK + (size_t)r * CC;

    // A loads: rows 128, 2 segs/thread; B loads: 64 rows, 1 seg/thread
    const int arow = tid >> 1;
    const int asp  = (tid & 1) * 2;
    const int brow = tid >> 2;
    const int bsg  = tid & 3;

    auto load_stage = [&](int kc, int buf) {
        uint32_t b0 = sbase + buf * CSTG;
        const __half* sa = Ph + (size_t)arow * CC + kc * BKC;
        const __half* sl = Pl + (size_t)arow * CC + kc * BKC;
        cpa16(b0 + swz64(arow * 64 + (asp + 0) * 16), sa + (asp + 0) * 8);
        cpa16(b0 + swz64(arow * 64 + (asp + 1) * 16), sa + (asp + 1) * 8);
        cpa16(b0 + 8192 + swz64(arow * 64 + (asp + 0) * 16), sl + (asp + 0) * 8);
        cpa16(b0 + 8192 + swz64(arow * 64 + (asp + 1) * 16), sl + (asp + 1) * 8);
        const __half* sv = Vb + (size_t)brow * MTOK + kc * BKC;
        cpa16(b0 + 16384 + swz64(brow * 64 + bsg * 16), sv + bsg * 8);
        CP_COMMIT();
    };

    float acc[4][2][4];
#pragma unroll
    for (int mt = 0; mt < 4; mt++)
#pragma unroll
        for (int nt = 0; nt < 2; nt++)
#pragma unroll
            for (int e = 0; e < 4; e++) acc[mt][nt][e] = 0.f;

    load_stage(0, 0);
    load_stage(1, 1);

    for (int kc = 0; kc < nch; kc++) {
        CP_WAIT1();
        __syncthreads();
        int nb = kc + 2;
        if (nb < nch) load_stage(nb, nb % 3);
        else CP_COMMIT();

        const uint32_t st = sbase + (kc % 3) * CSTG;
        const uint32_t sPh = st, sPl = st + 8192, sV = st + 16384;

#pragma unroll
        for (int k16 = 0; k16 < 2; k16++) {
            uint32_t Ah[4][4], Al[4][4], Bh[4];
#pragma unroll
            for (int mt = 0; mt < 4; mt++) ldsm4_a(Ah[mt], sPh, wm * 64 + mt * 16, k16);
#pragma unroll
            for (int mt = 0; mt < 4; mt++) ldsm4_a(Al[mt], sPl, wm * 64 + mt * 16, k16);
            ldsm4_b(Bh, sV, wn * 16, k16);

#pragma unroll
            for (int mt = 0; mt < 4; mt++)
#pragma unroll
                for (int nt = 0; nt < 2; nt++) {
                    const uint32_t* bh = &Bh[nt * 2];
                    mma16816(acc[mt][nt], Ah[mt], bh);
                    mma16816(acc[mt][nt], Al[mt], bh);
                }
        }
    }

#pragma unroll
    for (int mt = 0; mt < 4; mt++) {
        const int iL = i0 + wm * 64 + mt * 16 + (lane >> 2);
        const size_t tok0 = (size_t)(r * CC + iL) * EE + h * DKK;
        const size_t tok1 = (size_t)(r * CC + iL + 8) * EE + h * DKK;
#pragma unroll
        for (int nt = 0; nt < 2; nt++) {
            const int col = wn * 16 + nt * 8 + 2 * (lane & 3);
            float v00 = acc[mt][nt][0], v01 = acc[mt][nt][1];
            float v10 = acc[mt][nt][2], v11 = acc[mt][nt][3];
            __half h00 = __float2half(v00), h01 = __float2half(v01);
            __half h10 = __float2half(v10), h11 = __float2half(v11);
            *(__half2*)(g_chi + tok0 + col) = __halves2half2(h00, h01);
            *(__half2*)(g_chi + tok1 + col) = __halves2half2(h10, h11);
            *(__half2*)(g_clo + tok0 + col) =
                __halves2half2(__float2half(v00 - __half2float(h00)),
                               __float2half(v01 - __half2float(h01)));
            *(__half2*)(g_clo + tok1 + col) =
                __halves2half2(__float2half(v10 - __half2float(h10)),
                               __float2half(v11 - __half2float(h11)));
        }
    }
}

// ---------------------------------------------------------------------------
extern "C" void kernel_launch(void* const* d_in, const int* in_sizes, int n_in,
                              void* d_out, int out_size)
{
    const float* x  = (const float*)d_in[0];
    const float* Wq = (const float*)d_in[1];
    const float* bq = (const float*)d_in[2];
    const float* Wk = (const float*)d_in[3];
    const float* bk = (const float*)d_in[4];
    const float* Wv = (const float*)d_in[5];
    const float* bv = (const float*)d_in[6];
    const float* Wo = (const float*)d_in[7];
    const float* bo = (const float*)d_in[8];

    float* out = (float*)d_out;                       // [R,C,B,E]
    float* probs = out + (size_t)MTOK * EE;           // [H,B,C,C]

    __half* xhi; cudaGetSymbolAddress((void**)&xhi, g_xhi);
    __half* xlo; cudaGetSymbolAddress((void**)&xlo, g_xlo);
    __half* whi; cudaGetSymbolAddress((void**)&whi, g_whi);

    cudaFuncSetAttribute(qkv_gemm_kernel,
                         cudaFuncAttributeMaxDynamicSharedMemorySize, GEMM_DSMEM);
    cudaFuncSetAttribute(o_gemm_kernel,
                         cudaFuncAttributeMaxDynamicSharedMemorySize, GEMM_DSMEM);
    cudaFuncSetAttribute(logits_kernel,
                         cudaFuncAttributeMaxDynamicSharedMemorySize, LOGITS_DSMEM);
    cudaFuncSetAttribute(context_kernel,
                         cudaFuncAttributeMaxDynamicSharedMemorySize, CTX_DSMEM);

    const float scaling = 0.125f / sqrtf((float)RR);  // DK^-0.5 / sqrt(R)
    const size_t WN = (size_t)EE * EE;

    // splits
    {
        int n4x = (int)((size_t)MTOK * EE / 4);
        split_kernel<<<(n4x + 255) / 256, 256>>>(x, xhi, xlo, n4x);
        int n4w = (int)(WN / 4);
        split_hi_kernel<<<(n4w + 255) / 256, 256>>>(Wq, whi + 0 * WN, n4w);
        split_hi_kernel<<<(n4w + 255) / 256, 256>>>(Wk, whi + 1 * WN, n4w);
        split_hi_kernel<<<(n4w + 255) / 256, 256>>>(Wv, whi + 2 * WN, n4w);
        split_hi_kernel<<<(n4w + 255) / 256, 256>>>(Wo, whi + 3 * WN, n4w);
    }

    qkv_gemm_kernel<<<dim3(3 * EE / 128, MTOK / 128), 256, GEMM_DSMEM>>>(
        xhi, xlo, bq, bk, bv, scaling);

    logits_kernel<<<dim3(2, 2, HH * NPARTL), 256, LOGITS_DSMEM>>>();
    softmax_kernel<<<HH * CC, 256>>>(probs);
    context_kernel<<<dim3(2, RR, HH), 256, CTX_DSMEM>>>();

    o_gemm_kernel<<<dim3(EE / 128, MTOK / 128), 256, GEMM_DSMEM>>>(bo, out);
}

// round 6
// speedup vs baseline: 4.6528x; 1.3007x over previous
#include <cuda_runtime.h>
#include <cuda_fp16.h>
#include <math.h>
#include <stdint.h>

// Problem constants
#define RR 128
#define CC 256
#define EE 768
#define HH 12
#define DKK 64
#define MTOK (RR*CC)          // 32768 tokens
#define NPARTL 8              // r-split for attention logits

// ---------------------------------------------------------------------------
// Scratch (device globals — no allocation allowed)
// ---------------------------------------------------------------------------
__device__ float g_attn_part[NPARTL][(size_t)HH * CC * CC];

__device__ __half g_xhi[(size_t)MTOK * EE];
__device__ __half g_xlo[(size_t)MTOK * EE];
__device__ __half g_qhi[(size_t)MTOK * EE];
__device__ __half g_qlo[(size_t)MTOK * EE];
__device__ __half g_khi[(size_t)MTOK * EE];
__device__ __half g_vt [(size_t)EE * MTOK];     // V transposed: [E][token]
__device__ __half g_phi[(size_t)HH * CC * CC];
__device__ __half g_plo[(size_t)HH * CC * CC];
__device__ __half g_chi[(size_t)MTOK * EE];
__device__ __half g_clo[(size_t)MTOK * EE];
__device__ __half g_whi[4][(size_t)EE * EE];

// ---------------------------------------------------------------------------
// Helpers (suffix-free PTX only: cp.async / ldmatrix / mma.sync)
// ---------------------------------------------------------------------------
__device__ __forceinline__ uint32_t smem_u32(const void* p) {
    uint32_t a;
    asm("{ .reg .u64 t; cvta.to.shared.u64 t, %1; cvt.u32.u64 %0, t; }"
        : "=r"(a) : "l"(p));
    return a;
}

__device__ __forceinline__ uint32_t swz64(uint32_t off) {
    return off ^ ((off >> 3) & 0x30);   // 64B-row swizzle
}
__device__ __forceinline__ uint32_t swz128(uint32_t off) {
    return off ^ ((off >> 3) & 0x70);   // 128B-row swizzle
}

__device__ __forceinline__ void cpa16(uint32_t dst, const void* src) {
    asm volatile("cp.async.cg.shared.global [%0], [%1], 16;"
                 :: "r"(dst), "l"(src));
}
#define CP_COMMIT() asm volatile("cp.async.commit_group;" ::: "memory")
#define CP_WAIT1()  asm volatile("cp.async.wait_group 1;" ::: "memory")
#define CP_WAIT0()  asm volatile("cp.async.wait_group 0;" ::: "memory")

// ldmatrix x4 from 64B-row tile: A side (m16 x k16)
__device__ __forceinline__ void ldsm4_a(uint32_t* r, uint32_t sb, int mbase, int k16) {
    int lane = threadIdx.x & 31;
    uint32_t row = mbase + (lane & 15);
    uint32_t cb  = (lane & 16);
    uint32_t addr = sb + swz64(row * 64 + k16 * 32 + cb);
    asm volatile("ldmatrix.sync.aligned.m8n8.x4.shared.b16 {%0,%1,%2,%3}, [%4];"
                 : "=r"(r[0]), "=r"(r[1]), "=r"(r[2]), "=r"(r[3]) : "r"(addr));
}
// ldmatrix x4 from 64B-row tile: B side (two n8 x k16 frags)
__device__ __forceinline__ void ldsm4_b(uint32_t* r, uint32_t sb, int nbase, int k16) {
    int lane = threadIdx.x & 31;
    uint32_t row = nbase + (lane & 7) + ((lane & 16) >> 1);
    uint32_t cb  = (lane & 8) << 1;
    uint32_t addr = sb + swz64(row * 64 + k16 * 32 + cb);
    asm volatile("ldmatrix.sync.aligned.m8n8.x4.shared.b16 {%0,%1,%2,%3}, [%4];"
                 : "=r"(r[0]), "=r"(r[1]), "=r"(r[2]), "=r"(r[3]) : "r"(addr));
}
// 128B-row variants (BK=64 tiles)
__device__ __forceinline__ void ldsm4_a128(uint32_t* r, uint32_t sb, int mbase, int k16) {
    int lane = threadIdx.x & 31;
    uint32_t row = mbase + (lane & 15);
    uint32_t cb  = (lane & 16);
    uint32_t addr = sb + swz128(row * 128 + k16 * 32 + cb);
    asm volatile("ldmatrix.sync.aligned.m8n8.x4.shared.b16 {%0,%1,%2,%3}, [%4];"
                 : "=r"(r[0]), "=r"(r[1]), "=r"(r[2]), "=r"(r[3]) : "r"(addr));
}
__device__ __forceinline__ void ldsm4_b128(uint32_t* r, uint32_t sb, int nbase, int k16) {
    int lane = threadIdx.x & 31;
    uint32_t row = nbase + (lane & 7) + ((lane & 16) >> 1);
    uint32_t cb  = (lane & 8) << 1;
    uint32_t addr = sb + swz128(row * 128 + k16 * 32 + cb);
    asm volatile("ldmatrix.sync.aligned.m8n8.x4.shared.b16 {%0,%1,%2,%3}, [%4];"
                 : "=r"(r[0]), "=r"(r[1]), "=r"(r[2]), "=r"(r[3]) : "r"(addr));
}

__device__ __forceinline__ void mma16816(float* c, const uint32_t* a, const uint32_t* b) {
    asm volatile(
        "mma.sync.aligned.m16n8k16.row.col.f32.f16.f16.f32 "
        "{%0,%1,%2,%3}, {%4,%5,%6,%7}, {%8,%9}, {%0,%1,%2,%3};"
        : "+f"(c[0]), "+f"(c[1]), "+f"(c[2]), "+f"(c[3])
        : "r"(a[0]), "r"(a[1]), "r"(a[2]), "r"(a[3]), "r"(b[0]), "r"(b[1]));
}

// ---------------------------------------------------------------------------
// Splits
// ---------------------------------------------------------------------------
__global__ __launch_bounds__(256) void split_kernel(
    const float* __restrict__ src,
    __half* __restrict__ hi, __half* __restrict__ lo, int n4)
{
    int i = blockIdx.x * 256 + threadIdx.x;
    if (i >= n4) return;
    float4 v = ((const float4*)src)[i];
    __half h0 = __float2half(v.x), h1 = __float2half(v.y);
    __half h2 = __float2half(v.z), h3 = __float2half(v.w);
    __half2* hp = (__half2*)hi;
    __half2* lp = (__half2*)lo;
    hp[2 * i + 0] = __halves2half2(h0, h1);
    hp[2 * i + 1] = __halves2half2(h2, h3);
    lp[2 * i + 0] = __halves2half2(__float2half(v.x - __half2float(h0)),
                                   __float2half(v.y - __half2float(h1)));
    lp[2 * i + 1] = __halves2half2(__float2half(v.z - __half2float(h2)),
                                   __float2half(v.w - __half2float(h3)));
}

// Single launch converting all 4 weight matrices to fp16 hi.
__global__ __launch_bounds__(256) void wsplit_kernel(
    const float* __restrict__ Wq, const float* __restrict__ Wk,
    const float* __restrict__ Wv, const float* __restrict__ Wo, int n4each)
{
    int i = blockIdx.x * 256 + threadIdx.x;
    int w = i / n4each;
    int j = i - w * n4each;
    if (w >= 4) return;
    const float* src = (w == 0) ? Wq : (w == 1) ? Wk : (w == 2) ? Wv : Wo;
    float4 v = ((const float4*)src)[j];
    __half2* hp = (__half2*)(g_whi[w]);
    hp[2 * j + 0] = __halves2half2(__float2half(v.x), __float2half(v.y));
    hp[2 * j + 1] = __halves2half2(__float2half(v.z), __float2half(v.w));
}

// ---------------------------------------------------------------------------
// Fused QKV projection GEMM (HMMA):
//   Q (wsel 0): 2-product (xhi+xlo)·Whi, scaled, -> g_qhi/g_qlo
//   K (wsel 1): 1-product xhi·Whi -> g_khi
//   V (wsel 2): 1-product xhi·Whi -> g_vt transposed
// CTA 128x128, BK=32, 8 warps (2m x 4n), 3-stage cp.async, 2 CTAs/SM forced.
// ---------------------------------------------------------------------------
#define BKC 32
#define STG3 24576            // 3 tiles x 128 x 32 x 2B
#define GEMM_DSMEM (3 * STG3)

__global__ __launch_bounds__(256, 2) void qkv_gemm_kernel(
    const __half* __restrict__ Ahi, const __half* __restrict__ Alo,
    const float* __restrict__ bq, const float* __restrict__ bk,
    const float* __restrict__ bv, float scaling)
{
    extern __shared__ char dsm[];
    const uint32_t sbase = smem_u32(dsm);

    const int tid  = threadIdx.x;
    const int wid  = tid >> 5;
    const int lane = tid & 31;
    const int wm = wid >> 2;
    const int wn = wid & 3;
    const int bm = blockIdx.y * 128;
    const int bng = blockIdx.x * 128;
    const int wsel = bng / EE;
    const int bn = bng - wsel * EE;
    const int Kdim = EE;
    const int nch = Kdim / BKC;     // 24
    const bool twoprod = (wsel == 0);

    const __half* W = g_whi[wsel];
    const float* bias = (wsel == 0) ? bq : (wsel == 1) ? bk : bv;

    const __half* srcA = Ahi + (size_t)bm * Kdim;
    const __half* srcL = Alo + (size_t)bm * Kdim;
    const __half* srcW = W + (size_t)bn * Kdim;

    const int seg0 = tid * 2;
    const int row_g = seg0 >> 2;
    const int ch0   = seg0 & 3;

    auto load_stage = [&](int kc, int buf) {
        uint32_t base = sbase + buf * STG3;
        const __half* sa = srcA + (size_t)row_g * Kdim + kc * BKC;
        cpa16(base + swz64(row_g * 64 + (ch0 + 0) * 16), sa + (ch0 + 0) * 8);
        cpa16(base + swz64(row_g * 64 + (ch0 + 1) * 16), sa + (ch0 + 1) * 8);
        if (twoprod) {
            const __half* sl = srcL + (size_t)row_g * Kdim + kc * BKC;
            cpa16(base + 8192 + swz64(row_g * 64 + (ch0 + 0) * 16), sl + (ch0 + 0) * 8);
            cpa16(base + 8192 + swz64(row_g * 64 + (ch0 + 1) * 16), sl + (ch0 + 1) * 8);
        }
        const __half* sw = srcW + (size_t)row_g * Kdim + kc * BKC;
        cpa16(base + 16384 + swz64(row_g * 64 + (ch0 + 0) * 16), sw + (ch0 + 0) * 8);
        cpa16(base + 16384 + swz64(row_g * 64 + (ch0 + 1) * 16), sw + (ch0 + 1) * 8);
        CP_COMMIT();
    };

    float acc[4][4][4];
#pragma unroll
    for (int mt = 0; mt < 4; mt++)
#pragma unroll
        for (int nt = 0; nt < 4; nt++)
#pragma unroll
            for (int e = 0; e < 4; e++) acc[mt][nt][e] = 0.f;

    load_stage(0, 0);
    load_stage(1, 1);

    for (int kc = 0; kc < nch; kc++) {
        CP_WAIT1();
        __syncthreads();
        int nb = kc + 2;
        if (nb < nch) load_stage(nb, nb % 3);
        else CP_COMMIT();

        const uint32_t st = sbase + (kc % 3) * STG3;
        const uint32_t sAh = st, sAl = st + 8192, sWh = st + 16384;

#pragma unroll
        for (int k16 = 0; k16 < 2; k16++) {
            uint32_t Ah[4][4], Bh[2][4];
#pragma unroll
            for (int mt = 0; mt < 4; mt++) ldsm4_a(Ah[mt], sAh, wm * 64 + mt * 16, k16);
#pragma unroll
            for (int p = 0; p < 2; p++) ldsm4_b(Bh[p], sWh, wn * 32 + p * 16, k16);

#pragma unroll
            for (int mt = 0; mt < 4; mt++)
#pragma unroll
                for (int nt = 0; nt < 4; nt++)
                    mma16816(acc[mt][nt], Ah[mt], &Bh[nt >> 1][(nt & 1) * 2]);

            if (twoprod) {
                uint32_t Al[4][4];
#pragma unroll
                for (int mt = 0; mt < 4; mt++) ldsm4_a(Al[mt], sAl, wm * 64 + mt * 16, k16);
#pragma unroll
                for (int mt = 0; mt < 4; mt++)
#pragma unroll
                    for (int nt = 0; nt < 4; nt++)
                        mma16816(acc[mt][nt], Al[mt], &Bh[nt >> 1][(nt & 1) * 2]);
            }
        }
    }

    if (wsel == 2) {
        // V: transpose via smem, write g_vt[n][m] coalesced
        CP_WAIT0();
        __syncthreads();
        __half* smt = (__half*)dsm;     // [128 n][128 m]
#pragma unroll
        for (int mt = 0; mt < 4; mt++) {
            const int ml = wm * 64 + mt * 16 + (lane >> 2);
#pragma unroll
            for (int nt = 0; nt < 4; nt++) {
                const int nl = wn * 32 + nt * 8 + 2 * (lane & 3);
                const float b0 = bias[bn + nl], b1 = bias[bn + nl + 1];
                smt[(nl + 0) * 128 + ml] = __float2half(acc[mt][nt][0] + b0);
                smt[(nl + 1) * 128 + ml] = __float2half(acc[mt][nt][1] + b1);
                smt[(nl + 0) * 128 + ml + 8] = __float2half(acc[mt][nt][2] + b0);
                smt[(nl + 1) * 128 + ml + 8] = __float2half(acc[mt][nt][3] + b1);
            }
        }
        __syncthreads();
        const int nrow = tid >> 1;
        const int seg  = tid & 1;
        const uint4* srcv = (const uint4*)(smt + nrow * 128 + seg * 64);
        uint4* dstv = (uint4*)(g_vt + (size_t)(bn + nrow) * MTOK + bm + seg * 64);
#pragma unroll
        for (int u = 0; u < 8; u++) dstv[u] = srcv[u];
        return;
    }

#pragma unroll
    for (int mt = 0; mt < 4; mt++) {
        const int m0 = bm + wm * 64 + mt * 16 + (lane >> 2);
#pragma unroll
        for (int nt = 0; nt < 4; nt++) {
            const int col = bn + wn * 32 + nt * 8 + 2 * (lane & 3);
            const float b0 = bias[col], b1 = bias[col + 1];
            float v00 = acc[mt][nt][0] + b0, v01 = acc[mt][nt][1] + b1;
            float v10 = acc[mt][nt][2] + b0, v11 = acc[mt][nt][3] + b1;
            if (wsel == 0) {
                v00 *= scaling; v01 *= scaling; v10 *= scaling; v11 *= scaling;
                __half h00 = __float2half(v00), h01 = __float2half(v01);
                __half h10 = __float2half(v10), h11 = __float2half(v11);
                *(__half2*)(g_qhi + (size_t)m0 * EE + col) = __halves2half2(h00, h01);
                *(__half2*)(g_qhi + (size_t)(m0 + 8) * EE + col) = __halves2half2(h10, h11);
                *(__half2*)(g_qlo + (size_t)m0 * EE + col) =
                    __halves2half2(__float2half(v00 - __half2float(h00)),
                                   __float2half(v01 - __half2float(h01)));
                *(__half2*)(g_qlo + (size_t)(m0 + 8) * EE + col) =
                    __halves2half2(__float2half(v10 - __half2float(h10)),
                                   __float2half(v11 - __half2float(h11)));
            } else {
                *(__half2*)(g_khi + (size_t)m0 * EE + col) =
                    __halves2half2(__float2half(v00), __float2half(v01));
                *(__half2*)(g_khi + (size_t)(m0 + 8) * EE + col) =
                    __halves2half2(__float2half(v10), __float2half(v11));
            }
        }
    }
}

// ---------------------------------------------------------------------------
// O projection GEMM: out = c @ Wo.T + bo  (fp32 out), c = chi + clo, 2-product
// ---------------------------------------------------------------------------
__global__ __launch_bounds__(256, 2) void o_gemm_kernel(
    const float* __restrict__ bias, float* __restrict__ out)
{
    extern __shared__ char dsm[];
    const uint32_t sbase = smem_u32(dsm);

    const int tid  = threadIdx.x;
    const int wid  = tid >> 5;
    const int lane = tid & 31;
    const int wm = wid >> 2;
    const int wn = wid & 3;
    const int bm = blockIdx.y * 128;
    const int bn = blockIdx.x * 128;
    const int Kdim = EE;
    const int nch = Kdim / BKC;

    const __half* srcs[3] = {
        g_chi + (size_t)bm * Kdim, g_clo + (size_t)bm * Kdim,
        g_whi[3] + (size_t)bn * Kdim };

    const int seg0 = tid * 2;
    const int row_g = seg0 >> 2;
    const int ch0   = seg0 & 3;

    auto load_stage = [&](int kc, int buf) {
#pragma unroll
        for (int t = 0; t < 3; t++) {
            const __half* s = srcs[t] + (size_t)row_g * Kdim + kc * BKC;
            uint32_t base = sbase + buf * STG3 + t * 8192;
            cpa16(base + swz64(row_g * 64 + (ch0 + 0) * 16), s + (ch0 + 0) * 8);
            cpa16(base + swz64(row_g * 64 + (ch0 + 1) * 16), s + (ch0 + 1) * 8);
        }
        CP_COMMIT();
    };

    float acc[4][4][4];
#pragma unroll
    for (int mt = 0; mt < 4; mt++)
#pragma unroll
        for (int nt = 0; nt < 4; nt++)
#pragma unroll
            for (int e = 0; e < 4; e++) acc[mt][nt][e] = 0.f;

    load_stage(0, 0);
    load_stage(1, 1);

    for (int kc = 0; kc < nch; kc++) {
        CP_WAIT1();
        __syncthreads();
        int nb = kc + 2;
        if (nb < nch) load_stage(nb, nb % 3);
        else CP_COMMIT();

        const uint32_t st = sbase + (kc % 3) * STG3;
        const uint32_t sAh = st, sAl = st + 8192, sWh = st + 16384;

#pragma unroll
        for (int k16 = 0; k16 < 2; k16++) {
            uint32_t Ah[4][4], Bh[2][4];
#pragma unroll
            for (int mt = 0; mt < 4; mt++) ldsm4_a(Ah[mt], sAh, wm * 64 + mt * 16, k16);
#pragma unroll
            for (int p = 0; p < 2; p++) ldsm4_b(Bh[p], sWh, wn * 32 + p * 16, k16);
#pragma unroll
            for (int mt = 0; mt < 4; mt++)
#pragma unroll
                for (int nt = 0; nt < 4; nt++)
                    mma16816(acc[mt][nt], Ah[mt], &Bh[nt >> 1][(nt & 1) * 2]);

            uint32_t Al[4][4];
#pragma unroll
            for (int mt = 0; mt < 4; mt++) ldsm4_a(Al[mt], sAl, wm * 64 + mt * 16, k16);
#pragma unroll
            for (int mt = 0; mt < 4; mt++)
#pragma unroll
                for (int nt = 0; nt < 4; nt++)
                    mma16816(acc[mt][nt], Al[mt], &Bh[nt >> 1][(nt & 1) * 2]);
        }
    }

#pragma unroll
    for (int mt = 0; mt < 4; mt++) {
        const int m0 = bm + wm * 64 + mt * 16 + (lane >> 2);
#pragma unroll
        for (int nt = 0; nt < 4; nt++) {
            const int col = bn + wn * 32 + nt * 8 + 2 * (lane & 3);
            const float b0 = bias[col], b1 = bias[col + 1];
            *(float2*)(out + (size_t)m0 * EE + col) =
                make_float2(acc[mt][nt][0] + b0, acc[mt][nt][1] + b1);
            *(float2*)(out + (size_t)(m0 + 8) * EE + col) =
                make_float2(acc[mt][nt][2] + b0, acc[mt][nt][3] + b1);
        }
    }
}

// ---------------------------------------------------------------------------
// Attention logits (HMMA): part[p][h,i,j] = sum_{r in chunk, d} q[i]*k[j]
// Per CTA: 128(i) x 128(j), BK = 64 (one r). grid (2 j, 2 i, HH*NPARTL).
// ---------------------------------------------------------------------------
#define LSTG 49152
#define LOGITS_DSMEM (3 * LSTG)

__global__ __launch_bounds__(256) void logits_kernel()
{
    extern __shared__ char dsm[];
    const uint32_t sbase = smem_u32(dsm);

    const int tid  = threadIdx.x;
    const int wid  = tid >> 5;
    const int lane = tid & 31;
    const int wm = wid >> 2;
    const int wn = wid & 3;
    const int j0 = blockIdx.x * 128;
    const int i0 = blockIdx.y * 128;
    const int h  = blockIdx.z % HH;
    const int p  = blockIdx.z / HH;
    const int rbeg = p * (RR / NPARTL);    // 16 r's per CTA
    const int nch = RR / NPARTL;

    const int lrow = tid & 127;
    const int sg0  = (tid >> 7) * 4;

    auto load_stage = [&](int rc, int buf) {
        const int r = rbeg + rc;
        const __half* qh = g_qhi + ((size_t)(r * CC + i0 + lrow)) * EE + h * DKK;
        const __half* ql = g_qlo + ((size_t)(r * CC + i0 + lrow)) * EE + h * DKK;
        const __half* kh = g_khi + ((size_t)(r * CC + j0 + lrow)) * EE + h * DKK;
        uint32_t b0 = sbase + buf * LSTG;
#pragma unroll
        for (int s = 0; s < 4; s++) {
            uint32_t off = swz128(lrow * 128 + (sg0 + s) * 16);
            cpa16(b0 + off, qh + (sg0 + s) * 8);
            cpa16(b0 + 16384 + off, ql + (sg0 + s) * 8);
            cpa16(b0 + 32768 + off, kh + (sg0 + s) * 8);
        }
        CP_COMMIT();
    };

    float acc[4][4][4];
#pragma unroll
    for (int mt = 0; mt < 4; mt++)
#pragma unroll
        for (int nt = 0; nt < 4; nt++)
#pragma unroll
            for (int e = 0; e < 4; e++) acc[mt][nt][e] = 0.f;

    load_stage(0, 0);
    load_stage(1, 1);

    for (int rc = 0; rc < nch; rc++) {
        CP_WAIT1();
        __syncthreads();
        int nb = rc + 2;
        if (nb < nch) load_stage(nb, nb % 3);
        else CP_COMMIT();

        const uint32_t st = sbase + (rc % 3) * LSTG;
        const uint32_t sQh = st, sQl = st + 16384, sKh = st + 32768;

#pragma unroll
        for (int k16 = 0; k16 < 4; k16++) {
            uint32_t Ah[4][4], Bh[2][4];
#pragma unroll
            for (int mt = 0; mt < 4; mt++) ldsm4_a128(Ah[mt], sQh, wm * 64 + mt * 16, k16);
#pragma unroll
            for (int pq = 0; pq < 2; pq++) ldsm4_b128(Bh[pq], sKh, wn * 32 + pq * 16, k16);
#pragma unroll
            for (int mt = 0; mt < 4; mt++)
#pragma unroll
                for (int nt = 0; nt < 4; nt++)
                    mma16816(acc[mt][nt], Ah[mt], &Bh[nt >> 1][(nt & 1) * 2]);

            uint32_t Al[4][4];
#pragma unroll
            for (int mt = 0; mt < 4; mt++) ldsm4_a128(Al[mt], sQl, wm * 64 + mt * 16, k16);
#pragma unroll
            for (int mt = 0; mt < 4; mt++)
#pragma unroll
                for (int nt = 0; nt < 4; nt++)
                    mma16816(acc[mt][nt], Al[mt], &Bh[nt >> 1][(nt & 1) * 2]);
        }
    }

    float* ab = g_attn_part[p] + (size_t)h * CC * CC;
#pragma unroll
    for (int mt = 0; mt < 4; mt++) {
        const int m0 = i0 + wm * 64 + mt * 16 + (lane >> 2);
#pragma unroll
        for (int nt = 0; nt < 4; nt++) {
            const int col = j0 + wn * 32 + nt * 8 + 2 * (lane & 3);
            *(float2*)(ab + (size_t)m0 * CC + col) =
                make_float2(acc[mt][nt][0], acc[mt][nt][1]);
            *(float2*)(ab + (size_t)(m0 + 8) * CC + col) =
                make_float2(acc[mt][nt][2], acc[mt][nt][3]);
        }
    }
}

// ---------------------------------------------------------------------------
// Row softmax; sums NPARTL partials; writes fp32 probs + fp16 hi/lo probs.
// ---------------------------------------------------------------------------
__global__ __launch_bounds__(256) void softmax_kernel(float* __restrict__ probs_out)
{
    __shared__ float red[256];
    const int row = blockIdx.x;                 // 0 .. H*C-1
    const int tid = threadIdx.x;
    float v = 0.f;
#pragma unroll
    for (int pp = 0; pp < NPARTL; pp++)
        v += g_attn_part[pp][(size_t)row * CC + tid];

    red[tid] = v; __syncthreads();
    for (int s = 128; s > 0; s >>= 1) {
        if (tid < s) red[tid] = fmaxf(red[tid], red[tid + s]);
        __syncthreads();
    }
    float mx = red[0];
    __syncthreads();

    float e = __expf(v - mx);
    red[tid] = e; __syncthreads();
    for (int s = 128; s > 0; s >>= 1) {
        if (tid < s) red[tid] += red[tid + s];
        __syncthreads();
    }
    float pr = e / red[0];

    probs_out[(size_t)row * CC + tid] = pr;
    __half hh = __float2half(pr);
    g_phi[(size_t)row * CC + tid] = hh;
    g_plo[(size_t)row * CC + tid] = __float2half(pr - __half2float(hh));
}

// ---------------------------------------------------------------------------
// Context (HMMA): c = probs @ v_t rows; per CTA fixed (h, r), 128(i) x 64(d).
// ---------------------------------------------------------------------------
#define CSTG 20480             // Phi 8K + Plo 8K + V 4K
#define CTX_DSMEM (3 * CSTG)

__global__ __launch_bounds__(256, 2) void context_kernel()
{
    extern __shared__ char dsm[];
    const uint32_t sbase = smem_u32(dsm);

    const int tid  = threadIdx.x;
    const int wid  = tid >> 5;
    const int lane = tid & 31;
    const int wm = wid >> 2;        // 0..1
    const int wn = wid & 3;         // 0..3
    const int i0 = blockIdx.x * 128;
    const int r  = blockIdx.y;
    const int h  = blockIdx.z;
    const int nch = CC / BKC;       // 8

    const __half* Ph = g_phi + (size_t)h * CC * CC + (size_t)i0 * CC;
    const __half* Pl = g_plo + (size_t)h * CC * CC + (size_t)i0 * CC;
    const __half* Vb = g_vt + (size_t)(h * DKK) * MTOK + (size_t)r * CC;

    const int arow = tid >> 1;
    const int asp  = (tid & 1) * 2;
    const int brow = tid >> 2;
    const int bsg  = tid & 3;

    auto load_stage = [&](int kc, int buf) {
        uint32_t b0 = sbase + buf * CSTG;
        const __half* sa = Ph + (size_t)arow * CC + kc * BKC;
        const __half* sl = Pl + (size_t)arow * CC + kc * BKC;
        cpa16(b0 + swz64(arow * 64 + (asp + 0) * 16), sa + (asp + 0) * 8);
        cpa16(b0 + swz64(arow * 64 + (asp + 1) * 16), sa + (asp + 1) * 8);
        cpa16(b0 + 8192 + swz64(arow * 64 + (asp + 0) * 16), sl + (asp + 0) * 8);
        cpa16(b0 + 8192 + swz64(arow * 64 + (asp + 1) * 16), sl + (asp + 1) * 8);
        const __half* sv = Vb + (size_t)brow * MTOK + kc * BKC;
        cpa16(b0 + 16384 + swz64(brow * 64 + bsg * 16), sv + bsg * 8);
        CP_COMMIT();
    };

    float acc[4][2][4];
#pragma unroll
    for (int mt = 0; mt < 4; mt++)
#pragma unroll
        for (int nt = 0; nt < 2; nt++)
#pragma unroll
            for (int e = 0; e < 4; e++) acc[mt][nt][e] = 0.f;

    load_stage(0, 0);
    load_stage(1, 1);

    for (int kc = 0; kc < nch; kc++) {
        CP_WAIT1();
        __syncthreads();
        int nb = kc + 2;
        if (nb < nch) load_stage(nb, nb % 3);
        else CP_COMMIT();

        const uint32_t st = sbase + (kc % 3) * CSTG;
        const uint32_t sPh = st, sPl = st + 8192, sV = st + 16384;

#pragma unroll
        for (int k16 = 0; k16 < 2; k16++) {
            uint32_t Ah[4][4], Al[4][4], Bh[4];
#pragma unroll
            for (int mt = 0; mt < 4; mt++) ldsm4_a(Ah[mt], sPh, wm * 64 + mt * 16, k16);
#pragma unroll
            for (int mt = 0; mt < 4; mt++) ldsm4_a(Al[mt], sPl, wm * 64 + mt * 16, k16);
            ldsm4_b(Bh, sV, wn * 16, k16);

#pragma unroll
            for (int mt = 0; mt < 4; mt++)
#pragma unroll
                for (int nt = 0; nt < 2; nt++) {
                    mma16816(acc[mt][nt], Ah[mt], &Bh[nt * 2]);
                    mma16816(acc[mt][nt], Al[mt], &Bh[nt * 2]);
                }
        }
    }

#pragma unroll
    for (int mt = 0; mt < 4; mt++) {
        const int iL = i0 + wm * 64 + mt * 16 + (lane >> 2);
        const size_t tok0 = (size_t)(r * CC + iL) * EE + h * DKK;
        const size_t tok1 = (size_t)(r * CC + iL + 8) * EE + h * DKK;
#pragma unroll
        for (int nt = 0; nt < 2; nt++) {
            const int col = wn * 16 + nt * 8 + 2 * (lane & 3);
            float v00 = acc[mt][nt][0], v01 = acc[mt][nt][1];
            float v10 = acc[mt][nt][2], v11 = acc[mt][nt][3];
            __half h00 = __float2half(v00), h01 = __float2half(v01);
            __half h10 = __float2half(v10), h11 = __float2half(v11);
            *(__half2*)(g_chi + tok0 + col) = __halves2half2(h00, h01);
            *(__half2*)(g_chi + tok1 + col) = __halves2half2(h10, h11);
            *(__half2*)(g_clo + tok0 + col) =
                __halves2half2(__float2half(v00 - __half2float(h00)),
                               __float2half(v01 - __half2float(h01)));
            *(__half2*)(g_clo + tok1 + col) =
                __halves2half2(__float2half(v10 - __half2float(h10)),
                               __float2half(v11 - __half2float(h11)));
        }
    }
}

// ---------------------------------------------------------------------------
extern "C" void kernel_launch(void* const* d_in, const int* in_sizes, int n_in,
                              void* d_out, int out_size)
{
    const float* x  = (const float*)d_in[0];
    const float* Wq = (const float*)d_in[1];
    const float* bq = (const float*)d_in[2];
    const float* Wk = (const float*)d_in[3];
    const float* bk = (const float*)d_in[4];
    const float* Wv = (const float*)d_in[5];
    const float* bv = (const float*)d_in[6];
    const float* Wo = (const float*)d_in[7];
    const float* bo = (const float*)d_in[8];

    float* out = (float*)d_out;                       // [R,C,B,E]
    float* probs = out + (size_t)MTOK * EE;           // [H,B,C,C]

    __half* xhi; cudaGetSymbolAddress((void**)&xhi, g_xhi);
    __half* xlo; cudaGetSymbolAddress((void**)&xlo, g_xlo);

    cudaFuncSetAttribute(qkv_gemm_kernel,
                         cudaFuncAttributeMaxDynamicSharedMemorySize, GEMM_DSMEM);
    cudaFuncSetAttribute(o_gemm_kernel,
                         cudaFuncAttributeMaxDynamicSharedMemorySize, GEMM_DSMEM);
    cudaFuncSetAttribute(logits_kernel,
                         cudaFuncAttributeMaxDynamicSharedMemorySize, LOGITS_DSMEM);
    cudaFuncSetAttribute(context_kernel,
                         cudaFuncAttributeMaxDynamicSharedMemorySize, CTX_DSMEM);

    const float scaling = 0.125f / sqrtf((float)RR);  // DK^-0.5 / sqrt(R)
    const size_t WN = (size_t)EE * EE;

    // splits
    {
        int n4x = (int)((size_t)MTOK * EE / 4);
        split_kernel<<<(n4x + 255) / 256, 256>>>(x, xhi, xlo, n4x);
        int n4w = (int)(WN / 4);
        wsplit_kernel<<<(4 * n4w + 255) / 256, 256>>>(Wq, Wk, Wv, Wo, n4w);
    }

    qkv_gemm_kernel<<<dim3(3 * EE / 128, MTOK / 128), 256, GEMM_DSMEM>>>(
        xhi, xlo, bq, bk, bv, scaling);

    logits_kernel<<<dim3(2, 2, HH * NPARTL), 256, LOGITS_DSMEM>>>();
    softmax_kernel<<<HH * CC, 256>>>(probs);
    context_kernel<<<dim3(2, RR, HH), 256, CTX_DSMEM>>>();

    o_gemm_kernel<<<dim3(EE / 128, MTOK / 128), 256, GEMM_DSMEM>>>(bo, out);
}

// round 7
// speedup vs baseline: 5.5112x; 1.1845x over previous
#include <cuda_runtime.h>
#include <cuda_fp16.h>
#include <math.h>
#include <stdint.h>

// Problem constants
#define RR 128
#define CC 256
#define EE 768
#define HH 12
#define DKK 64
#define MTOK (RR*CC)          // 32768 tokens
#define NPARTL 16             // r-split for attention logits

// ---------------------------------------------------------------------------
// Scratch (device globals — no allocation allowed)
// ---------------------------------------------------------------------------
__device__ float g_attn_part[NPARTL][(size_t)HH * CC * CC];

__device__ __half g_xhi[(size_t)MTOK * EE];
__device__ __half g_qhi[(size_t)MTOK * EE];
__device__ __half g_khi[(size_t)MTOK * EE];
__device__ __half g_vt [(size_t)EE * MTOK];     // V transposed: [E][token]
__device__ __half g_phi[(size_t)HH * CC * CC];
__device__ __half g_plo[(size_t)HH * CC * CC];
__device__ __half g_chi[(size_t)MTOK * EE];
__device__ __half g_clo[(size_t)MTOK * EE];
__device__ __half g_whi[4][(size_t)EE * EE];

// ---------------------------------------------------------------------------
// Helpers (suffix-free PTX only: cp.async / ldmatrix / mma.sync)
// ---------------------------------------------------------------------------
__device__ __forceinline__ uint32_t smem_u32(const void* p) {
    uint32_t a;
    asm("{ .reg .u64 t; cvta.to.shared.u64 t, %1; cvt.u32.u64 %0, t; }"
        : "=r"(a) : "l"(p));
    return a;
}

__device__ __forceinline__ uint32_t swz64(uint32_t off) {
    return off ^ ((off >> 3) & 0x30);   // 64B-row swizzle
}
__device__ __forceinline__ uint32_t swz128(uint32_t off) {
    return off ^ ((off >> 3) & 0x70);   // 128B-row swizzle
}

__device__ __forceinline__ void cpa16(uint32_t dst, const void* src) {
    asm volatile("cp.async.cg.shared.global [%0], [%1], 16;"
                 :: "r"(dst), "l"(src));
}
#define CP_COMMIT() asm volatile("cp.async.commit_group;" ::: "memory")
#define CP_WAIT1()  asm volatile("cp.async.wait_group 1;" ::: "memory")
#define CP_WAIT0()  asm volatile("cp.async.wait_group 0;" ::: "memory")

// ldmatrix x4 from 64B-row tile: A side (m16 x k16)
__device__ __forceinline__ void ldsm4_a(uint32_t* r, uint32_t sb, int mbase, int k16) {
    int lane = threadIdx.x & 31;
    uint32_t row = mbase + (lane & 15);
    uint32_t cb  = (lane & 16);
    uint32_t addr = sb + swz64(row * 64 + k16 * 32 + cb);
    asm volatile("ldmatrix.sync.aligned.m8n8.x4.shared.b16 {%0,%1,%2,%3}, [%4];"
                 : "=r"(r[0]), "=r"(r[1]), "=r"(r[2]), "=r"(r[3]) : "r"(addr));
}
// ldmatrix x4 from 64B-row tile: B side (two n8 x k16 frags)
__device__ __forceinline__ void ldsm4_b(uint32_t* r, uint32_t sb, int nbase, int k16) {
    int lane = threadIdx.x & 31;
    uint32_t row = nbase + (lane & 7) + ((lane & 16) >> 1);
    uint32_t cb  = (lane & 8) << 1;
    uint32_t addr = sb + swz64(row * 64 + k16 * 32 + cb);
    asm volatile("ldmatrix.sync.aligned.m8n8.x4.shared.b16 {%0,%1,%2,%3}, [%4];"
                 : "=r"(r[0]), "=r"(r[1]), "=r"(r[2]), "=r"(r[3]) : "r"(addr));
}
// 128B-row variants (BK=64 tiles)
__device__ __forceinline__ void ldsm4_a128(uint32_t* r, uint32_t sb, int mbase, int k16) {
    int lane = threadIdx.x & 31;
    uint32_t row = mbase + (lane & 15);
    uint32_t cb  = (lane & 16);
    uint32_t addr = sb + swz128(row * 128 + k16 * 32 + cb);
    asm volatile("ldmatrix.sync.aligned.m8n8.x4.shared.b16 {%0,%1,%2,%3}, [%4];"
                 : "=r"(r[0]), "=r"(r[1]), "=r"(r[2]), "=r"(r[3]) : "r"(addr));
}
__device__ __forceinline__ void ldsm4_b128(uint32_t* r, uint32_t sb, int nbase, int k16) {
    int lane = threadIdx.x & 31;
    uint32_t row = nbase + (lane & 7) + ((lane & 16) >> 1);
    uint32_t cb  = (lane & 8) << 1;
    uint32_t addr = sb + swz128(row * 128 + k16 * 32 + cb);
    asm volatile("ldmatrix.sync.aligned.m8n8.x4.shared.b16 {%0,%1,%2,%3}, [%4];"
                 : "=r"(r[0]), "=r"(r[1]), "=r"(r[2]), "=r"(r[3]) : "r"(addr));
}

__device__ __forceinline__ void mma16816(float* c, const uint32_t* a, const uint32_t* b) {
    asm volatile(
        "mma.sync.aligned.m16n8k16.row.col.f32.f16.f16.f32 "
        "{%0,%1,%2,%3}, {%4,%5,%6,%7}, {%8,%9}, {%0,%1,%2,%3};"
        : "+f"(c[0]), "+f"(c[1]), "+f"(c[2]), "+f"(c[3])
        : "r"(a[0]), "r"(a[1]), "r"(a[2]), "r"(a[3]), "r"(b[0]), "r"(b[1]));
}

// ---------------------------------------------------------------------------
// Splits (hi only now — lo terms retired from x and weights)
// ---------------------------------------------------------------------------
__global__ __launch_bounds__(256) void xsplit_kernel(
    const float* __restrict__ src, int n4)
{
    int i = blockIdx.x * 256 + threadIdx.x;
    if (i >= n4) return;
    float4 v = ((const float4*)src)[i];
    __half2* hp = (__half2*)g_xhi;
    hp[2 * i + 0] = __halves2half2(__float2half(v.x), __float2half(v.y));
    hp[2 * i + 1] = __halves2half2(__float2half(v.z), __float2half(v.w));
}

__global__ __launch_bounds__(256) void wsplit_kernel(
    const float* __restrict__ Wq, const float* __restrict__ Wk,
    const float* __restrict__ Wv, const float* __restrict__ Wo, int n4each)
{
    int i = blockIdx.x * 256 + threadIdx.x;
    int w = i / n4each;
    int j = i - w * n4each;
    if (w >= 4) return;
    const float* src = (w == 0) ? Wq : (w == 1) ? Wk : (w == 2) ? Wv : Wo;
    float4 v = ((const float4*)src)[j];
    __half2* hp = (__half2*)(g_whi[w]);
    hp[2 * j + 0] = __halves2half2(__float2half(v.x), __float2half(v.y));
    hp[2 * j + 1] = __halves2half2(__float2half(v.z), __float2half(v.w));
}

// ---------------------------------------------------------------------------
// Fused QKV projection GEMM (HMMA, single product xhi·Whi for all three):
//   wsel 0 (Q): scaled -> g_qhi
//   wsel 1 (K): -> g_khi
//   wsel 2 (V): transposed -> g_vt[n][m]
// CTA 128x128, BK=32, 8 warps, 3-stage cp.async (2 tiles/stage), 2 CTAs/SM.
// ---------------------------------------------------------------------------
#define BKC 32
#define STG2 16384            // 2 tiles x 128 x 32 x 2B
#define GEMM_DSMEM (3 * STG2)

__global__ __launch_bounds__(256, 2) void qkv_gemm_kernel(
    const float* __restrict__ bq, const float* __restrict__ bk,
    const float* __restrict__ bv, float scaling)
{
    extern __shared__ char dsm[];
    const uint32_t sbase = smem_u32(dsm);

    const int tid  = threadIdx.x;
    const int wid  = tid >> 5;
    const int lane = tid & 31;
    const int wm = wid >> 2;
    const int wn = wid & 3;
    const int bm = blockIdx.y * 128;
    const int bng = blockIdx.x * 128;
    const int wsel = bng / EE;
    const int bn = bng - wsel * EE;
    const int Kdim = EE;
    const int nch = Kdim / BKC;     // 24

    const __half* W = g_whi[wsel];
    const float* bias = (wsel == 0) ? bq : (wsel == 1) ? bk : bv;

    const __half* srcA = g_xhi + (size_t)bm * Kdim;
    const __half* srcW = W + (size_t)bn * Kdim;

    const int seg0 = tid * 2;
    const int row_g = seg0 >> 2;
    const int ch0   = seg0 & 3;

    auto load_stage = [&](int kc, int buf) {
        uint32_t base = sbase + buf * STG2;
        const __half* sa = srcA + (size_t)row_g * Kdim + kc * BKC;
        cpa16(base + swz64(row_g * 64 + (ch0 + 0) * 16), sa + (ch0 + 0) * 8);
        cpa16(base + swz64(row_g * 64 + (ch0 + 1) * 16), sa + (ch0 + 1) * 8);
        const __half* sw = srcW + (size_t)row_g * Kdim + kc * BKC;
        cpa16(base + 8192 + swz64(row_g * 64 + (ch0 + 0) * 16), sw + (ch0 + 0) * 8);
        cpa16(base + 8192 + swz64(row_g * 64 + (ch0 + 1) * 16), sw + (ch0 + 1) * 8);
        CP_COMMIT();
    };

    float acc[4][4][4];
#pragma unroll
    for (int mt = 0; mt < 4; mt++)
#pragma unroll
        for (int nt = 0; nt < 4; nt++)
#pragma unroll
            for (int e = 0; e < 4; e++) acc[mt][nt][e] = 0.f;

    load_stage(0, 0);
    load_stage(1, 1);

    for (int kc = 0; kc < nch; kc++) {
        CP_WAIT1();
        __syncthreads();
        int nb = kc + 2;
        if (nb < nch) load_stage(nb, nb % 3);
        else CP_COMMIT();

        const uint32_t st = sbase + (kc % 3) * STG2;
        const uint32_t sAh = st, sWh = st + 8192;

#pragma unroll
        for (int k16 = 0; k16 < 2; k16++) {
            uint32_t Ah[4][4], Bh[2][4];
#pragma unroll
            for (int mt = 0; mt < 4; mt++) ldsm4_a(Ah[mt], sAh, wm * 64 + mt * 16, k16);
#pragma unroll
            for (int p = 0; p < 2; p++) ldsm4_b(Bh[p], sWh, wn * 32 + p * 16, k16);
#pragma unroll
            for (int mt = 0; mt < 4; mt++)
#pragma unroll
                for (int nt = 0; nt < 4; nt++)
                    mma16816(acc[mt][nt], Ah[mt], &Bh[nt >> 1][(nt & 1) * 2]);
        }
    }

    if (wsel == 2) {
        // V: transpose via smem, write g_vt[n][m] coalesced
        CP_WAIT0();
        __syncthreads();
        __half* smt = (__half*)dsm;     // [128 n][128 m] = 32KB <= 48KB
#pragma unroll
        for (int mt = 0; mt < 4; mt++) {
            const int ml = wm * 64 + mt * 16 + (lane >> 2);
#pragma unroll
            for (int nt = 0; nt < 4; nt++) {
                const int nl = wn * 32 + nt * 8 + 2 * (lane & 3);
                const float b0 = bias[bn + nl], b1 = bias[bn + nl + 1];
                smt[(nl + 0) * 128 + ml] = __float2half(acc[mt][nt][0] + b0);
                smt[(nl + 1) * 128 + ml] = __float2half(acc[mt][nt][1] + b1);
                smt[(nl + 0) * 128 + ml + 8] = __float2half(acc[mt][nt][2] + b0);
                smt[(nl + 1) * 128 + ml + 8] = __float2half(acc[mt][nt][3] + b1);
            }
        }
        __syncthreads();
        const int nrow = tid >> 1;
        const int seg  = tid & 1;
        const uint4* srcv = (const uint4*)(smt + nrow * 128 + seg * 64);
        uint4* dstv = (uint4*)(g_vt + (size_t)(bn + nrow) * MTOK + bm + seg * 64);
#pragma unroll
        for (int u = 0; u < 8; u++) dstv[u] = srcv[u];
        return;
    }

    __half* dst = (wsel == 0) ? g_qhi : g_khi;
    const float sc = (wsel == 0) ? scaling : 1.0f;
#pragma unroll
    for (int mt = 0; mt < 4; mt++) {
        const int m0 = bm + wm * 64 + mt * 16 + (lane >> 2);
#pragma unroll
        for (int nt = 0; nt < 4; nt++) {
            const int col = bn + wn * 32 + nt * 8 + 2 * (lane & 3);
            const float b0 = bias[col], b1 = bias[col + 1];
            *(__half2*)(dst + (size_t)m0 * EE + col) =
                __halves2half2(__float2half(sc * (acc[mt][nt][0] + b0)),
                               __float2half(sc * (acc[mt][nt][1] + b1)));
            *(__half2*)(dst + (size_t)(m0 + 8) * EE + col) =
                __halves2half2(__float2half(sc * (acc[mt][nt][2] + b0)),
                               __float2half(sc * (acc[mt][nt][3] + b1)));
        }
    }
}

// ---------------------------------------------------------------------------
// O projection GEMM: out = (chi + clo) @ Wo.T + bo  (fp32 out, 2-product)
// ---------------------------------------------------------------------------
#define OSTG 24576             // 3 tiles x 8KB
#define OGEMM_DSMEM (3 * OSTG)

__global__ __launch_bounds__(256, 2) void o_gemm_kernel(
    const float* __restrict__ bias, float* __restrict__ out)
{
    extern __shared__ char dsm[];
    const uint32_t sbase = smem_u32(dsm);

    const int tid  = threadIdx.x;
    const int wid  = tid >> 5;
    const int lane = tid & 31;
    const int wm = wid >> 2;
    const int wn = wid & 3;
    const int bm = blockIdx.y * 128;
    const int bn = blockIdx.x * 128;
    const int Kdim = EE;
    const int nch = Kdim / BKC;

    const __half* srcs[3] = {
        g_chi + (size_t)bm * Kdim, g_clo + (size_t)bm * Kdim,
        g_whi[3] + (size_t)bn * Kdim };

    const int seg0 = tid * 2;
    const int row_g = seg0 >> 2;
    const int ch0   = seg0 & 3;

    auto load_stage = [&](int kc, int buf) {
#pragma unroll
        for (int t = 0; t < 3; t++) {
            const __half* s = srcs[t] + (size_t)row_g * Kdim + kc * BKC;
            uint32_t base = sbase + buf * OSTG + t * 8192;
            cpa16(base + swz64(row_g * 64 + (ch0 + 0) * 16), s + (ch0 + 0) * 8);
            cpa16(base + swz64(row_g * 64 + (ch0 + 1) * 16), s + (ch0 + 1) * 8);
        }
        CP_COMMIT();
    };

    float acc[4][4][4];
#pragma unroll
    for (int mt = 0; mt < 4; mt++)
#pragma unroll
        for (int nt = 0; nt < 4; nt++)
#pragma unroll
            for (int e = 0; e < 4; e++) acc[mt][nt][e] = 0.f;

    load_stage(0, 0);
    load_stage(1, 1);

    for (int kc = 0; kc < nch; kc++) {
        CP_WAIT1();
        __syncthreads();
        int nb = kc + 2;
        if (nb < nch) load_stage(nb, nb % 3);
        else CP_COMMIT();

        const uint32_t st = sbase + (kc % 3) * OSTG;
        const uint32_t sAh = st, sAl = st + 8192, sWh = st + 16384;

#pragma unroll
        for (int k16 = 0; k16 < 2; k16++) {
            uint32_t Ah[4][4], Bh[2][4];
#pragma unroll
            for (int mt = 0; mt < 4; mt++) ldsm4_a(Ah[mt], sAh, wm * 64 + mt * 16, k16);
#pragma unroll
            for (int p = 0; p < 2; p++) ldsm4_b(Bh[p], sWh, wn * 32 + p * 16, k16);
#pragma unroll
            for (int mt = 0; mt < 4; mt++)
#pragma unroll
                for (int nt = 0; nt < 4; nt++)
                    mma16816(acc[mt][nt], Ah[mt], &Bh[nt >> 1][(nt & 1) * 2]);

            uint32_t Al[4][4];
#pragma unroll
            for (int mt = 0; mt < 4; mt++) ldsm4_a(Al[mt], sAl, wm * 64 + mt * 16, k16);
#pragma unroll
            for (int mt = 0; mt < 4; mt++)
#pragma unroll
                for (int nt = 0; nt < 4; nt++)
                    mma16816(acc[mt][nt], Al[mt], &Bh[nt >> 1][(nt & 1) * 2]);
        }
    }

#pragma unroll
    for (int mt = 0; mt < 4; mt++) {
        const int m0 = bm + wm * 64 + mt * 16 + (lane >> 2);
#pragma unroll
        for (int nt = 0; nt < 4; nt++) {
            const int col = bn + wn * 32 + nt * 8 + 2 * (lane & 3);
            const float b0 = bias[col], b1 = bias[col + 1];
            *(float2*)(out + (size_t)m0 * EE + col) =
                make_float2(acc[mt][nt][0] + b0, acc[mt][nt][1] + b1);
            *(float2*)(out + (size_t)(m0 + 8) * EE + col) =
                make_float2(acc[mt][nt][2] + b0, acc[mt][nt][3] + b1);
        }
    }
}

// ---------------------------------------------------------------------------
// Attention logits (HMMA, 1-product qhi·khi):
// Per CTA: 128(i) x 128(j), BK = 64 (one r), 8 r's per CTA.
// grid (2 j, 2 i, HH*NPARTL). 32KB/stage x 3 -> 2 CTAs/SM.
// ---------------------------------------------------------------------------
#define LSTG 32768
#define LOGITS_DSMEM (3 * LSTG)

__global__ __launch_bounds__(256, 2) void logits_kernel()
{
    extern __shared__ char dsm[];
    const uint32_t sbase = smem_u32(dsm);

    const int tid  = threadIdx.x;
    const int wid  = tid >> 5;
    const int lane = tid & 31;
    const int wm = wid >> 2;
    const int wn = wid & 3;
    const int j0 = blockIdx.x * 128;
    const int i0 = blockIdx.y * 128;
    const int h  = blockIdx.z % HH;
    const int p  = blockIdx.z / HH;
    const int rbeg = p * (RR / NPARTL);    // 8 r's per CTA
    const int nch = RR / NPARTL;

    const int lrow = tid & 127;
    const int sg0  = (tid >> 7) * 4;

    auto load_stage = [&](int rc, int buf) {
        const int r = rbeg + rc;
        const __half* qh = g_qhi + ((size_t)(r * CC + i0 + lrow)) * EE + h * DKK;
        const __half* kh = g_khi + ((size_t)(r * CC + j0 + lrow)) * EE + h * DKK;
        uint32_t b0 = sbase + buf * LSTG;
#pragma unroll
        for (int s = 0; s < 4; s++) {
            uint32_t off = swz128(lrow * 128 + (sg0 + s) * 16);
            cpa16(b0 + off, qh + (sg0 + s) * 8);
            cpa16(b0 + 16384 + off, kh + (sg0 + s) * 8);
        }
        CP_COMMIT();
    };

    float acc[4][4][4];
#pragma unroll
    for (int mt = 0; mt < 4; mt++)
#pragma unroll
        for (int nt = 0; nt < 4; nt++)
#pragma unroll
            for (int e = 0; e < 4; e++) acc[mt][nt][e] = 0.f;

    load_stage(0, 0);
    load_stage(1, 1);

    for (int rc = 0; rc < nch; rc++) {
        CP_WAIT1();
        __syncthreads();
        int nb = rc + 2;
        if (nb < nch) load_stage(nb, nb % 3);
        else CP_COMMIT();

        const uint32_t st = sbase + (rc % 3) * LSTG;
        const uint32_t sQh = st, sKh = st + 16384;

#pragma unroll
        for (int k16 = 0; k16 < 4; k16++) {
            uint32_t Ah[4][4], Bh[2][4];
#pragma unroll
            for (int mt = 0; mt < 4; mt++) ldsm4_a128(Ah[mt], sQh, wm * 64 + mt * 16, k16);
#pragma unroll
            for (int pq = 0; pq < 2; pq++) ldsm4_b128(Bh[pq], sKh, wn * 32 + pq * 16, k16);
#pragma unroll
            for (int mt = 0; mt < 4; mt++)
#pragma unroll
                for (int nt = 0; nt < 4; nt++)
                    mma16816(acc[mt][nt], Ah[mt], &Bh[nt >> 1][(nt & 1) * 2]);
        }
    }

    float* ab = g_attn_part[p] + (size_t)h * CC * CC;
#pragma unroll
    for (int mt = 0; mt < 4; mt++) {
        const int m0 = i0 + wm * 64 + mt * 16 + (lane >> 2);
#pragma unroll
        for (int nt = 0; nt < 4; nt++) {
            const int col = j0 + wn * 32 + nt * 8 + 2 * (lane & 3);
            *(float2*)(ab + (size_t)m0 * CC + col) =
                make_float2(acc[mt][nt][0], acc[mt][nt][1]);
            *(float2*)(ab + (size_t)(m0 + 8) * CC + col) =
                make_float2(acc[mt][nt][2], acc[mt][nt][3]);
        }
    }
}

// ---------------------------------------------------------------------------
// Row softmax; sums NPARTL partials; writes fp32 probs + fp16 hi/lo probs.
// ---------------------------------------------------------------------------
__global__ __launch_bounds__(256) void softmax_kernel(float* __restrict__ probs_out)
{
    __shared__ float red[256];
    const int row = blockIdx.x;                 // 0 .. H*C-1
    const int tid = threadIdx.x;
    float v = 0.f;
#pragma unroll
    for (int pp = 0; pp < NPARTL; pp++)
        v += g_attn_part[pp][(size_t)row * CC + tid];

    red[tid] = v; __syncthreads();
    for (int s = 128; s > 0; s >>= 1) {
        if (tid < s) red[tid] = fmaxf(red[tid], red[tid + s]);
        __syncthreads();
    }
    float mx = red[0];
    __syncthreads();

    float e = __expf(v - mx);
    red[tid] = e; __syncthreads();
    for (int s = 128; s > 0; s >>= 1) {
        if (tid < s) red[tid] += red[tid + s];
        __syncthreads();
    }
    float pr = e / red[0];

    probs_out[(size_t)row * CC + tid] = pr;
    __half hh = __float2half(pr);
    g_phi[(size_t)row * CC + tid] = hh;
    g_plo[(size_t)row * CC + tid] = __float2half(pr - __half2float(hh));
}

// ---------------------------------------------------------------------------
// Context (HMMA): c = (phi+plo) @ v_t rows; per CTA fixed (h, r), 128(i) x 64(d).
// ---------------------------------------------------------------------------
#define CSTG 20480             // Phi 8K + Plo 8K + V 4K
#define CTX_DSMEM (3 * CSTG)

__global__ __launch_bounds__(256, 2) void context_kernel()
{
    extern __shared__ char dsm[];
    const uint32_t sbase = smem_u32(dsm);

    const int tid  = threadIdx.x;
    const int wid  = tid >> 5;
    const int lane = tid & 31;
    const int wm = wid >> 2;        // 0..1
    const int wn = wid & 3;         // 0..3
    const int i0 = blockIdx.x * 128;
    const int r  = blockIdx.y;
    const int h  = blockIdx.z;
    const int nch = CC / BKC;       // 8

    const __half* Ph = g_phi + (size_t)h * CC * CC + (size_t)i0 * CC;
    const __half* Pl = g_plo + (size_t)h * CC * CC + (size_t)i0 * CC;
    const __half* Vb = g_vt + (size_t)(h * DKK) * MTOK + (size_t)r * CC;

    const int arow = tid >> 1;
    const int asp  = (tid & 1) * 2;
    const int brow = tid >> 2;
    const int bsg  = tid & 3;

    auto load_stage = [&](int kc, int buf) {
        uint32_t b0 = sbase + buf * CSTG;
        const __half* sa = Ph + (size_t)arow * CC + kc * BKC;
        const __half* sl = Pl + (size_t)arow * CC + kc * BKC;
        cpa16(b0 + swz64(arow * 64 + (asp + 0) * 16), sa + (asp + 0) * 8);
        cpa16(b0 + swz64(arow * 64 + (asp + 1) * 16), sa + (asp + 1) * 8);
        cpa16(b0 + 8192 + swz64(arow * 64 + (asp + 0) * 16), sl + (asp + 0) * 8);
        cpa16(b0 + 8192 + swz64(arow * 64 + (asp + 1) * 16), sl + (asp + 1) * 8);
        const __half* sv = Vb + (size_t)brow * MTOK + kc * BKC;
        cpa16(b0 + 16384 + swz64(brow * 64 + bsg * 16), sv + bsg * 8);
        CP_COMMIT();
    };

    float acc[4][2][4];
#pragma unroll
    for (int mt = 0; mt < 4; mt++)
#pragma unroll
        for (int nt = 0; nt < 2; nt++)
#pragma unroll
            for (int e = 0; e < 4; e++) acc[mt][nt][e] = 0.f;

    load_stage(0, 0);
    load_stage(1, 1);

    for (int kc = 0; kc < nch; kc++) {
        CP_WAIT1();
        __syncthreads();
        int nb = kc + 2;
        if (nb < nch) load_stage(nb, nb % 3);
        else CP_COMMIT();

        const uint32_t st = sbase + (kc % 3) * CSTG;
        const uint32_t sPh = st, sPl = st + 8192, sV = st + 16384;

#pragma unroll
        for (int k16 = 0; k16 < 2; k16++) {
            uint32_t Ah[4][4], Al[4][4], Bh[4];
#pragma unroll
            for (int mt = 0; mt < 4; mt++) ldsm4_a(Ah[mt], sPh, wm * 64 + mt * 16, k16);
#pragma unroll
            for (int mt = 0; mt < 4; mt++) ldsm4_a(Al[mt], sPl, wm * 64 + mt * 16, k16);
            ldsm4_b(Bh, sV, wn * 16, k16);

#pragma unroll
            for (int mt = 0; mt < 4; mt++)
#pragma unroll
                for (int nt = 0; nt < 2; nt++) {
                    mma16816(acc[mt][nt], Ah[mt], &Bh[nt * 2]);
                    mma16816(acc[mt][nt], Al[mt], &Bh[nt * 2]);
                }
        }
    }

#pragma unroll
    for (int mt = 0; mt < 4; mt++) {
        const int iL = i0 + wm * 64 + mt * 16 + (lane >> 2);
        const size_t tok0 = (size_t)(r * CC + iL) * EE + h * DKK;
        const size_t tok1 = (size_t)(r * CC + iL + 8) * EE + h * DKK;
#pragma unroll
        for (int nt = 0; nt < 2; nt++) {
            const int col = wn * 16 + nt * 8 + 2 * (lane & 3);
            float v00 = acc[mt][nt][0], v01 = acc[mt][nt][1];
            float v10 = acc[mt][nt][2], v11 = acc[mt][nt][3];
            __half h00 = __float2half(v00), h01 = __float2half(v01);
            __half h10 = __float2half(v10), h11 = __float2half(v11);
            *(__half2*)(g_chi + tok0 + col) = __halves2half2(h00, h01);
            *(__half2*)(g_chi + tok1 + col) = __halves2half2(h10, h11);
            *(__half2*)(g_clo + tok0 + col) =
                __halves2half2(__float2half(v00 - __half2float(h00)),
                               __float2half(v01 - __half2float(h01)));
            *(__half2*)(g_clo + tok1 + col) =
                __halves2half2(__float2half(v10 - __half2float(h10)),
                               __float2half(v11 - __half2float(h11)));
        }
    }
}

// ---------------------------------------------------------------------------
extern "C" void kernel_launch(void* const* d_in, const int* in_sizes, int n_in,
                              void* d_out, int out_size)
{
    const float* x  = (const float*)d_in[0];
    const float* Wq = (const float*)d_in[1];
    const float* bq = (const float*)d_in[2];
    const float* Wk = (const float*)d_in[3];
    const float* bk = (const float*)d_in[4];
    const float* Wv = (const float*)d_in[5];
    const float* bv = (const float*)d_in[6];
    const float* Wo = (const float*)d_in[7];
    const float* bo = (const float*)d_in[8];

    float* out = (float*)d_out;                       // [R,C,B,E]
    float* probs = out + (size_t)MTOK * EE;           // [H,B,C,C]

    cudaFuncSetAttribute(qkv_gemm_kernel,
                         cudaFuncAttributeMaxDynamicSharedMemorySize, GEMM_DSMEM);
    cudaFuncSetAttribute(o_gemm_kernel,
                         cudaFuncAttributeMaxDynamicSharedMemorySize, OGEMM_DSMEM);
    cudaFuncSetAttribute(logits_kernel,
                         cudaFuncAttributeMaxDynamicSharedMemorySize, LOGITS_DSMEM);
    cudaFuncSetAttribute(context_kernel,
                         cudaFuncAttributeMaxDynamicSharedMemorySize, CTX_DSMEM);

    const float scaling = 0.125f / sqrtf((float)RR);  // DK^-0.5 / sqrt(R)
    const size_t WN = (size_t)EE * EE;

    // splits
    {
        int n4x = (int)((size_t)MTOK * EE / 4);
        xsplit_kernel<<<(n4x + 255) / 256, 256>>>(x, n4x);
        int n4w = (int)(WN / 4);
        wsplit_kernel<<<(4 * n4w + 255) / 256, 256>>>(Wq, Wk, Wv, Wo, n4w);
    }

    qkv_gemm_kernel<<<dim3(3 * EE / 128, MTOK / 128), 256, GEMM_DSMEM>>>(
        bq, bk, bv, scaling);

    logits_kernel<<<dim3(2, 2, HH * NPARTL), 256, LOGITS_DSMEM>>>();
    softmax_kernel<<<HH * CC, 256>>>(probs);
    context_kernel<<<dim3(2, RR, HH), 256, CTX_DSMEM>>>();

    o_gemm_kernel<<<dim3(EE / 128, MTOK / 128), 256, OGEMM_DSMEM>>>(bo, out);
}

// round 8
// speedup vs baseline: 6.1725x; 1.1200x over previous
#include <cuda_runtime.h>
#include <cuda_fp16.h>
#include <math.h>
#include <stdint.h>

// Problem constants
#define RR 128
#define CC 256
#define EE 768
#define HH 12
#define DKK 64
#define MTOK (RR*CC)          // 32768 tokens
#define NPARTL 16             // r-split for attention logits

// ---------------------------------------------------------------------------
// Scratch (device globals — no allocation allowed)
// ---------------------------------------------------------------------------
__device__ float g_attn_part[NPARTL][(size_t)HH * CC * CC];

__device__ __half g_xhi[(size_t)MTOK * EE];
__device__ __half g_qhi[(size_t)MTOK * EE];
__device__ __half g_khi[(size_t)MTOK * EE];
__device__ __half g_vt [(size_t)EE * MTOK];     // V transposed: [E][token]
__device__ __half g_phi[(size_t)HH * CC * CC];
__device__ __half g_plo[(size_t)HH * CC * CC];
__device__ __half g_chi[(size_t)MTOK * EE];
__device__ __half g_whi[4][(size_t)EE * EE];

// ---------------------------------------------------------------------------
// Helpers (suffix-free PTX only: cp.async / ldmatrix / mma.sync)
// ---------------------------------------------------------------------------
__device__ __forceinline__ uint32_t smem_u32(const void* p) {
    uint32_t a;
    asm("{ .reg .u64 t; cvta.to.shared.u64 t, %1; cvt.u32.u64 %0, t; }"
        : "=r"(a) : "l"(p));
    return a;
}

__device__ __forceinline__ uint32_t swz64(uint32_t off) {
    return off ^ ((off >> 3) & 0x30);   // 64B-row swizzle
}
__device__ __forceinline__ uint32_t swz128(uint32_t off) {
    return off ^ ((off >> 3) & 0x70);   // 128B-row swizzle
}

__device__ __forceinline__ void cpa16(uint32_t dst, const void* src) {
    asm volatile("cp.async.cg.shared.global [%0], [%1], 16;"
                 :: "r"(dst), "l"(src));
}
#define CP_COMMIT() asm volatile("cp.async.commit_group;" ::: "memory")
#define CP_WAIT1()  asm volatile("cp.async.wait_group 1;" ::: "memory")
#define CP_WAIT0()  asm volatile("cp.async.wait_group 0;" ::: "memory")

// ldmatrix x4 from 64B-row tile: A side (m16 x k16)
__device__ __forceinline__ void ldsm4_a(uint32_t* r, uint32_t sb, int mbase, int k16) {
    int lane = threadIdx.x & 31;
    uint32_t row = mbase + (lane & 15);
    uint32_t cb  = (lane & 16);
    uint32_t addr = sb + swz64(row * 64 + k16 * 32 + cb);
    asm volatile("ldmatrix.sync.aligned.m8n8.x4.shared.b16 {%0,%1,%2,%3}, [%4];"
                 : "=r"(r[0]), "=r"(r[1]), "=r"(r[2]), "=r"(r[3]) : "r"(addr));
}
// ldmatrix x4 from 64B-row tile: B side (two n8 x k16 frags)
__device__ __forceinline__ void ldsm4_b(uint32_t* r, uint32_t sb, int nbase, int k16) {
    int lane = threadIdx.x & 31;
    uint32_t row = nbase + (lane & 7) + ((lane & 16) >> 1);
    uint32_t cb  = (lane & 8) << 1;
    uint32_t addr = sb + swz64(row * 64 + k16 * 32 + cb);
    asm volatile("ldmatrix.sync.aligned.m8n8.x4.shared.b16 {%0,%1,%2,%3}, [%4];"
                 : "=r"(r[0]), "=r"(r[1]), "=r"(r[2]), "=r"(r[3]) : "r"(addr));
}
// 128B-row variants (BK=64 tiles)
__device__ __forceinline__ void ldsm4_a128(uint32_t* r, uint32_t sb, int mbase, int k16) {
    int lane = threadIdx.x & 31;
    uint32_t row = mbase + (lane & 15);
    uint32_t cb  = (lane & 16);
    uint32_t addr = sb + swz128(row * 128 + k16 * 32 + cb);
    asm volatile("ldmatrix.sync.aligned.m8n8.x4.shared.b16 {%0,%1,%2,%3}, [%4];"
                 : "=r"(r[0]), "=r"(r[1]), "=r"(r[2]), "=r"(r[3]) : "r"(addr));
}
__device__ __forceinline__ void ldsm4_b128(uint32_t* r, uint32_t sb, int nbase, int k16) {
    int lane = threadIdx.x & 31;
    uint32_t row = nbase + (lane & 7) + ((lane & 16) >> 1);
    uint32_t cb  = (lane & 8) << 1;
    uint32_t addr = sb + swz128(row * 128 + k16 * 32 + cb);
    asm volatile("ldmatrix.sync.aligned.m8n8.x4.shared.b16 {%0,%1,%2,%3}, [%4];"
                 : "=r"(r[0]), "=r"(r[1]), "=r"(r[2]), "=r"(r[3]) : "r"(addr));
}

__device__ __forceinline__ void mma16816(float* c, const uint32_t* a, const uint32_t* b) {
    asm volatile(
        "mma.sync.aligned.m16n8k16.row.col.f32.f16.f16.f32 "
        "{%0,%1,%2,%3}, {%4,%5,%6,%7}, {%8,%9}, {%0,%1,%2,%3};"
        : "+f"(c[0]), "+f"(c[1]), "+f"(c[2]), "+f"(c[3])
        : "r"(a[0]), "r"(a[1]), "r"(a[2]), "r"(a[3]), "r"(b[0]), "r"(b[1]));
}

// ---------------------------------------------------------------------------
// Splits (hi only)
// ---------------------------------------------------------------------------
__global__ __launch_bounds__(256) void xsplit_kernel(
    const float* __restrict__ src, int n4)
{
    int i = blockIdx.x * 256 + threadIdx.x;
    if (i >= n4) return;
    float4 v = ((const float4*)src)[i];
    __half2* hp = (__half2*)g_xhi;
    hp[2 * i + 0] = __halves2half2(__float2half(v.x), __float2half(v.y));
    hp[2 * i + 1] = __halves2half2(__float2half(v.z), __float2half(v.w));
}

__global__ __launch_bounds__(256) void wsplit_kernel(
    const float* __restrict__ Wq, const float* __restrict__ Wk,
    const float* __restrict__ Wv, const float* __restrict__ Wo, int n4each)
{
    int i = blockIdx.x * 256 + threadIdx.x;
    int w = i / n4each;
    int j = i - w * n4each;
    if (w >= 4) return;
    const float* src = (w == 0) ? Wq : (w == 1) ? Wk : (w == 2) ? Wv : Wo;
    float4 v = ((const float4*)src)[j];
    __half2* hp = (__half2*)(g_whi[w]);
    hp[2 * j + 0] = __halves2half2(__float2half(v.x), __float2half(v.y));
    hp[2 * j + 1] = __halves2half2(__float2half(v.z), __float2half(v.w));
}

// ---------------------------------------------------------------------------
// Fused QKV projection GEMM (HMMA, 1-product xhi·Whi):
//   wsel 0 (Q): scaled -> g_qhi;  wsel 1 (K): -> g_khi;  wsel 2 (V): -> g_vt^T
// CTA 128x128, BK=64, 8 warps, 3-stage cp.async (2 tiles/stage), 2 CTAs/SM.
// ---------------------------------------------------------------------------
#define GSTG 32768             // 2 tiles x 128 x 64 x 2B
#define GEMM_DSMEM (3 * GSTG)

__global__ __launch_bounds__(256, 2) void qkv_gemm_kernel(
    const float* __restrict__ bq, const float* __restrict__ bk,
    const float* __restrict__ bv, float scaling)
{
    extern __shared__ char dsm[];
    const uint32_t sbase = smem_u32(dsm);

    const int tid  = threadIdx.x;
    const int wid  = tid >> 5;
    const int lane = tid & 31;
    const int wm = wid >> 2;
    const int wn = wid & 3;
    const int bm = blockIdx.y * 128;
    const int bng = blockIdx.x * 128;
    const int wsel = bng / EE;
    const int bn = bng - wsel * EE;
    const int Kdim = EE;
    const int nch = Kdim / 64;      // 12

    const __half* W = g_whi[wsel];
    const float* bias = (wsel == 0) ? bq : (wsel == 1) ? bk : bv;

    const __half* srcA = g_xhi + (size_t)bm * Kdim;
    const __half* srcW = W + (size_t)bn * Kdim;

    const int row_g = tid >> 1;          // 0..127
    const int sg0   = (tid & 1) * 4;     // 0 or 4

    auto load_stage = [&](int kc, int buf) {
        uint32_t base = sbase + buf * GSTG;
        const __half* sa = srcA + (size_t)row_g * Kdim + kc * 64;
        const __half* sw = srcW + (size_t)row_g * Kdim + kc * 64;
#pragma unroll
        for (int s = 0; s < 4; s++) {
            uint32_t off = swz128(row_g * 128 + (sg0 + s) * 16);
            cpa16(base + off, sa + (sg0 + s) * 8);
            cpa16(base + 16384 + off, sw + (sg0 + s) * 8);
        }
        CP_COMMIT();
    };

    float acc[4][4][4];
#pragma unroll
    for (int mt = 0; mt < 4; mt++)
#pragma unroll
        for (int nt = 0; nt < 4; nt++)
#pragma unroll
            for (int e = 0; e < 4; e++) acc[mt][nt][e] = 0.f;

    load_stage(0, 0);
    load_stage(1, 1);

    for (int kc = 0; kc < nch; kc++) {
        CP_WAIT1();
        __syncthreads();
        int nb = kc + 2;
        if (nb < nch) load_stage(nb, nb % 3);
        else CP_COMMIT();

        const uint32_t st = sbase + (kc % 3) * GSTG;
        const uint32_t sAh = st, sWh = st + 16384;

#pragma unroll
        for (int k16 = 0; k16 < 4; k16++) {
            uint32_t Ah[4][4], Bh[2][4];
#pragma unroll
            for (int mt = 0; mt < 4; mt++) ldsm4_a128(Ah[mt], sAh, wm * 64 + mt * 16, k16);
#pragma unroll
            for (int p = 0; p < 2; p++) ldsm4_b128(Bh[p], sWh, wn * 32 + p * 16, k16);
#pragma unroll
            for (int mt = 0; mt < 4; mt++)
#pragma unroll
                for (int nt = 0; nt < 4; nt++)
                    mma16816(acc[mt][nt], Ah[mt], &Bh[nt >> 1][(nt & 1) * 2]);
        }
    }

    if (wsel == 2) {
        // V: transpose via smem, write g_vt[n][m] coalesced
        CP_WAIT0();
        __syncthreads();
        __half* smt = (__half*)dsm;     // [128 n][128 m] = 32KB
#pragma unroll
        for (int mt = 0; mt < 4; mt++) {
            const int ml = wm * 64 + mt * 16 + (lane >> 2);
#pragma unroll
            for (int nt = 0; nt < 4; nt++) {
                const int nl = wn * 32 + nt * 8 + 2 * (lane & 3);
                const float b0 = bias[bn + nl], b1 = bias[bn + nl + 1];
                smt[(nl + 0) * 128 + ml] = __float2half(acc[mt][nt][0] + b0);
                smt[(nl + 1) * 128 + ml] = __float2half(acc[mt][nt][1] + b1);
                smt[(nl + 0) * 128 + ml + 8] = __float2half(acc[mt][nt][2] + b0);
                smt[(nl + 1) * 128 + ml + 8] = __float2half(acc[mt][nt][3] + b1);
            }
        }
        __syncthreads();
        const int nrow = tid >> 1;
        const int seg  = tid & 1;
        const uint4* srcv = (const uint4*)(smt + nrow * 128 + seg * 64);
        uint4* dstv = (uint4*)(g_vt + (size_t)(bn + nrow) * MTOK + bm + seg * 64);
#pragma unroll
        for (int u = 0; u < 8; u++) dstv[u] = srcv[u];
        return;
    }

    __half* dst = (wsel == 0) ? g_qhi : g_khi;
    const float sc = (wsel == 0) ? scaling : 1.0f;
#pragma unroll
    for (int mt = 0; mt < 4; mt++) {
        const int m0 = bm + wm * 64 + mt * 16 + (lane >> 2);
#pragma unroll
        for (int nt = 0; nt < 4; nt++) {
            const int col = bn + wn * 32 + nt * 8 + 2 * (lane & 3);
            const float b0 = bias[col], b1 = bias[col + 1];
            *(__half2*)(dst + (size_t)m0 * EE + col) =
                __halves2half2(__float2half(sc * (acc[mt][nt][0] + b0)),
                               __float2half(sc * (acc[mt][nt][1] + b1)));
            *(__half2*)(dst + (size_t)(m0 + 8) * EE + col) =
                __halves2half2(__float2half(sc * (acc[mt][nt][2] + b0)),
                               __float2half(sc * (acc[mt][nt][3] + b1)));
        }
    }
}

// ---------------------------------------------------------------------------
// O projection GEMM: out = chi @ Wo.T + bo  (fp32 out, 1-product, BK=64)
// ---------------------------------------------------------------------------
__global__ __launch_bounds__(256, 2) void o_gemm_kernel(
    const float* __restrict__ bias, float* __restrict__ out)
{
    extern __shared__ char dsm[];
    const uint32_t sbase = smem_u32(dsm);

    const int tid  = threadIdx.x;
    const int wid  = tid >> 5;
    const int lane = tid & 31;
    const int wm = wid >> 2;
    const int wn = wid & 3;
    const int bm = blockIdx.y * 128;
    const int bn = blockIdx.x * 128;
    const int Kdim = EE;
    const int nch = Kdim / 64;      // 12

    const __half* srcA = g_chi + (size_t)bm * Kdim;
    const __half* srcW = g_whi[3] + (size_t)bn * Kdim;

    const int row_g = tid >> 1;
    const int sg0   = (tid & 1) * 4;

    auto load_stage = [&](int kc, int buf) {
        uint32_t base = sbase + buf * GSTG;
        const __half* sa = srcA + (size_t)row_g * Kdim + kc * 64;
        const __half* sw = srcW + (size_t)row_g * Kdim + kc * 64;
#pragma unroll
        for (int s = 0; s < 4; s++) {
            uint32_t off = swz128(row_g * 128 + (sg0 + s) * 16);
            cpa16(base + off, sa + (sg0 + s) * 8);
            cpa16(base + 16384 + off, sw + (sg0 + s) * 8);
        }
        CP_COMMIT();
    };

    float acc[4][4][4];
#pragma unroll
    for (int mt = 0; mt < 4; mt++)
#pragma unroll
        for (int nt = 0; nt < 4; nt++)
#pragma unroll
            for (int e = 0; e < 4; e++) acc[mt][nt][e] = 0.f;

    load_stage(0, 0);
    load_stage(1, 1);

    for (int kc = 0; kc < nch; kc++) {
        CP_WAIT1();
        __syncthreads();
        int nb = kc + 2;
        if (nb < nch) load_stage(nb, nb % 3);
        else CP_COMMIT();

        const uint32_t st = sbase + (kc % 3) * GSTG;
        const uint32_t sAh = st, sWh = st + 16384;

#pragma unroll
        for (int k16 = 0; k16 < 4; k16++) {
            uint32_t Ah[4][4], Bh[2][4];
#pragma unroll
            for (int mt = 0; mt < 4; mt++) ldsm4_a128(Ah[mt], sAh, wm * 64 + mt * 16, k16);
#pragma unroll
            for (int p = 0; p < 2; p++) ldsm4_b128(Bh[p], sWh, wn * 32 + p * 16, k16);
#pragma unroll
            for (int mt = 0; mt < 4; mt++)
#pragma unroll
                for (int nt = 0; nt < 4; nt++)
                    mma16816(acc[mt][nt], Ah[mt], &Bh[nt >> 1][(nt & 1) * 2]);
        }
    }

#pragma unroll
    for (int mt = 0; mt < 4; mt++) {
        const int m0 = bm + wm * 64 + mt * 16 + (lane >> 2);
#pragma unroll
        for (int nt = 0; nt < 4; nt++) {
            const int col = bn + wn * 32 + nt * 8 + 2 * (lane & 3);
            const float b0 = bias[col], b1 = bias[col + 1];
            *(float2*)(out + (size_t)m0 * EE + col) =
                make_float2(acc[mt][nt][0] + b0, acc[mt][nt][1] + b1);
            *(float2*)(out + (size_t)(m0 + 8) * EE + col) =
                make_float2(acc[mt][nt][2] + b0, acc[mt][nt][3] + b1);
        }
    }
}

// ---------------------------------------------------------------------------
// Attention logits (HMMA, 1-product qhi·khi):
// Per CTA: 128(i) x 128(j), BK = 64 (one r), 8 r's per CTA.
// grid (2 j, 2 i, HH*NPARTL). 32KB/stage x 3 -> 2 CTAs/SM.
// ---------------------------------------------------------------------------
#define LSTG 32768
#define LOGITS_DSMEM (3 * LSTG)

__global__ __launch_bounds__(256, 2) void logits_kernel()
{
    extern __shared__ char dsm[];
    const uint32_t sbase = smem_u32(dsm);

    const int tid  = threadIdx.x;
    const int wid  = tid >> 5;
    const int lane = tid & 31;
    const int wm = wid >> 2;
    const int wn = wid & 3;
    const int j0 = blockIdx.x * 128;
    const int i0 = blockIdx.y * 128;
    const int h  = blockIdx.z % HH;
    const int p  = blockIdx.z / HH;
    const int rbeg = p * (RR / NPARTL);    // 8 r's per CTA
    const int nch = RR / NPARTL;

    const int lrow = tid & 127;
    const int sg0  = (tid >> 7) * 4;

    auto load_stage = [&](int rc, int buf) {
        const int r = rbeg + rc;
        const __half* qh = g_qhi + ((size_t)(r * CC + i0 + lrow)) * EE + h * DKK;
        const __half* kh = g_khi + ((size_t)(r * CC + j0 + lrow)) * EE + h * DKK;
        uint32_t b0 = sbase + buf * LSTG;
#pragma unroll
        for (int s = 0; s < 4; s++) {
            uint32_t off = swz128(lrow * 128 + (sg0 + s) * 16);
            cpa16(b0 + off, qh + (sg0 + s) * 8);
            cpa16(b0 + 16384 + off, kh + (sg0 + s) * 8);
        }
        CP_COMMIT();
    };

    float acc[4][4][4];
#pragma unroll
    for (int mt = 0; mt < 4; mt++)
#pragma unroll
        for (int nt = 0; nt < 4; nt++)
#pragma unroll
            for (int e = 0; e < 4; e++) acc[mt][nt][e] = 0.f;

    load_stage(0, 0);
    load_stage(1, 1);

    for (int rc = 0; rc < nch; rc++) {
        CP_WAIT1();
        __syncthreads();
        int nb = rc + 2;
        if (nb < nch) load_stage(nb, nb % 3);
        else CP_COMMIT();

        const uint32_t st = sbase + (rc % 3) * LSTG;
        const uint32_t sQh = st, sKh = st + 16384;

#pragma unroll
        for (int k16 = 0; k16 < 4; k16++) {
            uint32_t Ah[4][4], Bh[2][4];
#pragma unroll
            for (int mt = 0; mt < 4; mt++) ldsm4_a128(Ah[mt], sQh, wm * 64 + mt * 16, k16);
#pragma unroll
            for (int pq = 0; pq < 2; pq++) ldsm4_b128(Bh[pq], sKh, wn * 32 + pq * 16, k16);
#pragma unroll
            for (int mt = 0; mt < 4; mt++)
#pragma unroll
                for (int nt = 0; nt < 4; nt++)
                    mma16816(acc[mt][nt], Ah[mt], &Bh[nt >> 1][(nt & 1) * 2]);
        }
    }

    float* ab = g_attn_part[p] + (size_t)h * CC * CC;
#pragma unroll
    for (int mt = 0; mt < 4; mt++) {
        const int m0 = i0 + wm * 64 + mt * 16 + (lane >> 2);
#pragma unroll
        for (int nt = 0; nt < 4; nt++) {
            const int col = j0 + wn * 32 + nt * 8 + 2 * (lane & 3);
            *(float2*)(ab + (size_t)m0 * CC + col) =
                make_float2(acc[mt][nt][0], acc[mt][nt][1]);
            *(float2*)(ab + (size_t)(m0 + 8) * CC + col) =
                make_float2(acc[mt][nt][2], acc[mt][nt][3]);
        }
    }
}

// ---------------------------------------------------------------------------
// Row softmax; sums NPARTL partials; writes fp32 probs + fp16 hi/lo probs.
// ---------------------------------------------------------------------------
__global__ __launch_bounds__(256) void softmax_kernel(float* __restrict__ probs_out)
{
    __shared__ float red[256];
    const int row = blockIdx.x;                 // 0 .. H*C-1
    const int tid = threadIdx.x;
    float v = 0.f;
#pragma unroll
    for (int pp = 0; pp < NPARTL; pp++)
        v += g_attn_part[pp][(size_t)row * CC + tid];

    red[tid] = v; __syncthreads();
    for (int s = 128; s > 0; s >>= 1) {
        if (tid < s) red[tid] = fmaxf(red[tid], red[tid + s]);
        __syncthreads();
    }
    float mx = red[0];
    __syncthreads();

    float e = __expf(v - mx);
    red[tid] = e; __syncthreads();
    for (int s = 128; s > 0; s >>= 1) {
        if (tid < s) red[tid] += red[tid + s];
        __syncthreads();
    }
    float pr = e / red[0];

    probs_out[(size_t)row * CC + tid] = pr;
    __half hh = __float2half(pr);
    g_phi[(size_t)row * CC + tid] = hh;
    g_plo[(size_t)row * CC + tid] = __float2half(pr - __half2float(hh));
}

// ---------------------------------------------------------------------------
// Context (HMMA): c = (phi+plo) @ v_t rows; per CTA fixed (h, r), 128(i) x 64(d).
// Writes c as plain fp16 (single rounding) for the 1-product O projection.
// ---------------------------------------------------------------------------
#define CSTG 20480             // Phi 8K + Plo 8K + V 4K
#define CTX_DSMEM (3 * CSTG)

__global__ __launch_bounds__(256, 2) void context_kernel()
{
    extern __shared__ char dsm[];
    const uint32_t sbase = smem_u32(dsm);

    const int tid  = threadIdx.x;
    const int wid  = tid >> 5;
    const int lane = tid & 31;
    const int wm = wid >> 2;        // 0..1
    const int wn = wid & 3;         // 0..3
    const int i0 = blockIdx.x * 128;
    const int r  = blockIdx.y;
    const int h  = blockIdx.z;
    const int nch = CC / 32;        // 8

    const __half* Ph = g_phi + (size_t)h * CC * CC + (size_t)i0 * CC;
    const __half* Pl = g_plo + (size_t)h * CC * CC + (size_t)i0 * CC;
    const __half* Vb = g_vt + (size_t)(h * DKK) * MTOK + (size_t)r * CC;

    const int arow = tid >> 1;
    const int asp  = (tid & 1) * 2;
    const int brow = tid >> 2;
    const int bsg  = tid & 3;

    auto load_stage = [&](int kc, int buf) {
        uint32_t b0 = sbase + buf * CSTG;
        const __half* sa = Ph + (size_t)arow * CC + kc * 32;
        const __half* sl = Pl + (size_t)arow * CC + kc * 32;
        cpa16(b0 + swz64(arow * 64 + (asp + 0) * 16), sa + (asp + 0) * 8);
        cpa16(b0 + swz64(arow * 64 + (asp + 1) * 16), sa + (asp + 1) * 8);
        cpa16(b0 + 8192 + swz64(arow * 64 + (asp + 0) * 16), sl + (asp + 0) * 8);
        cpa16(b0 + 8192 + swz64(arow * 64 + (asp + 1) * 16), sl + (asp + 1) * 8);
        const __half* sv = Vb + (size_t)brow * MTOK + kc * 32;
        cpa16(b0 + 16384 + swz64(brow * 64 + bsg * 16), sv + bsg * 8);
        CP_COMMIT();
    };

    float acc[4][2][4];
#pragma unroll
    for (int mt = 0; mt < 4; mt++)
#pragma unroll
        for (int nt = 0; nt < 2; nt++)
#pragma unroll
            for (int e = 0; e < 4; e++) acc[mt][nt][e] = 0.f;

    load_stage(0, 0);
    load_stage(1, 1);

    for (int kc = 0; kc < nch; kc++) {
        CP_WAIT1();
        __syncthreads();
        int nb = kc + 2;
        if (nb < nch) load_stage(nb, nb % 3);
        else CP_COMMIT();

        const uint32_t st = sbase + (kc % 3) * CSTG;
        const uint32_t sPh = st, sPl = st + 8192, sV = st + 16384;

#pragma unroll
        for (int k16 = 0; k16 < 2; k16++) {
            uint32_t Ah[4][4], Al[4][4], Bh[4];
#pragma unroll
            for (int mt = 0; mt < 4; mt++) ldsm4_a(Ah[mt], sPh, wm * 64 + mt * 16, k16);
#pragma unroll
            for (int mt = 0; mt < 4; mt++) ldsm4_a(Al[mt], sPl, wm * 64 + mt * 16, k16);
            ldsm4_b(Bh, sV, wn * 16, k16);

#pragma unroll
            for (int mt = 0; mt < 4; mt++)
#pragma unroll
                for (int nt = 0; nt < 2; nt++) {
                    mma16816(acc[mt][nt], Ah[mt], &Bh[nt * 2]);
                    mma16816(acc[mt][nt], Al[mt], &Bh[nt * 2]);
                }
        }
    }

#pragma unroll
    for (int mt = 0; mt < 4; mt++) {
        const int iL = i0 + wm * 64 + mt * 16 + (lane >> 2);
        const size_t tok0 = (size_t)(r * CC + iL) * EE + h * DKK;
        const size_t tok1 = (size_t)(r * CC + iL + 8) * EE + h * DKK;
#pragma unroll
        for (int nt = 0; nt < 2; nt++) {
            const int col = wn * 16 + nt * 8 + 2 * (lane & 3);
            *(__half2*)(g_chi + tok0 + col) =
                __halves2half2(__float2half(acc[mt][nt][0]),
                               __float2half(acc[mt][nt][1]));
            *(__half2*)(g_chi + tok1 + col) =
                __halves2half2(__float2half(acc[mt][nt][2]),
                               __float2half(acc[mt][nt][3]));
        }
    }
}

// ---------------------------------------------------------------------------
extern "C" void kernel_launch(void* const* d_in, const int* in_sizes, int n_in,
                              void* d_out, int out_size)
{
    const float* x  = (const float*)d_in[0];
    const float* Wq = (const float*)d_in[1];
    const float* bq = (const float*)d_in[2];
    const float* Wk = (const float*)d_in[3];
    const float* bk = (const float*)d_in[4];
    const float* Wv = (const float*)d_in[5];
    const float* bv = (const float*)d_in[6];
    const float* Wo = (const float*)d_in[7];
    const float* bo = (const float*)d_in[8];

    float* out = (float*)d_out;                       // [R,C,B,E]
    float* probs = out + (size_t)MTOK * EE;           // [H,B,C,C]

    cudaFuncSetAttribute(qkv_gemm_kernel,
                         cudaFuncAttributeMaxDynamicSharedMemorySize, GEMM_DSMEM);
    cudaFuncSetAttribute(o_gemm_kernel,
                         cudaFuncAttributeMaxDynamicSharedMemorySize, GEMM_DSMEM);
    cudaFuncSetAttribute(logits_kernel,
                         cudaFuncAttributeMaxDynamicSharedMemorySize, LOGITS_DSMEM);
    cudaFuncSetAttribute(context_kernel,
                         cudaFuncAttributeMaxDynamicSharedMemorySize, CTX_DSMEM);

    const float scaling = 0.125f / sqrtf((float)RR);  // DK^-0.5 / sqrt(R)
    const size_t WN = (size_t)EE * EE;

    // splits
    {
        int n4x = (int)((size_t)MTOK * EE / 4);
        xsplit_kernel<<<(n4x + 255) / 256, 256>>>(x, n4x);
        int n4w = (int)(WN / 4);
        wsplit_kernel<<<(4 * n4w + 255) / 256, 256>>>(Wq, Wk, Wv, Wo, n4w);
    }

    qkv_gemm_kernel<<<dim3(3 * EE / 128, MTOK / 128), 256, GEMM_DSMEM>>>(
        bq, bk, bv, scaling);

    logits_kernel<<<dim3(2, 2, HH * NPARTL), 256, LOGITS_DSMEM>>>();
    softmax_kernel<<<HH * CC, 256>>>(probs);
    context_kernel<<<dim3(2, RR, HH), 256, CTX_DSMEM>>>();

    o_gemm_kernel<<<dim3(EE / 128, MTOK / 128), 256, GEMM_DSMEM>>>(bo, out);
}

// round 9
// speedup vs baseline: 6.2365x; 1.0104x over previous
#include <cuda_runtime.h>
#include <cuda_fp16.h>
#include <math.h>
#include <stdint.h>

// Problem constants
#define RR 128
#define CC 256
#define EE 768
#define HH 12
#define DKK 64
#define MTOK (RR*CC)          // 32768 tokens
#define NPARTL 16             // r-split for attention logits

// ---------------------------------------------------------------------------
// Scratch (device globals — no allocation allowed)
// ---------------------------------------------------------------------------
__device__ float g_attn_part[NPARTL][(size_t)HH * CC * CC];

__device__ __half g_xhi[(size_t)MTOK * EE];
__device__ __half g_qhi[(size_t)MTOK * EE];
__device__ __half g_khi[(size_t)MTOK * EE];
__device__ __half g_vt [(size_t)EE * MTOK];     // V transposed: [E][token]
__device__ __half g_phi[(size_t)HH * CC * CC];
__device__ __half g_plo[(size_t)HH * CC * CC];
__device__ __half g_chi[(size_t)MTOK * EE];
__device__ __half g_whi[4][(size_t)EE * EE];

// ---------------------------------------------------------------------------
// Helpers (suffix-free PTX only: cp.async / ldmatrix / mma.sync)
// ---------------------------------------------------------------------------
__device__ __forceinline__ uint32_t smem_u32(const void* p) {
    uint32_t a;
    asm("{ .reg .u64 t; cvta.to.shared.u64 t, %1; cvt.u32.u64 %0, t; }"
        : "=r"(a) : "l"(p));
    return a;
}

__device__ __forceinline__ uint32_t swz64(uint32_t off) {
    return off ^ ((off >> 3) & 0x30);   // 64B-row swizzle
}
__device__ __forceinline__ uint32_t swz128(uint32_t off) {
    return off ^ ((off >> 3) & 0x70);   // 128B-row swizzle
}

__device__ __forceinline__ void cpa16(uint32_t dst, const void* src) {
    asm volatile("cp.async.cg.shared.global [%0], [%1], 16;"
                 :: "r"(dst), "l"(src));
}
#define CP_COMMIT() asm volatile("cp.async.commit_group;" ::: "memory")
#define CP_WAIT1()  asm volatile("cp.async.wait_group 1;" ::: "memory")
#define CP_WAIT2()  asm volatile("cp.async.wait_group 2;" ::: "memory")
#define CP_WAIT4()  asm volatile("cp.async.wait_group 4;" ::: "memory")
#define CP_WAIT0()  asm volatile("cp.async.wait_group 0;" ::: "memory")

// ldmatrix x4 from 64B-row tile: A side (m16 x k16)
__device__ __forceinline__ void ldsm4_a(uint32_t* r, uint32_t sb, int mbase, int k16) {
    int lane = threadIdx.x & 31;
    uint32_t row = mbase + (lane & 15);
    uint32_t cb  = (lane & 16);
    uint32_t addr = sb + swz64(row * 64 + k16 * 32 + cb);
    asm volatile("ldmatrix.sync.aligned.m8n8.x4.shared.b16 {%0,%1,%2,%3}, [%4];"
                 : "=r"(r[0]), "=r"(r[1]), "=r"(r[2]), "=r"(r[3]) : "r"(addr));
}
// ldmatrix x4 from 64B-row tile: B side (two n8 x k16 frags)
__device__ __forceinline__ void ldsm4_b(uint32_t* r, uint32_t sb, int nbase, int k16) {
    int lane = threadIdx.x & 31;
    uint32_t row = nbase + (lane & 7) + ((lane & 16) >> 1);
    uint32_t cb  = (lane & 8) << 1;
    uint32_t addr = sb + swz64(row * 64 + k16 * 32 + cb);
    asm volatile("ldmatrix.sync.aligned.m8n8.x4.shared.b16 {%0,%1,%2,%3}, [%4];"
                 : "=r"(r[0]), "=r"(r[1]), "=r"(r[2]), "=r"(r[3]) : "r"(addr));
}
// 128B-row variants (BK=64 tiles)
__device__ __forceinline__ void ldsm4_a128(uint32_t* r, uint32_t sb, int mbase, int k16) {
    int lane = threadIdx.x & 31;
    uint32_t row = mbase + (lane & 15);
    uint32_t cb  = (lane & 16);
    uint32_t addr = sb + swz128(row * 128 + k16 * 32 + cb);
    asm volatile("ldmatrix.sync.aligned.m8n8.x4.shared.b16 {%0,%1,%2,%3}, [%4];"
                 : "=r"(r[0]), "=r"(r[1]), "=r"(r[2]), "=r"(r[3]) : "r"(addr));
}
__device__ __forceinline__ void ldsm4_b128(uint32_t* r, uint32_t sb, int nbase, int k16) {
    int lane = threadIdx.x & 31;
    uint32_t row = nbase + (lane & 7) + ((lane & 16) >> 1);
    uint32_t cb  = (lane & 8) << 1;
    uint32_t addr = sb + swz128(row * 128 + k16 * 32 + cb);
    asm volatile("ldmatrix.sync.aligned.m8n8.x4.shared.b16 {%0,%1,%2,%3}, [%4];"
                 : "=r"(r[0]), "=r"(r[1]), "=r"(r[2]), "=r"(r[3]) : "r"(addr));
}

__device__ __forceinline__ void mma16816(float* c, const uint32_t* a, const uint32_t* b) {
    asm volatile(
        "mma.sync.aligned.m16n8k16.row.col.f32.f16.f16.f32 "
        "{%0,%1,%2,%3}, {%4,%5,%6,%7}, {%8,%9}, {%0,%1,%2,%3};"
        : "+f"(c[0]), "+f"(c[1]), "+f"(c[2]), "+f"(c[3])
        : "r"(a[0]), "r"(a[1]), "r"(a[2]), "r"(a[3]), "r"(b[0]), "r"(b[1]));
}

// ---------------------------------------------------------------------------
// Splits (hi only)
// ---------------------------------------------------------------------------
__global__ __launch_bounds__(256) void xsplit_kernel(
    const float* __restrict__ src, int n4)
{
    int i = blockIdx.x * 256 + threadIdx.x;
    if (i >= n4) return;
    float4 v = ((const float4*)src)[i];
    __half2* hp = (__half2*)g_xhi;
    hp[2 * i + 0] = __halves2half2(__float2half(v.x), __float2half(v.y));
    hp[2 * i + 1] = __halves2half2(__float2half(v.z), __float2half(v.w));
}

__global__ __launch_bounds__(256) void wsplit_kernel(
    const float* __restrict__ Wq, const float* __restrict__ Wk,
    const float* __restrict__ Wv, const float* __restrict__ Wo, int n4each)
{
    int i = blockIdx.x * 256 + threadIdx.x;
    int w = i / n4each;
    int j = i - w * n4each;
    if (w >= 4) return;
    const float* src = (w == 0) ? Wq : (w == 1) ? Wk : (w == 2) ? Wv : Wo;
    float4 v = ((const float4*)src)[j];
    __half2* hp = (__half2*)(g_whi[w]);
    hp[2 * j + 0] = __halves2half2(__float2half(v.x), __float2half(v.y));
    hp[2 * j + 1] = __halves2half2(__float2half(v.z), __float2half(v.w));
}

// ---------------------------------------------------------------------------
// Fused QKV projection GEMM (HMMA, 1-product xhi·Whi):
//   wsel 0 (Q): scaled -> g_qhi;  wsel 1 (K): -> g_khi;  wsel 2 (V): -> g_vt^T
// CTA 128x128, BK=32, 8 warps, 6-stage cp.async (depth 5), 2 CTAs/SM.
// ---------------------------------------------------------------------------
#define QSTG 16384             // 2 tiles x 128 x 32 x 2B
#define QNST 6
#define GEMM_DSMEM (QNST * QSTG)

__global__ __launch_bounds__(256, 2) void qkv_gemm_kernel(
    const float* __restrict__ bq, const float* __restrict__ bk,
    const float* __restrict__ bv, float scaling)
{
    extern __shared__ char dsm[];
    const uint32_t sbase = smem_u32(dsm);

    const int tid  = threadIdx.x;
    const int wid  = tid >> 5;
    const int lane = tid & 31;
    const int wm = wid >> 2;
    const int wn = wid & 3;
    const int bm = blockIdx.y * 128;
    const int bng = blockIdx.x * 128;
    const int wsel = bng / EE;
    const int bn = bng - wsel * EE;
    const int Kdim = EE;
    const int nch = Kdim / 32;      // 24

    const __half* W = g_whi[wsel];
    const float* bias = (wsel == 0) ? bq : (wsel == 1) ? bk : bv;

    const __half* srcA = g_xhi + (size_t)bm * Kdim;
    const __half* srcW = W + (size_t)bn * Kdim;

    const int row_g = tid >> 1;          // 0..127
    const int ch0   = (tid & 1) * 2;     // 0 or 2

    auto load_stage = [&](int kc, int buf) {
        uint32_t base = sbase + buf * QSTG;
        const __half* sa = srcA + (size_t)row_g * Kdim + kc * 32;
        const __half* sw = srcW + (size_t)row_g * Kdim + kc * 32;
        cpa16(base + swz64(row_g * 64 + (ch0 + 0) * 16), sa + (ch0 + 0) * 8);
        cpa16(base + swz64(row_g * 64 + (ch0 + 1) * 16), sa + (ch0 + 1) * 8);
        cpa16(base + 8192 + swz64(row_g * 64 + (ch0 + 0) * 16), sw + (ch0 + 0) * 8);
        cpa16(base + 8192 + swz64(row_g * 64 + (ch0 + 1) * 16), sw + (ch0 + 1) * 8);
        CP_COMMIT();
    };

    float acc[4][4][4];
#pragma unroll
    for (int mt = 0; mt < 4; mt++)
#pragma unroll
        for (int nt = 0; nt < 4; nt++)
#pragma unroll
            for (int e = 0; e < 4; e++) acc[mt][nt][e] = 0.f;

#pragma unroll
    for (int s = 0; s < QNST - 1; s++) load_stage(s, s);

    for (int kc = 0; kc < nch; kc++) {
        CP_WAIT4();
        __syncthreads();
        int nb = kc + QNST - 1;
        if (nb < nch) load_stage(nb, nb % QNST);
        else CP_COMMIT();                      // keep group counts uniform

        const uint32_t st = sbase + (kc % QNST) * QSTG;
        const uint32_t sAh = st, sWh = st + 8192;

#pragma unroll
        for (int k16 = 0; k16 < 2; k16++) {
            uint32_t Ah[4][4], Bh[2][4];
#pragma unroll
            for (int mt = 0; mt < 4; mt++) ldsm4_a(Ah[mt], sAh, wm * 64 + mt * 16, k16);
#pragma unroll
            for (int p = 0; p < 2; p++) ldsm4_b(Bh[p], sWh, wn * 32 + p * 16, k16);
#pragma unroll
            for (int mt = 0; mt < 4; mt++)
#pragma unroll
                for (int nt = 0; nt < 4; nt++)
                    mma16816(acc[mt][nt], Ah[mt], &Bh[nt >> 1][(nt & 1) * 2]);
        }
    }

    if (wsel == 2) {
        // V: transpose via smem, write g_vt[n][m] coalesced
        CP_WAIT0();
        __syncthreads();
        __half* smt = (__half*)dsm;     // [128 n][128 m] = 32KB
#pragma unroll
        for (int mt = 0; mt < 4; mt++) {
            const int ml = wm * 64 + mt * 16 + (lane >> 2);
#pragma unroll
            for (int nt = 0; nt < 4; nt++) {
                const int nl = wn * 32 + nt * 8 + 2 * (lane & 3);
                const float b0 = bias[bn + nl], b1 = bias[bn + nl + 1];
                smt[(nl + 0) * 128 + ml] = __float2half(acc[mt][nt][0] + b0);
                smt[(nl + 1) * 128 + ml] = __float2half(acc[mt][nt][1] + b1);
                smt[(nl + 0) * 128 + ml + 8] = __float2half(acc[mt][nt][2] + b0);
                smt[(nl + 1) * 128 + ml + 8] = __float2half(acc[mt][nt][3] + b1);
            }
        }
        __syncthreads();
        const int nrow = tid >> 1;
        const int seg  = tid & 1;
        const uint4* srcv = (const uint4*)(smt + nrow * 128 + seg * 64);
        uint4* dstv = (uint4*)(g_vt + (size_t)(bn + nrow) * MTOK + bm + seg * 64);
#pragma unroll
        for (int u = 0; u < 8; u++) dstv[u] = srcv[u];
        return;
    }

    __half* dst = (wsel == 0) ? g_qhi : g_khi;
    const float sc = (wsel == 0) ? scaling : 1.0f;
#pragma unroll
    for (int mt = 0; mt < 4; mt++) {
        const int m0 = bm + wm * 64 + mt * 16 + (lane >> 2);
#pragma unroll
        for (int nt = 0; nt < 4; nt++) {
            const int col = bn + wn * 32 + nt * 8 + 2 * (lane & 3);
            const float b0 = bias[col], b1 = bias[col + 1];
            *(__half2*)(dst + (size_t)m0 * EE + col) =
                __halves2half2(__float2half(sc * (acc[mt][nt][0] + b0)),
                               __float2half(sc * (acc[mt][nt][1] + b1)));
            *(__half2*)(dst + (size_t)(m0 + 8) * EE + col) =
                __halves2half2(__float2half(sc * (acc[mt][nt][2] + b0)),
                               __float2half(sc * (acc[mt][nt][3] + b1)));
        }
    }
}

// ---------------------------------------------------------------------------
// O projection GEMM: out = chi @ Wo.T + bo  (fp32 out, 1-product, BK=32, 6 stg)
// ---------------------------------------------------------------------------
__global__ __launch_bounds__(256, 2) void o_gemm_kernel(
    const float* __restrict__ bias, float* __restrict__ out)
{
    extern __shared__ char dsm[];
    const uint32_t sbase = smem_u32(dsm);

    const int tid  = threadIdx.x;
    const int wid  = tid >> 5;
    const int lane = tid & 31;
    const int wm = wid >> 2;
    const int wn = wid & 3;
    const int bm = blockIdx.y * 128;
    const int bn = blockIdx.x * 128;
    const int Kdim = EE;
    const int nch = Kdim / 32;      // 24

    const __half* srcA = g_chi + (size_t)bm * Kdim;
    const __half* srcW = g_whi[3] + (size_t)bn * Kdim;

    const int row_g = tid >> 1;
    const int ch0   = (tid & 1) * 2;

    auto load_stage = [&](int kc, int buf) {
        uint32_t base = sbase + buf * QSTG;
        const __half* sa = srcA + (size_t)row_g * Kdim + kc * 32;
        const __half* sw = srcW + (size_t)row_g * Kdim + kc * 32;
        cpa16(base + swz64(row_g * 64 + (ch0 + 0) * 16), sa + (ch0 + 0) * 8);
        cpa16(base + swz64(row_g * 64 + (ch0 + 1) * 16), sa + (ch0 + 1) * 8);
        cpa16(base + 8192 + swz64(row_g * 64 + (ch0 + 0) * 16), sw + (ch0 + 0) * 8);
        cpa16(base + 8192 + swz64(row_g * 64 + (ch0 + 1) * 16), sw + (ch0 + 1) * 8);
        CP_COMMIT();
    };

    float acc[4][4][4];
#pragma unroll
    for (int mt = 0; mt < 4; mt++)
#pragma unroll
        for (int nt = 0; nt < 4; nt++)
#pragma unroll
            for (int e = 0; e < 4; e++) acc[mt][nt][e] = 0.f;

#pragma unroll
    for (int s = 0; s < QNST - 1; s++) load_stage(s, s);

    for (int kc = 0; kc < nch; kc++) {
        CP_WAIT4();
        __syncthreads();
        int nb = kc + QNST - 1;
        if (nb < nch) load_stage(nb, nb % QNST);
        else CP_COMMIT();

        const uint32_t st = sbase + (kc % QNST) * QSTG;
        const uint32_t sAh = st, sWh = st + 8192;

#pragma unroll
        for (int k16 = 0; k16 < 2; k16++) {
            uint32_t Ah[4][4], Bh[2][4];
#pragma unroll
            for (int mt = 0; mt < 4; mt++) ldsm4_a(Ah[mt], sAh, wm * 64 + mt * 16, k16);
#pragma unroll
            for (int p = 0; p < 2; p++) ldsm4_b(Bh[p], sWh, wn * 32 + p * 16, k16);
#pragma unroll
            for (int mt = 0; mt < 4; mt++)
#pragma unroll
                for (int nt = 0; nt < 4; nt++)
                    mma16816(acc[mt][nt], Ah[mt], &Bh[nt >> 1][(nt & 1) * 2]);
        }
    }

#pragma unroll
    for (int mt = 0; mt < 4; mt++) {
        const int m0 = bm + wm * 64 + mt * 16 + (lane >> 2);
#pragma unroll
        for (int nt = 0; nt < 4; nt++) {
            const int col = bn + wn * 32 + nt * 8 + 2 * (lane & 3);
            const float b0 = bias[col], b1 = bias[col + 1];
            *(float2*)(out + (size_t)m0 * EE + col) =
                make_float2(acc[mt][nt][0] + b0, acc[mt][nt][1] + b1);
            *(float2*)(out + (size_t)(m0 + 8) * EE + col) =
                make_float2(acc[mt][nt][2] + b0, acc[mt][nt][3] + b1);
        }
    }
}

// ---------------------------------------------------------------------------
// Attention logits (HMMA, 1-product qhi·khi):
// Per CTA: 128(i) x 128(j), BK = 64 (one r), 8 r's per CTA.
// grid (2 j, 2 i, HH*NPARTL). 32KB/stage x 3 -> 2 CTAs/SM.
// ---------------------------------------------------------------------------
#define LSTG 32768
#define LOGITS_DSMEM (3 * LSTG)

__global__ __launch_bounds__(256, 2) void logits_kernel()
{
    extern __shared__ char dsm[];
    const uint32_t sbase = smem_u32(dsm);

    const int tid  = threadIdx.x;
    const int wid  = tid >> 5;
    const int lane = tid & 31;
    const int wm = wid >> 2;
    const int wn = wid & 3;
    const int j0 = blockIdx.x * 128;
    const int i0 = blockIdx.y * 128;
    const int h  = blockIdx.z % HH;
    const int p  = blockIdx.z / HH;
    const int rbeg = p * (RR / NPARTL);    // 8 r's per CTA
    const int nch = RR / NPARTL;

    const int lrow = tid & 127;
    const int sg0  = (tid >> 7) * 4;

    auto load_stage = [&](int rc, int buf) {
        const int r = rbeg + rc;
        const __half* qh = g_qhi + ((size_t)(r * CC + i0 + lrow)) * EE + h * DKK;
        const __half* kh = g_khi + ((size_t)(r * CC + j0 + lrow)) * EE + h * DKK;
        uint32_t b0 = sbase + buf * LSTG;
#pragma unroll
        for (int s = 0; s < 4; s++) {
            uint32_t off = swz128(lrow * 128 + (sg0 + s) * 16);
            cpa16(b0 + off, qh + (sg0 + s) * 8);
            cpa16(b0 + 16384 + off, kh + (sg0 + s) * 8);
        }
        CP_COMMIT();
    };

    float acc[4][4][4];
#pragma unroll
    for (int mt = 0; mt < 4; mt++)
#pragma unroll
        for (int nt = 0; nt < 4; nt++)
#pragma unroll
            for (int e = 0; e < 4; e++) acc[mt][nt][e] = 0.f;

    load_stage(0, 0);
    load_stage(1, 1);

    for (int rc = 0; rc < nch; rc++) {
        CP_WAIT1();
        __syncthreads();
        int nb = rc + 2;
        if (nb < nch) load_stage(nb, nb % 3);
        else CP_COMMIT();

        const uint32_t st = sbase + (rc % 3) * LSTG;
        const uint32_t sQh = st, sKh = st + 16384;

#pragma unroll
        for (int k16 = 0; k16 < 4; k16++) {
            uint32_t Ah[4][4], Bh[2][4];
#pragma unroll
            for (int mt = 0; mt < 4; mt++) ldsm4_a128(Ah[mt], sQh, wm * 64 + mt * 16, k16);
#pragma unroll
            for (int pq = 0; pq < 2; pq++) ldsm4_b128(Bh[pq], sKh, wn * 32 + pq * 16, k16);
#pragma unroll
            for (int mt = 0; mt < 4; mt++)
#pragma unroll
                for (int nt = 0; nt < 4; nt++)
                    mma16816(acc[mt][nt], Ah[mt], &Bh[nt >> 1][(nt & 1) * 2]);
        }
    }

    float* ab = g_attn_part[p] + (size_t)h * CC * CC;
#pragma unroll
    for (int mt = 0; mt < 4; mt++) {
        const int m0 = i0 + wm * 64 + mt * 16 + (lane >> 2);
#pragma unroll
        for (int nt = 0; nt < 4; nt++) {
            const int col = j0 + wn * 32 + nt * 8 + 2 * (lane & 3);
            *(float2*)(ab + (size_t)m0 * CC + col) =
                make_float2(acc[mt][nt][0], acc[mt][nt][1]);
            *(float2*)(ab + (size_t)(m0 + 8) * CC + col) =
                make_float2(acc[mt][nt][2], acc[mt][nt][3]);
        }
    }
}

// ---------------------------------------------------------------------------
// Row softmax; sums NPARTL partials; writes fp32 probs + fp16 hi/lo probs.
// ---------------------------------------------------------------------------
__global__ __launch_bounds__(256) void softmax_kernel(float* __restrict__ probs_out)
{
    __shared__ float red[256];
    const int row = blockIdx.x;                 // 0 .. H*C-1
    const int tid = threadIdx.x;
    float v = 0.f;
#pragma unroll
    for (int pp = 0; pp < NPARTL; pp++)
        v += g_attn_part[pp][(size_t)row * CC + tid];

    red[tid] = v; __syncthreads();
    for (int s = 128; s > 0; s >>= 1) {
        if (tid < s) red[tid] = fmaxf(red[tid], red[tid + s]);
        __syncthreads();
    }
    float mx = red[0];
    __syncthreads();

    float e = __expf(v - mx);
    red[tid] = e; __syncthreads();
    for (int s = 128; s > 0; s >>= 1) {
        if (tid < s) red[tid] += red[tid + s];
        __syncthreads();
    }
    float pr = e / red[0];

    probs_out[(size_t)row * CC + tid] = pr;
    __half hh = __float2half(pr);
    g_phi[(size_t)row * CC + tid] = hh;
    g_plo[(size_t)row * CC + tid] = __float2half(pr - __half2float(hh));
}

// ---------------------------------------------------------------------------
// Context (HMMA): c = (phi+plo) @ v_t rows; per CTA fixed (h, r), 128(i) x 64(d).
// 4-stage pipeline (depth 3). Writes c as plain fp16 for the O projection.
// ---------------------------------------------------------------------------
#define CSTG 20480             // Phi 8K + Plo 8K + V 4K
#define CNST 4
#define CTX_DSMEM (CNST * CSTG)

__global__ __launch_bounds__(256, 2) void context_kernel()
{
    extern __shared__ char dsm[];
    const uint32_t sbase = smem_u32(dsm);

    const int tid  = threadIdx.x;
    const int wid  = tid >> 5;
    const int lane = tid & 31;
    const int wm = wid >> 2;        // 0..1
    const int wn = wid & 3;         // 0..3
    const int i0 = blockIdx.x * 128;
    const int r  = blockIdx.y;
    const int h  = blockIdx.z;
    const int nch = CC / 32;        // 8

    const __half* Ph = g_phi + (size_t)h * CC * CC + (size_t)i0 * CC;
    const __half* Pl = g_plo + (size_t)h * CC * CC + (size_t)i0 * CC;
    const __half* Vb = g_vt + (size_t)(h * DKK) * MTOK + (size_t)r * CC;

    const int arow = tid >> 1;
    const int asp  = (tid & 1) * 2;
    const int brow = tid >> 2;
    const int bsg  = tid & 3;

    auto load_stage = [&](int kc, int buf) {
        uint32_t b0 = sbase + buf * CSTG;
        const __half* sa = Ph + (size_t)arow * CC + kc * 32;
        const __half* sl = Pl + (size_t)arow * CC + kc * 32;
        cpa16(b0 + swz64(arow * 64 + (asp + 0) * 16), sa + (asp + 0) * 8);
        cpa16(b0 + swz64(arow * 64 + (asp + 1) * 16), sa + (asp + 1) * 8);
        cpa16(b0 + 8192 + swz64(arow * 64 + (asp + 0) * 16), sl + (asp + 0) * 8);
        cpa16(b0 + 8192 + swz64(arow * 64 + (asp + 1) * 16), sl + (asp + 1) * 8);
        const __half* sv = Vb + (size_t)brow * MTOK + kc * 32;
        cpa16(b0 + 16384 + swz64(brow * 64 + bsg * 16), sv + bsg * 8);
        CP_COMMIT();
    };

    float acc[4][2][4];
#pragma unroll
    for (int mt = 0; mt < 4; mt++)
#pragma unroll
        for (int nt = 0; nt < 2; nt++)
#pragma unroll
            for (int e = 0; e < 4; e++) acc[mt][nt][e] = 0.f;

#pragma unroll
    for (int s = 0; s < CNST - 1; s++) load_stage(s, s);

    for (int kc = 0; kc < nch; kc++) {
        CP_WAIT2();
        __syncthreads();
        int nb = kc + CNST - 1;
        if (nb < nch) load_stage(nb, nb % CNST);
        else CP_COMMIT();

        const uint32_t st = sbase + (kc % CNST) * CSTG;
        const uint32_t sPh = st, sPl = st + 8192, sV = st + 16384;

#pragma unroll
        for (int k16 = 0; k16 < 2; k16++) {
            uint32_t Ah[4][4], Al[4][4], Bh[4];
#pragma unroll
            for (int mt = 0; mt < 4; mt++) ldsm4_a(Ah[mt], sPh, wm * 64 + mt * 16, k16);
#pragma unroll
            for (int mt = 0; mt < 4; mt++) ldsm4_a(Al[mt], sPl, wm * 64 + mt * 16, k16);
            ldsm4_b(Bh, sV, wn * 16, k16);

#pragma unroll
            for (int mt = 0; mt < 4; mt++)
#pragma unroll
                for (int nt = 0; nt < 2; nt++) {
                    mma16816(acc[mt][nt], Ah[mt], &Bh[nt * 2]);
                    mma16816(acc[mt][nt], Al[mt], &Bh[nt * 2]);
                }
        }
    }

#pragma unroll
    for (int mt = 0; mt < 4; mt++) {
        const int iL = i0 + wm * 64 + mt * 16 + (lane >> 2);
        const size_t tok0 = (size_t)(r * CC + iL) * EE + h * DKK;
        const size_t tok1 = (size_t)(r * CC + iL + 8) * EE + h * DKK;
#pragma unroll
        for (int nt = 0; nt < 2; nt++) {
            const int col = wn * 16 + nt * 8 + 2 * (lane & 3);
            *(__half2*)(g_chi + tok0 + col) =
                __halves2half2(__float2half(acc[mt][nt][0]),
                               __float2half(acc[mt][nt][1]));
            *(__half2*)(g_chi + tok1 + col) =
                __halves2half2(__float2half(acc[mt][nt][2]),
                               __float2half(acc[mt][nt][3]));
        }
    }
}

// ---------------------------------------------------------------------------
extern "C" void kernel_launch(void* const* d_in, const int* in_sizes, int n_in,
                              void* d_out, int out_size)
{
    const float* x  = (const float*)d_in[0];
    const float* Wq = (const float*)d_in[1];
    const float* bq = (const float*)d_in[2];
    const float* Wk = (const float*)d_in[3];
    const float* bk = (const float*)d_in[4];
    const float* Wv = (const float*)d_in[5];
    const float* bv = (const float*)d_in[6];
    const float* Wo = (const float*)d_in[7];
    const float* bo = (const float*)d_in[8];

    float* out = (float*)d_out;                       // [R,C,B,E]
    float* probs = out + (size_t)MTOK * EE;           // [H,B,C,C]

    cudaFuncSetAttribute(qkv_gemm_kernel,
                         cudaFuncAttributeMaxDynamicSharedMemorySize, GEMM_DSMEM);
    cudaFuncSetAttribute(o_gemm_kernel,
                         cudaFuncAttributeMaxDynamicSharedMemorySize, GEMM_DSMEM);
    cudaFuncSetAttribute(logits_kernel,
                         cudaFuncAttributeMaxDynamicSharedMemorySize, LOGITS_DSMEM);
    cudaFuncSetAttribute(context_kernel,
                         cudaFuncAttributeMaxDynamicSharedMemorySize, CTX_DSMEM);

    const float scaling = 0.125f / sqrtf((float)RR);  // DK^-0.5 / sqrt(R)
    const size_t WN = (size_t)EE * EE;

    // splits
    {
        int n4x = (int)((size_t)MTOK * EE / 4);
        xsplit_kernel<<<(n4x + 255) / 256, 256>>>(x, n4x);
        int n4w = (int)(WN / 4);
        wsplit_kernel<<<(4 * n4w + 255) / 256, 256>>>(Wq, Wk, Wv, Wo, n4w);
    }

    qkv_gemm_kernel<<<dim3(3 * EE / 128, MTOK / 128), 256, GEMM_DSMEM>>>(
        bq, bk, bv, scaling);

    logits_kernel<<<dim3(2, 2, HH * NPARTL), 256, LOGITS_DSMEM>>>();
    softmax_kernel<<<HH * CC, 256>>>(probs);
    context_kernel<<<dim3(2, RR, HH), 256, CTX_DSMEM>>>();

    o_gemm_kernel<<<dim3(EE / 128, MTOK / 128), 256, GEMM_DSMEM>>>(bo, out);
}

// round 10
// speedup vs baseline: 6.5412x; 1.0489x over previous
#include <cuda_runtime.h>
#include <cuda_fp16.h>
#include <math.h>
#include <stdint.h>

// Problem constants
#define RR 128
#define CC 256
#define EE 768
#define HH 12
#define DKK 64
#define MTOK (RR*CC)          // 32768 tokens
#define NPARTL 16             // r-split for attention logits

// ---------------------------------------------------------------------------
// Scratch (device globals — no allocation allowed)
// ---------------------------------------------------------------------------
__device__ float g_attn_part[NPARTL][(size_t)HH * CC * CC];

__device__ __half g_xhi[(size_t)MTOK * EE];
__device__ __half g_qhi[(size_t)MTOK * EE];
__device__ __half g_khi[(size_t)MTOK * EE];
__device__ __half g_vt [(size_t)EE * MTOK];     // V transposed: [E][token]
__device__ __half g_phi[(size_t)HH * CC * CC];
__device__ __half g_chi[(size_t)MTOK * EE];
__device__ __half g_whi[4][(size_t)EE * EE];

// ---------------------------------------------------------------------------
// Helpers (suffix-free PTX only: cp.async / ldmatrix / mma.sync)
// ---------------------------------------------------------------------------
__device__ __forceinline__ uint32_t smem_u32(const void* p) {
    uint32_t a;
    asm("{ .reg .u64 t; cvta.to.shared.u64 t, %1; cvt.u32.u64 %0, t; }"
        : "=r"(a) : "l"(p));
    return a;
}

__device__ __forceinline__ uint32_t swz64(uint32_t off) {
    return off ^ ((off >> 3) & 0x30);   // 64B-row swizzle
}
__device__ __forceinline__ uint32_t swz128(uint32_t off) {
    return off ^ ((off >> 3) & 0x70);   // 128B-row swizzle
}

__device__ __forceinline__ void cpa16(uint32_t dst, const void* src) {
    asm volatile("cp.async.cg.shared.global [%0], [%1], 16;"
                 :: "r"(dst), "l"(src));
}
#define CP_COMMIT() asm volatile("cp.async.commit_group;" ::: "memory")
#define CP_WAIT1()  asm volatile("cp.async.wait_group 1;" ::: "memory")
#define CP_WAIT2()  asm volatile("cp.async.wait_group 2;" ::: "memory")
#define CP_WAIT4()  asm volatile("cp.async.wait_group 4;" ::: "memory")
#define CP_WAIT0()  asm volatile("cp.async.wait_group 0;" ::: "memory")

// ldmatrix x4 from 64B-row tile: A side (m16 x k16)
__device__ __forceinline__ void ldsm4_a(uint32_t* r, uint32_t sb, int mbase, int k16) {
    int lane = threadIdx.x & 31;
    uint32_t row = mbase + (lane & 15);
    uint32_t cb  = (lane & 16);
    uint32_t addr = sb + swz64(row * 64 + k16 * 32 + cb);
    asm volatile("ldmatrix.sync.aligned.m8n8.x4.shared.b16 {%0,%1,%2,%3}, [%4];"
                 : "=r"(r[0]), "=r"(r[1]), "=r"(r[2]), "=r"(r[3]) : "r"(addr));
}
// ldmatrix x4 from 64B-row tile: B side (two n8 x k16 frags)
__device__ __forceinline__ void ldsm4_b(uint32_t* r, uint32_t sb, int nbase, int k16) {
    int lane = threadIdx.x & 31;
    uint32_t row = nbase + (lane & 7) + ((lane & 16) >> 1);
    uint32_t cb  = (lane & 8) << 1;
    uint32_t addr = sb + swz64(row * 64 + k16 * 32 + cb);
    asm volatile("ldmatrix.sync.aligned.m8n8.x4.shared.b16 {%0,%1,%2,%3}, [%4];"
                 : "=r"(r[0]), "=r"(r[1]), "=r"(r[2]), "=r"(r[3]) : "r"(addr));
}
// 128B-row variants (BK=64 tiles)
__device__ __forceinline__ void ldsm4_a128(uint32_t* r, uint32_t sb, int mbase, int k16) {
    int lane = threadIdx.x & 31;
    uint32_t row = mbase + (lane & 15);
    uint32_t cb  = (lane & 16);
    uint32_t addr = sb + swz128(row * 128 + k16 * 32 + cb);
    asm volatile("ldmatrix.sync.aligned.m8n8.x4.shared.b16 {%0,%1,%2,%3}, [%4];"
                 : "=r"(r[0]), "=r"(r[1]), "=r"(r[2]), "=r"(r[3]) : "r"(addr));
}
__device__ __forceinline__ void ldsm4_b128(uint32_t* r, uint32_t sb, int nbase, int k16) {
    int lane = threadIdx.x & 31;
    uint32_t row = nbase + (lane & 7) + ((lane & 16) >> 1);
    uint32_t cb  = (lane & 8) << 1;
    uint32_t addr = sb + swz128(row * 128 + k16 * 32 + cb);
    asm volatile("ldmatrix.sync.aligned.m8n8.x4.shared.b16 {%0,%1,%2,%3}, [%4];"
                 : "=r"(r[0]), "=r"(r[1]), "=r"(r[2]), "=r"(r[3]) : "r"(addr));
}

__device__ __forceinline__ void mma16816(float* c, const uint32_t* a, const uint32_t* b) {
    asm volatile(
        "mma.sync.aligned.m16n8k16.row.col.f32.f16.f16.f32 "
        "{%0,%1,%2,%3}, {%4,%5,%6,%7}, {%8,%9}, {%0,%1,%2,%3};"
        : "+f"(c[0]), "+f"(c[1]), "+f"(c[2]), "+f"(c[3])
        : "r"(a[0]), "r"(a[1]), "r"(a[2]), "r"(a[3]), "r"(b[0]), "r"(b[1]));
}

// ---------------------------------------------------------------------------
// Splits (hi only)
// ---------------------------------------------------------------------------
__global__ __launch_bounds__(256) void xsplit_kernel(
    const float* __restrict__ src, int n4)
{
    int i = blockIdx.x * 256 + threadIdx.x;
    if (i >= n4) return;
    float4 v = ((const float4*)src)[i];
    __half2* hp = (__half2*)g_xhi;
    hp[2 * i + 0] = __halves2half2(__float2half(v.x), __float2half(v.y));
    hp[2 * i + 1] = __halves2half2(__float2half(v.z), __float2half(v.w));
}

__global__ __launch_bounds__(256) void wsplit_kernel(
    const float* __restrict__ Wq, const float* __restrict__ Wk,
    const float* __restrict__ Wv, const float* __restrict__ Wo, int n4each)
{
    int i = blockIdx.x * 256 + threadIdx.x;
    int w = i / n4each;
    int j = i - w * n4each;
    if (w >= 4) return;
    const float* src = (w == 0) ? Wq : (w == 1) ? Wk : (w == 2) ? Wv : Wo;
    float4 v = ((const float4*)src)[j];
    __half2* hp = (__half2*)(g_whi[w]);
    hp[2 * j + 0] = __halves2half2(__float2half(v.x), __float2half(v.y));
    hp[2 * j + 1] = __halves2half2(__float2half(v.z), __float2half(v.w));
}

// ---------------------------------------------------------------------------
// Fused QKV projection GEMM (HMMA, 1-product xhi·Whi):
//   wsel 0 (Q): scaled -> g_qhi;  wsel 1 (K): -> g_khi;  wsel 2 (V): -> g_vt^T
// CTA 128x128, BK=32, 8 warps, 6-stage cp.async, 2 CTAs/SM.
// ---------------------------------------------------------------------------
#define QSTG 16384             // 2 tiles x 128 x 32 x 2B
#define QNST 6
#define GEMM_DSMEM (QNST * QSTG)

__global__ __launch_bounds__(256, 2) void qkv_gemm_kernel(
    const float* __restrict__ bq, const float* __restrict__ bk,
    const float* __restrict__ bv, float scaling)
{
    extern __shared__ char dsm[];
    const uint32_t sbase = smem_u32(dsm);

    const int tid  = threadIdx.x;
    const int wid  = tid >> 5;
    const int lane = tid & 31;
    const int wm = wid >> 2;
    const int wn = wid & 3;
    const int bm = blockIdx.y * 128;
    const int bng = blockIdx.x * 128;
    const int wsel = bng / EE;
    const int bn = bng - wsel * EE;
    const int Kdim = EE;
    const int nch = Kdim / 32;      // 24

    const __half* W = g_whi[wsel];
    const float* bias = (wsel == 0) ? bq : (wsel == 1) ? bk : bv;

    const __half* srcA = g_xhi + (size_t)bm * Kdim;
    const __half* srcW = W + (size_t)bn * Kdim;

    const int row_g = tid >> 1;          // 0..127
    const int ch0   = (tid & 1) * 2;     // 0 or 2

    auto load_stage = [&](int kc, int buf) {
        uint32_t base = sbase + buf * QSTG;
        const __half* sa = srcA + (size_t)row_g * Kdim + kc * 32;
        const __half* sw = srcW + (size_t)row_g * Kdim + kc * 32;
        cpa16(base + swz64(row_g * 64 + (ch0 + 0) * 16), sa + (ch0 + 0) * 8);
        cpa16(base + swz64(row_g * 64 + (ch0 + 1) * 16), sa + (ch0 + 1) * 8);
        cpa16(base + 8192 + swz64(row_g * 64 + (ch0 + 0) * 16), sw + (ch0 + 0) * 8);
        cpa16(base + 8192 + swz64(row_g * 64 + (ch0 + 1) * 16), sw + (ch0 + 1) * 8);
        CP_COMMIT();
    };

    float acc[4][4][4];
#pragma unroll
    for (int mt = 0; mt < 4; mt++)
#pragma unroll
        for (int nt = 0; nt < 4; nt++)
#pragma unroll
            for (int e = 0; e < 4; e++) acc[mt][nt][e] = 0.f;

#pragma unroll
    for (int s = 0; s < QNST - 1; s++) load_stage(s, s);

    for (int kc = 0; kc < nch; kc++) {
        CP_WAIT4();
        __syncthreads();
        int nb = kc + QNST - 1;
        if (nb < nch) load_stage(nb, nb % QNST);
        else CP_COMMIT();                      // keep group counts uniform

        const uint32_t st = sbase + (kc % QNST) * QSTG;
        const uint32_t sAh = st, sWh = st + 8192;

#pragma unroll
        for (int k16 = 0; k16 < 2; k16++) {
            uint32_t Ah[4][4], Bh[2][4];
#pragma unroll
            for (int mt = 0; mt < 4; mt++) ldsm4_a(Ah[mt], sAh, wm * 64 + mt * 16, k16);
#pragma unroll
            for (int p = 0; p < 2; p++) ldsm4_b(Bh[p], sWh, wn * 32 + p * 16, k16);
#pragma unroll
            for (int mt = 0; mt < 4; mt++)
#pragma unroll
                for (int nt = 0; nt < 4; nt++)
                    mma16816(acc[mt][nt], Ah[mt], &Bh[nt >> 1][(nt & 1) * 2]);
        }
    }

    if (wsel == 2) {
        // V: transpose via smem, write g_vt[n][m] coalesced
        CP_WAIT0();
        __syncthreads();
        __half* smt = (__half*)dsm;     // [128 n][128 m] = 32KB
#pragma unroll
        for (int mt = 0; mt < 4; mt++) {
            const int ml = wm * 64 + mt * 16 + (lane >> 2);
#pragma unroll
            for (int nt = 0; nt < 4; nt++) {
                const int nl = wn * 32 + nt * 8 + 2 * (lane & 3);
                const float b0 = bias[bn + nl], b1 = bias[bn + nl + 1];
                smt[(nl + 0) * 128 + ml] = __float2half(acc[mt][nt][0] + b0);
                smt[(nl + 1) * 128 + ml] = __float2half(acc[mt][nt][1] + b1);
                smt[(nl + 0) * 128 + ml + 8] = __float2half(acc[mt][nt][2] + b0);
                smt[(nl + 1) * 128 + ml + 8] = __float2half(acc[mt][nt][3] + b1);
            }
        }
        __syncthreads();
        const int nrow = tid >> 1;
        const int seg  = tid & 1;
        const uint4* srcv = (const uint4*)(smt + nrow * 128 + seg * 64);
        uint4* dstv = (uint4*)(g_vt + (size_t)(bn + nrow) * MTOK + bm + seg * 64);
#pragma unroll
        for (int u = 0; u < 8; u++) dstv[u] = srcv[u];
        return;
    }

    __half* dst = (wsel == 0) ? g_qhi : g_khi;
    const float sc = (wsel == 0) ? scaling : 1.0f;
#pragma unroll
    for (int mt = 0; mt < 4; mt++) {
        const int m0 = bm + wm * 64 + mt * 16 + (lane >> 2);
#pragma unroll
        for (int nt = 0; nt < 4; nt++) {
            const int col = bn + wn * 32 + nt * 8 + 2 * (lane & 3);
            const float b0 = bias[col], b1 = bias[col + 1];
            *(__half2*)(dst + (size_t)m0 * EE + col) =
                __halves2half2(__float2half(sc * (acc[mt][nt][0] + b0)),
                               __float2half(sc * (acc[mt][nt][1] + b1)));
            *(__half2*)(dst + (size_t)(m0 + 8) * EE + col) =
                __halves2half2(__float2half(sc * (acc[mt][nt][2] + b0)),
                               __float2half(sc * (acc[mt][nt][3] + b1)));
        }
    }
}

// ---------------------------------------------------------------------------
// O projection GEMM: out = chi @ Wo.T + bo  (fp32 out, 1-product, BK=32, 6 stg)
// ---------------------------------------------------------------------------
__global__ __launch_bounds__(256, 2) void o_gemm_kernel(
    const float* __restrict__ bias, float* __restrict__ out)
{
    extern __shared__ char dsm[];
    const uint32_t sbase = smem_u32(dsm);

    const int tid  = threadIdx.x;
    const int wid  = tid >> 5;
    const int lane = tid & 31;
    const int wm = wid >> 2;
    const int wn = wid & 3;
    const int bm = blockIdx.y * 128;
    const int bn = blockIdx.x * 128;
    const int Kdim = EE;
    const int nch = Kdim / 32;      // 24

    const __half* srcA = g_chi + (size_t)bm * Kdim;
    const __half* srcW = g_whi[3] + (size_t)bn * Kdim;

    const int row_g = tid >> 1;
    const int ch0   = (tid & 1) * 2;

    auto load_stage = [&](int kc, int buf) {
        uint32_t base = sbase + buf * QSTG;
        const __half* sa = srcA + (size_t)row_g * Kdim + kc * 32;
        const __half* sw = srcW + (size_t)row_g * Kdim + kc * 32;
        cpa16(base + swz64(row_g * 64 + (ch0 + 0) * 16), sa + (ch0 + 0) * 8);
        cpa16(base + swz64(row_g * 64 + (ch0 + 1) * 16), sa + (ch0 + 1) * 8);
        cpa16(base + 8192 + swz64(row_g * 64 + (ch0 + 0) * 16), sw + (ch0 + 0) * 8);
        cpa16(base + 8192 + swz64(row_g * 64 + (ch0 + 1) * 16), sw + (ch0 + 1) * 8);
        CP_COMMIT();
    };

    float acc[4][4][4];
#pragma unroll
    for (int mt = 0; mt < 4; mt++)
#pragma unroll
        for (int nt = 0; nt < 4; nt++)
#pragma unroll
            for (int e = 0; e < 4; e++) acc[mt][nt][e] = 0.f;

#pragma unroll
    for (int s = 0; s < QNST - 1; s++) load_stage(s, s);

    for (int kc = 0; kc < nch; kc++) {
        CP_WAIT4();
        __syncthreads();
        int nb = kc + QNST - 1;
        if (nb < nch) load_stage(nb, nb % QNST);
        else CP_COMMIT();

        const uint32_t st = sbase + (kc % QNST) * QSTG;
        const uint32_t sAh = st, sWh = st + 8192;

#pragma unroll
        for (int k16 = 0; k16 < 2; k16++) {
            uint32_t Ah[4][4], Bh[2][4];
#pragma unroll
            for (int mt = 0; mt < 4; mt++) ldsm4_a(Ah[mt], sAh, wm * 64 + mt * 16, k16);
#pragma unroll
            for (int p = 0; p < 2; p++) ldsm4_b(Bh[p], sWh, wn * 32 + p * 16, k16);
#pragma unroll
            for (int mt = 0; mt < 4; mt++)
#pragma unroll
                for (int nt = 0; nt < 4; nt++)
                    mma16816(acc[mt][nt], Ah[mt], &Bh[nt >> 1][(nt & 1) * 2]);
        }
    }

#pragma unroll
    for (int mt = 0; mt < 4; mt++) {
        const int m0 = bm + wm * 64 + mt * 16 + (lane >> 2);
#pragma unroll
        for (int nt = 0; nt < 4; nt++) {
            const int col = bn + wn * 32 + nt * 8 + 2 * (lane & 3);
            const float b0 = bias[col], b1 = bias[col + 1];
            *(float2*)(out + (size_t)m0 * EE + col) =
                make_float2(acc[mt][nt][0] + b0, acc[mt][nt][1] + b1);
            *(float2*)(out + (size_t)(m0 + 8) * EE + col) =
                make_float2(acc[mt][nt][2] + b0, acc[mt][nt][3] + b1);
        }
    }
}

// ---------------------------------------------------------------------------
// Attention logits (HMMA, 1-product qhi·khi):
// Per CTA: 128(i) x 128(j), BK = 64 (one r), 8 r's per CTA.
// grid (2 j, 2 i, HH*NPARTL). 32KB/stage x 3 -> 2 CTAs/SM.
// ---------------------------------------------------------------------------
#define LSTG 32768
#define LOGITS_DSMEM (3 * LSTG)

__global__ __launch_bounds__(256, 2) void logits_kernel()
{
    extern __shared__ char dsm[];
    const uint32_t sbase = smem_u32(dsm);

    const int tid  = threadIdx.x;
    const int wid  = tid >> 5;
    const int lane = tid & 31;
    const int wm = wid >> 2;
    const int wn = wid & 3;
    const int j0 = blockIdx.x * 128;
    const int i0 = blockIdx.y * 128;
    const int h  = blockIdx.z % HH;
    const int p  = blockIdx.z / HH;
    const int rbeg = p * (RR / NPARTL);    // 8 r's per CTA
    const int nch = RR / NPARTL;

    const int lrow = tid & 127;
    const int sg0  = (tid >> 7) * 4;

    auto load_stage = [&](int rc, int buf) {
        const int r = rbeg + rc;
        const __half* qh = g_qhi + ((size_t)(r * CC + i0 + lrow)) * EE + h * DKK;
        const __half* kh = g_khi + ((size_t)(r * CC + j0 + lrow)) * EE + h * DKK;
        uint32_t b0 = sbase + buf * LSTG;
#pragma unroll
        for (int s = 0; s < 4; s++) {
            uint32_t off = swz128(lrow * 128 + (sg0 + s) * 16);
            cpa16(b0 + off, qh + (sg0 + s) * 8);
            cpa16(b0 + 16384 + off, kh + (sg0 + s) * 8);
        }
        CP_COMMIT();
    };

    float acc[4][4][4];
#pragma unroll
    for (int mt = 0; mt < 4; mt++)
#pragma unroll
        for (int nt = 0; nt < 4; nt++)
#pragma unroll
            for (int e = 0; e < 4; e++) acc[mt][nt][e] = 0.f;

    load_stage(0, 0);
    load_stage(1, 1);

    for (int rc = 0; rc < nch; rc++) {
        CP_WAIT1();
        __syncthreads();
        int nb = rc + 2;
        if (nb < nch) load_stage(nb, nb % 3);
        else CP_COMMIT();

        const uint32_t st = sbase + (rc % 3) * LSTG;
        const uint32_t sQh = st, sKh = st + 16384;

#pragma unroll
        for (int k16 = 0; k16 < 4; k16++) {
            uint32_t Ah[4][4], Bh[2][4];
#pragma unroll
            for (int mt = 0; mt < 4; mt++) ldsm4_a128(Ah[mt], sQh, wm * 64 + mt * 16, k16);
#pragma unroll
            for (int pq = 0; pq < 2; pq++) ldsm4_b128(Bh[pq], sKh, wn * 32 + pq * 16, k16);
#pragma unroll
            for (int mt = 0; mt < 4; mt++)
#pragma unroll
                for (int nt = 0; nt < 4; nt++)
                    mma16816(acc[mt][nt], Ah[mt], &Bh[nt >> 1][(nt & 1) * 2]);
        }
    }

    float* ab = g_attn_part[p] + (size_t)h * CC * CC;
#pragma unroll
    for (int mt = 0; mt < 4; mt++) {
        const int m0 = i0 + wm * 64 + mt * 16 + (lane >> 2);
#pragma unroll
        for (int nt = 0; nt < 4; nt++) {
            const int col = j0 + wn * 32 + nt * 8 + 2 * (lane & 3);
            *(float2*)(ab + (size_t)m0 * CC + col) =
                make_float2(acc[mt][nt][0], acc[mt][nt][1]);
            *(float2*)(ab + (size_t)(m0 + 8) * CC + col) =
                make_float2(acc[mt][nt][2], acc[mt][nt][3]);
        }
    }
}

// ---------------------------------------------------------------------------
// Row softmax; sums NPARTL partials; writes fp32 probs + fp16 probs.
// ---------------------------------------------------------------------------
__global__ __launch_bounds__(256) void softmax_kernel(float* __restrict__ probs_out)
{
    __shared__ float red[256];
    const int row = blockIdx.x;                 // 0 .. H*C-1
    const int tid = threadIdx.x;
    float v = 0.f;
#pragma unroll
    for (int pp = 0; pp < NPARTL; pp++)
        v += g_attn_part[pp][(size_t)row * CC + tid];

    red[tid] = v; __syncthreads();
    for (int s = 128; s > 0; s >>= 1) {
        if (tid < s) red[tid] = fmaxf(red[tid], red[tid + s]);
        __syncthreads();
    }
    float mx = red[0];
    __syncthreads();

    float e = __expf(v - mx);
    red[tid] = e; __syncthreads();
    for (int s = 128; s > 0; s >>= 1) {
        if (tid < s) red[tid] += red[tid + s];
        __syncthreads();
    }
    float pr = e / red[0];

    probs_out[(size_t)row * CC + tid] = pr;
    g_phi[(size_t)row * CC + tid] = __float2half(pr);
}

// ---------------------------------------------------------------------------
// Context (HMMA, 1-product phi·v): per CTA fixed (h, r), 128(i) x 64(d).
// 4-stage pipeline (depth 3). Writes c as plain fp16 for the O projection.
// ---------------------------------------------------------------------------
#define CSTG 12288             // Phi 8K + V 4K
#define CNST 4
#define CTX_DSMEM (CNST * CSTG)

__global__ __launch_bounds__(256, 2) void context_kernel()
{
    extern __shared__ char dsm[];
    const uint32_t sbase = smem_u32(dsm);

    const int tid  = threadIdx.x;
    const int wid  = tid >> 5;
    const int lane = tid & 31;
    const int wm = wid >> 2;        // 0..1
    const int wn = wid & 3;         // 0..3
    const int i0 = blockIdx.x * 128;
    const int r  = blockIdx.y;
    const int h  = blockIdx.z;
    const int nch = CC / 32;        // 8

    const __half* Ph = g_phi + (size_t)h * CC * CC + (size_t)i0 * CC;
    const __half* Vb = g_vt + (size_t)(h * DKK) * MTOK + (size_t)r * CC;

    const int arow = tid >> 1;
    const int asp  = (tid & 1) * 2;
    const int brow = tid >> 2;
    const int bsg  = tid & 3;

    auto load_stage = [&](int kc, int buf) {
        uint32_t b0 = sbase + buf * CSTG;
        const __half* sa = Ph + (size_t)arow * CC + kc * 32;
        cpa16(b0 + swz64(arow * 64 + (asp + 0) * 16), sa + (asp + 0) * 8);
        cpa16(b0 + swz64(arow * 64 + (asp + 1) * 16), sa + (asp + 1) * 8);
        const __half* sv = Vb + (size_t)brow * MTOK + kc * 32;
        cpa16(b0 + 8192 + swz64(brow * 64 + bsg * 16), sv + bsg * 8);
        CP_COMMIT();
    };

    float acc[4][2][4];
#pragma unroll
    for (int mt = 0; mt < 4; mt++)
#pragma unroll
        for (int nt = 0; nt < 2; nt++)
#pragma unroll
            for (int e = 0; e < 4; e++) acc[mt][nt][e] = 0.f;

#pragma unroll
    for (int s = 0; s < CNST - 1; s++) load_stage(s, s);

    for (int kc = 0; kc < nch; kc++) {
        CP_WAIT2();
        __syncthreads();
        int nb = kc + CNST - 1;
        if (nb < nch) load_stage(nb, nb % CNST);
        else CP_COMMIT();

        const uint32_t st = sbase + (kc % CNST) * CSTG;
        const uint32_t sPh = st, sV = st + 8192;

#pragma unroll
        for (int k16 = 0; k16 < 2; k16++) {
            uint32_t Ah[4][4], Bh[4];
#pragma unroll
            for (int mt = 0; mt < 4; mt++) ldsm4_a(Ah[mt], sPh, wm * 64 + mt * 16, k16);
            ldsm4_b(Bh, sV, wn * 16, k16);

#pragma unroll
            for (int mt = 0; mt < 4; mt++)
#pragma unroll
                for (int nt = 0; nt < 2; nt++)
                    mma16816(acc[mt][nt], Ah[mt], &Bh[nt * 2]);
        }
    }

#pragma unroll
    for (int mt = 0; mt < 4; mt++) {
        const int iL = i0 + wm * 64 + mt * 16 + (lane >> 2);
        const size_t tok0 = (size_t)(r * CC + iL) * EE + h * DKK;
        const size_t tok1 = (size_t)(r * CC + iL + 8) * EE + h * DKK;
#pragma unroll
        for (int nt = 0; nt < 2; nt++) {
            const int col = wn * 16 + nt * 8 + 2 * (lane & 3);
            *(__half2*)(g_chi + tok0 + col) =
                __halves2half2(__float2half(acc[mt][nt][0]),
                               __float2half(acc[mt][nt][1]));
            *(__half2*)(g_chi + tok1 + col) =
                __halves2half2(__float2half(acc[mt][nt][2]),
                               __float2half(acc[mt][nt][3]));
        }
    }
}

// ---------------------------------------------------------------------------
extern "C" void kernel_launch(void* const* d_in, const int* in_sizes, int n_in,
                              void* d_out, int out_size)
{
    const float* x  = (const float*)d_in[0];
    const float* Wq = (const float*)d_in[1];
    const float* bq = (const float*)d_in[2];
    const float* Wk = (const float*)d_in[3];
    const float* bk = (const float*)d_in[4];
    const float* Wv = (const float*)d_in[5];
    const float* bv = (const float*)d_in[6];
    const float* Wo = (const float*)d_in[7];
    const float* bo = (const float*)d_in[8];

    float* out = (float*)d_out;                       // [R,C,B,E]
    float* probs = out + (size_t)MTOK * EE;           // [H,B,C,C]

    cudaFuncSetAttribute(qkv_gemm_kernel,
                         cudaFuncAttributeMaxDynamicSharedMemorySize, GEMM_DSMEM);
    cudaFuncSetAttribute(o_gemm_kernel,
                         cudaFuncAttributeMaxDynamicSharedMemorySize, GEMM_DSMEM);
    cudaFuncSetAttribute(logits_kernel,
                         cudaFuncAttributeMaxDynamicSharedMemorySize, LOGITS_DSMEM);
    cudaFuncSetAttribute(context_kernel,
                         cudaFuncAttributeMaxDynamicSharedMemorySize, CTX_DSMEM);

    const float scaling = 0.125f / sqrtf((float)RR);  // DK^-0.5 / sqrt(R)
    const size_t WN = (size_t)EE * EE;

    // splits
    {
        int n4x = (int)((size_t)MTOK * EE / 4);
        xsplit_kernel<<<(n4x + 255) / 256, 256>>>(x, n4x);
        int n4w = (int)(WN / 4);
        wsplit_kernel<<<(4 * n4w + 255) / 256, 256>>>(Wq, Wk, Wv, Wo, n4w);
    }

    qkv_gemm_kernel<<<dim3(3 * EE / 128, MTOK / 128), 256, GEMM_DSMEM>>>(
        bq, bk, bv, scaling);

    logits_kernel<<<dim3(2, 2, HH * NPARTL), 256, LOGITS_DSMEM>>>();
    softmax_kernel<<<HH * CC, 256>>>(probs);
    context_kernel<<<dim3(2, RR, HH), 256, CTX_DSMEM>>>();

    o_gemm_kernel<<<dim3(EE / 128, MTOK / 128), 256, GEMM_DSMEM>>>(bo, out);
}